// round 9
// baseline (speedup 1.0000x reference)
#include <cuda_runtime.h>
#include <cuda_bf16.h>
#include <math.h>
#include <stdint.h>

using bf16 = __nv_bfloat16;

// ---------------- problem constants ----------------
static constexpr int BATCH  = 8;
static constexpr int DM     = 768;
static constexpr int HEADS  = 12;
static constexpr int LAYERS = 12;
static constexpr int NTOK   = 785;
static constexpr int NPATCH = 784;
static constexpr int MTOK   = BATCH * NTOK;    // 6280
static constexpr int MPATCH = BATCH * NPATCH;  // 6272
static constexpr int IMG    = 448;
static constexpr int PSZ    = 16;
static constexpr int GRID28 = 28;
static constexpr int SPAD   = 896;             // padded token stride for vT
static constexpr long long LW  = 7077888LL;    // per-layer weight elems
static constexpr int SBL    = 6912;            // per-layer scale cols (2304+768+3072+768)

// ---------------- device scratch ----------------
__device__ signed char g_wq1[(size_t)LAYERS * LW];
__device__ signed char g_wq2[(size_t)LAYERS * LW];
__device__ float       g_sbw[LAYERS * SBL];
__device__ signed char g_cq1[DM * DM];
__device__ signed char g_cq2[DM * DM];
__device__ float       g_sbc[DM];
__device__ signed char g_qp1[(size_t)MPATCH * DM];
__device__ signed char g_qp2[(size_t)MPATCH * DM];
__device__ float       g_sap[MPATCH];
__device__ signed char g_qx1[(size_t)MTOK * DM];
__device__ signed char g_qx2[(size_t)MTOK * DM];
__device__ float       g_dsx[MTOK];
__device__ signed char g_qm1[(size_t)MTOK * 4 * DM];
__device__ signed char g_qm2[(size_t)MTOK * 4 * DM];
__device__ float       g_dsm[MTOK];
__device__ float g_h[(size_t)MTOK * DM];
__device__ float g_ptmp[(size_t)MPATCH * DM];
__device__ bf16  g_yhi[(size_t)MTOK * DM];
__device__ bf16  g_ylo[(size_t)MTOK * DM];
__device__ bf16  g_qhi[(size_t)MTOK * 3 * DM];
__device__ bf16  g_qlo[(size_t)MTOK * 3 * DM];
__device__ bf16  g_mhi[(size_t)MTOK * 4 * DM];
__device__ bf16  g_mlo[(size_t)MTOK * 4 * DM];
__device__ bf16  g_vthi[(size_t)BATCH * HEADS * 64 * SPAD];
__device__ bf16  g_vtlo[(size_t)BATCH * HEADS * 64 * SPAD];

// ---------------- small helpers ----------------
__device__ __forceinline__ void split2(float v, bf16& h, bf16& l) {
    h = __float2bfloat16(v);
    l = __float2bfloat16(v - __bfloat162float(h));
}
__device__ __forceinline__ float geluf(float v) {
    return 0.5f * v * (1.0f + erff(v * 0.70710678118654752f));
}
__device__ __forceinline__ float warpSum(float v) {
#pragma unroll
    for (int o = 16; o > 0; o >>= 1) v += __shfl_xor_sync(0xffffffffu, v, o);
    return v;
}
__device__ __forceinline__ float warpMax(float v) {
#pragma unroll
    for (int o = 16; o > 0; o >>= 1) v = fmaxf(v, __shfl_xor_sync(0xffffffffu, v, o));
    return v;
}
__device__ __forceinline__ float blockSum256(float v, float* sh) {
    int lane = threadIdx.x & 31, w = threadIdx.x >> 5;
    v = warpSum(v);
    if (lane == 0) sh[w] = v;
    __syncthreads();
    float r = (threadIdx.x < 8) ? sh[threadIdx.x] : 0.f;
    if (w == 0) { r = warpSum(r); if (lane == 0) sh[0] = r; }
    __syncthreads();
    r = sh[0];
    __syncthreads();
    return r;
}
__device__ __forceinline__ float blockMax256(float v, float* sh) {
    int lane = threadIdx.x & 31, w = threadIdx.x >> 5;
    v = warpMax(v);
    if (lane == 0) sh[w] = v;
    __syncthreads();
    float r = (threadIdx.x < 8) ? sh[threadIdx.x] : 0.f;
    if (w == 0) { r = warpMax(r); if (lane == 0) sh[0] = r; }
    __syncthreads();
    r = sh[0];
    __syncthreads();
    return r;
}
// 2-digit int8 quantization: x ~= (q1 + q2/256) * ds, ds canonical
__device__ __forceinline__ void quant2(float x, float sa, float ds,
                                       signed char& a, signed char& b) {
    float q1 = fminf(fmaxf(rintf(x * sa), -127.f), 127.f);
    float r = x - q1 * ds;
    float q2 = fminf(fmaxf(rintf(r * sa * 256.f), -127.f), 127.f);
    a = (signed char)(int)q1;
    b = (signed char)(int)q2;
}

// ---------------- PTX wrappers ----------------
__device__ __forceinline__ uint32_t s2u(const void* p) {
    uint32_t a;
    asm("{ .reg .u64 t; cvta.to.shared.u64 t, %1; cvt.u32.u64 %0, t; }" : "=r"(a) : "l"(p));
    return a;
}
__device__ __forceinline__ void cp16(uint32_t d, const void* s, bool pred) {
    int sz = pred ? 16 : 0;
    asm volatile("cp.async.cg.shared.global [%0], [%1], 16, %2;" :: "r"(d), "l"(s), "r"(sz));
}
__device__ __forceinline__ void cpcommit() { asm volatile("cp.async.commit_group;" ::: "memory"); }
__device__ __forceinline__ void cpwait0()  { asm volatile("cp.async.wait_group 0;" ::: "memory"); }
__device__ __forceinline__ void cpwait1()  { asm volatile("cp.async.wait_group 1;" ::: "memory"); }
__device__ __forceinline__ void ldsm4(uint32_t* r, uint32_t addr) {
    asm volatile("ldmatrix.sync.aligned.m8n8.x4.shared.b16 {%0,%1,%2,%3}, [%4];"
                 : "=r"(r[0]), "=r"(r[1]), "=r"(r[2]), "=r"(r[3]) : "r"(addr));
}
__device__ __forceinline__ void mma16816(float* c, const uint32_t* a, const uint32_t* b) {
    asm volatile(
        "mma.sync.aligned.m16n8k16.row.col.f32.bf16.bf16.f32 "
        "{%0,%1,%2,%3}, {%4,%5,%6,%7}, {%8,%9}, {%0,%1,%2,%3};"
        : "+f"(c[0]), "+f"(c[1]), "+f"(c[2]), "+f"(c[3])
        : "r"(a[0]), "r"(a[1]), "r"(a[2]), "r"(a[3]), "r"(b[0]), "r"(b[1]));
}
__device__ __forceinline__ void mma_s8(int* c, const uint32_t* a, const uint32_t* b) {
    asm volatile(
        "mma.sync.aligned.m16n8k32.row.col.s32.s8.s8.s32 "
        "{%0,%1,%2,%3}, {%4,%5,%6,%7}, {%8,%9}, {%0,%1,%2,%3};"
        : "+r"(c[0]), "+r"(c[1]), "+r"(c[2]), "+r"(c[3])
        : "r"(a[0]), "r"(a[1]), "r"(a[2]), "r"(a[3]), "r"(b[0]), "r"(b[1]));
}
__device__ __forceinline__ uint32_t packsplit_hi(float a, float b, uint32_t& lo) {
    bf16 ah, al, bh, bl;
    split2(a, ah, al);
    split2(b, bh, bl);
    __nv_bfloat162 h2; h2.x = ah; h2.y = bh;
    __nv_bfloat162 l2; l2.x = al; l2.y = bl;
    lo = *reinterpret_cast<uint32_t*>(&l2);
    return *reinterpret_cast<uint32_t*>(&h2);
}

// ---------------- producers / prep ----------------
// per-patch-row im2col + 2-digit quant (block = one patch row)
__global__ void im2col_quant(const float* __restrict__ x, signed char* __restrict__ Q1,
                             signed char* __restrict__ Q2, float* __restrict__ DS) {
    int m = blockIdx.x;
    int b = m / NPATCH, t = m % NPATCH;
    int py = t / GRID28, px = t % GRID28;
    int tt = threadIdx.x;
    __shared__ float sh[8];
    float v[3];
#pragma unroll
    for (int e = 0; e < 3; e++) {
        int k = tt + e * 256;
        int c = k >> 8, rem = k & 255, i = rem >> 4, j = rem & 15;
        size_t src = (((size_t)(b * 3 + c) * IMG) + (size_t)(py * PSZ + i)) * IMG + (px * PSZ + j);
        v[e] = x[src];
    }
    float mx = blockMax256(fmaxf(fabsf(v[0]), fmaxf(fabsf(v[1]), fabsf(v[2]))), sh);
    mx = fmaxf(mx, 1e-20f);
    float sa = 127.f / mx, ds = 1.f / sa;
#pragma unroll
    for (int e = 0; e < 3; e++) {
        signed char a, c2;
        quant2(v[e], sa, ds, a, c2);
        Q1[(size_t)m * DM + tt + e * 256] = a;
        Q2[(size_t)m * DM + tt + e * 256] = c2;
    }
    if (tt == 0) DS[m] = ds;
}

// conv_w rows (row = output d, 768 contiguous k)
__global__ void rowquant768(const float* __restrict__ W, signed char* __restrict__ Q1,
                            signed char* __restrict__ Q2, float* __restrict__ DS) {
    int n = blockIdx.x, t = threadIdx.x;
    __shared__ float sh[8];
    float v0 = W[(size_t)n * DM + t], v1 = W[(size_t)n * DM + t + 256], v2 = W[(size_t)n * DM + t + 512];
    float mx = blockMax256(fmaxf(fabsf(v0), fmaxf(fabsf(v1), fabsf(v2))), sh);
    mx = fmaxf(mx, 1e-20f);
    float sa = 127.f / mx, ds = 1.f / sa;
    signed char a, b2;
    quant2(v0, sa, ds, a, b2); Q1[(size_t)n * DM + t] = a;       Q2[(size_t)n * DM + t] = b2;
    quant2(v1, sa, ds, a, b2); Q1[(size_t)n * DM + t + 256] = a; Q2[(size_t)n * DM + t + 256] = b2;
    quant2(v2, sa, ds, a, b2); Q1[(size_t)n * DM + t + 512] = a; Q2[(size_t)n * DM + t + 512] = b2;
    if (t == 0) DS[n] = ds;
}

// column max of W[K,N] -> DS[n]
__global__ void colmax_k(const float* __restrict__ W, float* __restrict__ DS, int K, int N) {
    int n = blockIdx.x * 256 + threadIdx.x;
    if (n >= N) return;
    float mx = 1e-20f;
    for (int k = 0; k < K; k++) mx = fmaxf(mx, fabsf(W[(size_t)k * N + n]));
    DS[n] = mx * (1.f / 127.f);
}

// transpose + quant: W[K,N] -> Q[n*K+k]
__global__ void wt_transq(const float* __restrict__ W, const float* __restrict__ DS,
                          signed char* __restrict__ Q1, signed char* __restrict__ Q2,
                          int K, int N) {
    __shared__ float tile[32][33];
    int kb = blockIdx.y * 32, nb = blockIdx.x * 32;
    int tx = threadIdx.x, ty = threadIdx.y;  // 32 x 8
#pragma unroll
    for (int i = 0; i < 32; i += 8) {
        int k = kb + ty + i, n = nb + tx;
        tile[ty + i][tx] = (k < K && n < N) ? W[(size_t)k * N + n] : 0.f;
    }
    __syncthreads();
#pragma unroll
    for (int i = 0; i < 32; i += 8) {
        int n = nb + ty + i, k = kb + tx;
        if (n < N && k < K) {
            float ds = DS[n], sa = 1.f / ds;
            signed char a, b2;
            quant2(tile[tx][ty + i], sa, ds, a, b2);
            Q1[(size_t)n * K + k] = a;
            Q2[(size_t)n * K + k] = b2;
        }
    }
}

__global__ void assemble_kernel(const float* __restrict__ tok, const float* __restrict__ cls,
                                const float* __restrict__ pos, float* __restrict__ H) {
    int idx = blockIdx.x * blockDim.x + threadIdx.x;
    if (idx >= MTOK * DM) return;
    int d = idx % DM;
    int r = idx / DM;
    int n = r % NTOK, b = r / NTOK;
    float v;
    if (n == 0) v = cls[d] + pos[d];
    else        v = tok[((size_t)b * NPATCH + (n - 1)) * DM + d] + pos[(size_t)n * DM + d];
    H[idx] = v;
}

__global__ void ln_kernel(const float* __restrict__ X, const float* __restrict__ g,
                          const float* __restrict__ bb, float* __restrict__ Y,
                          long long inStride, long long outStride) {
    const float* x = X + (long long)blockIdx.x * inStride;
    float* y = Y + (long long)blockIdx.x * outStride;
    int t = threadIdx.x;
    __shared__ float sh[8];
    float v0 = x[t], v1 = x[t + 256], v2 = x[t + 512];
    float mu = blockSum256(v0 + v1 + v2, sh) * (1.0f / 768.0f);
    float d0 = v0 - mu, d1 = v1 - mu, d2 = v2 - mu;
    float var = blockSum256(d0 * d0 + d1 * d1 + d2 * d2, sh) * (1.0f / 768.0f);
    float rs = rsqrtf(var + 1e-5f);
    y[t]       = d0 * rs * g[t]       + bb[t];
    y[t + 256] = d1 * rs * g[t + 256] + bb[t + 256];
    y[t + 512] = d2 * rs * g[t + 512] + bb[t + 512];
}

// LayerNorm -> 2-digit int8 quant (block = row)
__global__ void ln_quant(const float* __restrict__ X, const float* __restrict__ g,
                         const float* __restrict__ bb, signed char* __restrict__ Q1,
                         signed char* __restrict__ Q2, float* __restrict__ DS) {
    const float* x = X + (size_t)blockIdx.x * DM;
    int t = threadIdx.x;
    __shared__ float sh[8];
    float v0 = x[t], v1 = x[t + 256], v2 = x[t + 512];
    float mu = blockSum256(v0 + v1 + v2, sh) * (1.0f / 768.0f);
    float d0 = v0 - mu, d1 = v1 - mu, d2 = v2 - mu;
    float var = blockSum256(d0 * d0 + d1 * d1 + d2 * d2, sh) * (1.0f / 768.0f);
    float rs = rsqrtf(var + 1e-5f);
    float o0 = d0 * rs * g[t] + bb[t];
    float o1 = d1 * rs * g[t + 256] + bb[t + 256];
    float o2 = d2 * rs * g[t + 512] + bb[t + 512];
    float mx = blockMax256(fmaxf(fabsf(o0), fmaxf(fabsf(o1), fabsf(o2))), sh);
    mx = fmaxf(mx, 1e-20f);
    float sa = 127.f / mx, ds = 1.f / sa;
    signed char a, b2;
    size_t base = (size_t)blockIdx.x * DM;
    quant2(o0, sa, ds, a, b2); Q1[base + t] = a;       Q2[base + t] = b2;
    quant2(o1, sa, ds, a, b2); Q1[base + t + 256] = a; Q2[base + t + 256] = b2;
    quant2(o2, sa, ds, a, b2); Q1[base + t + 512] = a; Q2[base + t + 512] = b2;
    if (t == 0) DS[blockIdx.x] = ds;
}

// bf16 hi/lo rows -> 2-digit int8 (block = row, W multiple of 256, W<=3072)
__global__ void quant_rows(const bf16* __restrict__ Hi, const bf16* __restrict__ Lo,
                           signed char* __restrict__ Q1, signed char* __restrict__ Q2,
                           float* __restrict__ DS, int W) {
    int row = blockIdx.x, t = threadIdx.x;
    int E = W >> 8;
    __shared__ float sh[8];
    float v[12];
    float mx = 0.f;
    size_t base = (size_t)row * W;
    for (int e = 0; e < E; e++) {
        int k = t + e * 256;
        v[e] = __bfloat162float(Hi[base + k]) + __bfloat162float(Lo[base + k]);
        mx = fmaxf(mx, fabsf(v[e]));
    }
    mx = blockMax256(mx, sh);
    mx = fmaxf(mx, 1e-20f);
    float sa = 127.f / mx, ds = 1.f / sa;
    for (int e = 0; e < E; e++) {
        signed char a, b2;
        quant2(v[e], sa, ds, a, b2);
        Q1[base + t + e * 256] = a;
        Q2[base + t + e * 256] = b2;
    }
    if (t == 0) DS[row] = ds;
}

// vT[z][d][t] = qkv[b*785+t][1536 + h*64 + d]  (validated)
__global__ void vt_split(const bf16* __restrict__ Qh, const bf16* __restrict__ Ql,
                         bf16* __restrict__ Vh, bf16* __restrict__ Vl) {
    size_t idx = (size_t)blockIdx.x * blockDim.x + threadIdx.x;
    if (idx >= (size_t)BATCH * HEADS * 64 * SPAD) return;
    int t = (int)(idx % SPAD);
    int d = (int)((idx / SPAD) % 64);
    int z = (int)(idx / ((size_t)SPAD * 64));
    int b = z / HEADS, h = z % HEADS;
    bf16 vh = __float2bfloat16(0.f), vl = vh;
    if (t < NTOK) {
        size_t src = ((size_t)(b * NTOK + t)) * (3 * DM) + 2 * DM + h * 64 + d;
        vh = Qh[src]; vl = Ql[src];
    }
    Vh[idx] = vh; Vl[idx] = vl;
}

// ---------------- fused flash attention v4 (validated round 8, unchanged) ----------------
static constexpr int ARS    = 144;
static constexpr int KTILE  = 128 * ARS;
static constexpr int VRS    = 272;
static constexpr int VTILE  = 64 * VRS;
static constexpr int KVBUF  = 2 * KTILE + 2 * VTILE;
static constexpr int PRS2   = 272;
static constexpr int SPTILE = 128 * PRS2;
static constexpr int OFF_SPH = 2 * KVBUF;
static constexpr int OFF_SPL = OFF_SPH + SPTILE;
static constexpr int OFF_M  = OFF_SPL + SPTILE;
static constexpr int OFF_L  = OFF_M + 512;
static constexpr int OFF_CA = OFF_L + 512;
static constexpr int OFF_T  = OFF_CA + 512;
static constexpr int FA_SMEM = OFF_T + 1024;
static constexpr int NCHUNK = 7;

__global__ void __launch_bounds__(256, 1)
fused_attn(const bf16* __restrict__ qkvh, const bf16* __restrict__ qkvl,
           const bf16* __restrict__ vth, const bf16* __restrict__ vtl,
           bf16* __restrict__ yh, bf16* __restrict__ yl) {
    extern __shared__ __align__(16) char smem[];
    uint32_t s0 = s2u(smem);
    const int tid = threadIdx.x, lane = tid & 31, warp = tid >> 5;
    const int qt = blockIdx.x;
    const int z = blockIdx.y;
    const int b = z / HEADS, h = z % HEADS;
    const float SC = 0.125f;

    const int wm0 = warp * 16;
    const uint32_t a_lane  = (uint32_t)(wm0 + (lane & 15)) * ARS + (uint32_t)(lane >> 4) * 16u;
    const uint32_t b_lane  = (uint32_t)((lane & 7) + ((lane >> 4) << 3)) * ARS +
                             (uint32_t)((lane >> 3) & 1) * 16u;
    const uint32_t vb_lane = (uint32_t)((lane & 7) + ((lane >> 4) << 3)) * VRS +
                             (uint32_t)((lane >> 3) & 1) * 16u;
    const uint32_t ap_lane = (uint32_t)(wm0 + (lane & 15)) * PRS2 + (uint32_t)(lane >> 4) * 16u;

    float* mrow = reinterpret_cast<float*>(smem + OFF_M);
    float* lrow = reinterpret_cast<float*>(smem + OFF_L);
    float* crow = reinterpret_cast<float*>(smem + OFF_CA);
    float* tred = reinterpret_cast<float*>(smem + OFF_T);

    auto load_qk = [&](int rowbase, int colbase, uint32_t dsth, uint32_t dstl) {
#pragma unroll
        for (int i = 0; i < 4; i++) {
            int idx = tid + i * 256;
            int r = idx >> 3, g = idx & 7;
            bool v = (rowbase + r) < NTOK;
            size_t off = ((size_t)(b * NTOK + rowbase + r)) * (3 * DM) + colbase + g * 8;
            const bf16* sh2 = v ? (qkvh + off) : qkvh;
            const bf16* sl2 = v ? (qkvl + off) : qkvl;
            uint32_t d = (uint32_t)r * ARS + (uint32_t)g * 16u;
            cp16(dsth + d, sh2, v);
            cp16(dstl + d, sl2, v);
        }
    };
    auto load_vt = [&](int c, uint32_t dsth, uint32_t dstl) {
        const bf16* bh2 = vth + (size_t)z * 64 * SPAD + (size_t)c * 128;
        const bf16* bl2 = vtl + (size_t)z * 64 * SPAD + (size_t)c * 128;
#pragma unroll
        for (int i = 0; i < 4; i++) {
            int idx = tid + i * 256;
            int r = idx >> 4, g = idx & 15;
            size_t off = (size_t)r * SPAD + g * 8;
            uint32_t d = (uint32_t)r * VRS + (uint32_t)g * 16u;
            cp16(dsth + d, bh2 + off, true);
            cp16(dstl + d, bl2 + off, true);
        }
    };
    auto load_chunk = [&](int c, int bsel) {
        uint32_t base = s0 + bsel * KVBUF;
        load_qk(c * 128, DM + h * 64, base, base + KTILE);
        load_vt(c, base + 2 * KTILE, base + 2 * KTILE + VTILE);
        cpcommit();
    };

    load_qk(qt * 128, h * 64, s0 + OFF_SPH, s0 + OFF_SPH + KTILE);
    cpcommit();
    cpwait0();
    __syncthreads();
    uint32_t aQh[4][4], aQl[4][4];
#pragma unroll
    for (int ks = 0; ks < 4; ks++) {
        ldsm4(aQh[ks], s0 + OFF_SPH + a_lane + ks * 32);
        ldsm4(aQl[ks], s0 + OFF_SPH + KTILE + a_lane + ks * 32);
    }
    if (tid < 128) { mrow[tid] = -1e30f; lrow[tid] = 0.f; }
    __syncthreads();

    float o[8][4];
#pragma unroll
    for (int i = 0; i < 8; i++)
#pragma unroll
        for (int j = 0; j < 4; j++) o[i][j] = 0.f;

    load_chunk(0, 0);
    for (int c = 0; c < NCHUNK; c++) {
        if (c + 1 < NCHUNK) { load_chunk(c + 1, (c + 1) & 1); cpwait1(); }
        else                { cpwait0(); }
        __syncthreads();
        uint32_t kvb = s0 + (c & 1) * KVBUF;
        uint32_t Kh = kvb, Kl = kvb + KTILE;
        uint32_t Vh = kvb + 2 * KTILE, Vl = kvb + 2 * KTILE + VTILE;

        float s[16][4];
#pragma unroll
        for (int j = 0; j < 16; j++)
#pragma unroll
            for (int q = 0; q < 4; q++) s[j][q] = 0.f;
#pragma unroll
        for (int ks = 0; ks < 4; ks++) {
#pragma unroll
            for (int jp = 0; jp < 8; jp++) {
                uint32_t kh[4], kl[4];
                uint32_t koff = b_lane + (uint32_t)jp * (16 * ARS) + (uint32_t)ks * 32u;
                ldsm4(kh, Kh + koff);
                ldsm4(kl, Kl + koff);
#pragma unroll
                for (int hf = 0; hf < 2; hf++) {
                    int j = jp * 2 + hf;
                    mma16816(s[j], aQh[ks], &kh[hf * 2]);
                    mma16816(s[j], aQh[ks], &kl[hf * 2]);
                    mma16816(s[j], aQl[ks], &kh[hf * 2]);
                }
            }
        }

        {
            char* smp = smem;
            int r0 = wm0 + (lane >> 2);
            int c0 = 2 * (lane & 3);
#pragma unroll
            for (int j = 0; j < 16; j++) {
                int cc = j * 8 + c0;
                uint32_t loA, hiA = packsplit_hi(s[j][0], s[j][1], loA);
                uint32_t loB, hiB = packsplit_hi(s[j][2], s[j][3], loB);
                *(uint32_t*)(smp + OFF_SPH + (uint32_t)r0 * PRS2 + cc * 2) = hiA;
                *(uint32_t*)(smp + OFF_SPL + (uint32_t)r0 * PRS2 + cc * 2) = loA;
                *(uint32_t*)(smp + OFF_SPH + (uint32_t)(r0 + 8) * PRS2 + cc * 2) = hiB;
                *(uint32_t*)(smp + OFF_SPL + (uint32_t)(r0 + 8) * PRS2 + cc * 2) = loB;
            }
        }
        __syncthreads();

        const int r = tid >> 1, half = tid & 1;
        char* smp = smem;
        const uint32_t rowoff = (uint32_t)r * PRS2 + (uint32_t)half * 128u;
        const int colbase = c * 128 + half * 64;
        const int nvalid0 = NTOK - colbase;
        const int nvalid = nvalid0 < 0 ? 0 : (nvalid0 > 64 ? 64 : nvalid0);

        float chmax = -1e30f;
#pragma unroll 8
        for (int k = 0; k < 64; k += 2) {
            uint32_t hi = *(uint32_t*)(smp + OFF_SPH + rowoff + k * 2);
            uint32_t lo = *(uint32_t*)(smp + OFF_SPL + rowoff + k * 2);
            __nv_bfloat162 h2 = *reinterpret_cast<__nv_bfloat162*>(&hi);
            __nv_bfloat162 l2 = *reinterpret_cast<__nv_bfloat162*>(&lo);
            float v0 = __bfloat162float(h2.x) + __bfloat162float(l2.x);
            float v1 = __bfloat162float(h2.y) + __bfloat162float(l2.y);
            if (k < nvalid)     chmax = fmaxf(chmax, v0);
            if (k + 1 < nvalid) chmax = fmaxf(chmax, v1);
        }
        tred[tid] = chmax;
        __syncthreads();
        float m_old = mrow[r];
        float rmax = fmaxf(tred[2 * r], tred[2 * r + 1]);
        float m_new = fmaxf(m_old, rmax);
        float ca = __expf(SC * (m_old - m_new));
        __syncthreads();

        float esum = 0.f;
#pragma unroll 8
        for (int k = 0; k < 64; k += 2) {
            uint32_t hi = *(uint32_t*)(smp + OFF_SPH + rowoff + k * 2);
            uint32_t lo = *(uint32_t*)(smp + OFF_SPL + rowoff + k * 2);
            __nv_bfloat162 h2 = *reinterpret_cast<__nv_bfloat162*>(&hi);
            __nv_bfloat162 l2 = *reinterpret_cast<__nv_bfloat162*>(&lo);
            float v0 = __bfloat162float(h2.x) + __bfloat162float(l2.x);
            float v1 = __bfloat162float(h2.y) + __bfloat162float(l2.y);
            float e0 = (k < nvalid)     ? __expf(SC * (v0 - m_new)) : 0.f;
            float e1 = (k + 1 < nvalid) ? __expf(SC * (v1 - m_new)) : 0.f;
            esum += e0 + e1;
            uint32_t plo, phi = packsplit_hi(e0, e1, plo);
            *(uint32_t*)(smp + OFF_SPH + rowoff + k * 2) = phi;
            *(uint32_t*)(smp + OFF_SPL + rowoff + k * 2) = plo;
        }
        tred[tid] = esum;
        __syncthreads();
        if (half == 0) {
            lrow[r] = lrow[r] * ca + tred[2 * r] + tred[2 * r + 1];
            mrow[r] = m_new;
            crow[r] = ca;
        }
        __syncthreads();

        float caA = crow[wm0 + (lane >> 2)];
        float caB = crow[wm0 + 8 + (lane >> 2)];
#pragma unroll
        for (int nt = 0; nt < 8; nt++) {
            o[nt][0] *= caA; o[nt][1] *= caA;
            o[nt][2] *= caB; o[nt][3] *= caB;
        }

#pragma unroll
        for (int kt = 0; kt < 8; kt++) {
            uint32_t pa[4], pb[4];
            ldsm4(pa, s0 + OFF_SPH + ap_lane + (uint32_t)kt * 32u);
            ldsm4(pb, s0 + OFF_SPL + ap_lane + (uint32_t)kt * 32u);
#pragma unroll
            for (int dp = 0; dp < 4; dp++) {
                uint32_t vh[4], vl[4];
                uint32_t voff = vb_lane + (uint32_t)dp * (16 * VRS) + (uint32_t)kt * 32u;
                ldsm4(vh, Vh + voff);
                ldsm4(vl, Vl + voff);
#pragma unroll
                for (int hf = 0; hf < 2; hf++) {
                    int nt = dp * 2 + hf;
                    mma16816(o[nt], pa, &vh[hf * 2]);
                    mma16816(o[nt], pa, &vl[hf * 2]);
                    mma16816(o[nt], pb, &vh[hf * 2]);
                }
            }
        }
        __syncthreads();
    }

    float la = lrow[wm0 + (lane >> 2)];
    float lb = lrow[wm0 + 8 + (lane >> 2)];
    float ia = 1.0f / la, ib = 1.0f / lb;
    int ra = qt * 128 + wm0 + (lane >> 2);
    int rb = ra + 8;
#pragma unroll
    for (int nt = 0; nt < 8; nt++) {
        int col = h * 64 + nt * 8 + 2 * (lane & 3);
        if (ra < NTOK) {
            size_t p = (size_t)(b * NTOK + ra) * DM + col;
            uint32_t lo, hi = packsplit_hi(o[nt][0] * ia, o[nt][1] * ia, lo);
            *reinterpret_cast<uint32_t*>(yh + p) = hi;
            *reinterpret_cast<uint32_t*>(yl + p) = lo;
        }
        if (rb < NTOK) {
            size_t p = (size_t)(b * NTOK + rb) * DM + col;
            uint32_t lo, hi = packsplit_hi(o[nt][2] * ib, o[nt][3] * ib, lo);
            *reinterpret_cast<uint32_t*>(yh + p) = hi;
            *reinterpret_cast<uint32_t*>(yl + p) = lo;
        }
    }
}

// ---------------- int8 2-digit GEMM ----------------
// C[m,n] = dsA[m]*dsB[n]*(q1A.q1B + (q1A.q2B + q2A.q1B)/256)   (+ epilogue)
// BM=128, BN=128, BK=64, 8 warps (warp tile 64x32), double-buffered cp.async.
// EPI: 0 fp32 (+bias?+res?), 1 split bf16 (+bias), 2 split gelu(+bias)
static constexpr int RS8   = 80;               // 64 int8 + 16 pad
static constexpr int A8SZ  = 128 * RS8;        // 10240
static constexpr int BUF8  = 4 * A8SZ;         // q1A,q2A,q1B,q2B = 40960

template <int EPI>
__global__ void __launch_bounds__(256, 1)
i8_gemm(const signed char* __restrict__ q1A, const signed char* __restrict__ q2A,
        const float* __restrict__ dsA, int lda,
        const signed char* __restrict__ q1B, const signed char* __restrict__ q2B,
        const float* __restrict__ dsB, int ldb,
        float* __restrict__ Cf, bf16* __restrict__ Chi, bf16* __restrict__ Clo, int ldc,
        const float* __restrict__ bias, const float* __restrict__ res,
        int M, int N, int NC) {
    extern __shared__ __align__(16) char smem[];
    uint32_t s0 = s2u(smem);

    const int tid = threadIdx.x, lane = tid & 31, warp = tid >> 5;
    const int wm0 = (warp / 4) * 64;          // WGN=4
    const int wn0 = (warp % 4) * 32;
    const int row0 = blockIdx.y * 128, col0 = blockIdx.x * 128;

    int lead[4][4][4], cross[4][4][4];
#pragma unroll
    for (int i = 0; i < 4; i++)
#pragma unroll
        for (int j = 0; j < 4; j++)
#pragma unroll
            for (int k = 0; k < 4; k++) { lead[i][j][k] = 0; cross[i][j][k] = 0; }

    // same lane formulas as validated bf16 paths, stride RS8
    const uint32_t a_lane = (uint32_t)(wm0 + (lane & 15)) * RS8 + (uint32_t)(lane >> 4) * 16u;
    const uint32_t b_lane = (uint32_t)(wn0 + (lane & 7) + ((lane >> 4) << 3)) * RS8 +
                            (uint32_t)((lane >> 3) & 1) * 16u;

    auto load_chunk = [&](int ck, int bsel) {
        uint32_t base = s0 + bsel * BUF8;
        // A: 128 rows x 4 granules of 16B, x2 digits
#pragma unroll
        for (int i = 0; i < 2; i++) {
            int idx = tid + i * 256;
            int r = idx >> 2, c = idx & 3;
            int gm = row0 + r;
            bool v = gm < M;
            const signed char* p1 = v ? (q1A + (size_t)gm * lda + (size_t)ck * 64 + c * 16) : q1A;
            const signed char* p2 = v ? (q2A + (size_t)gm * lda + (size_t)ck * 64 + c * 16) : q2A;
            uint32_t d = base + (uint32_t)r * RS8 + (uint32_t)c * 16u;
            cp16(d, p1, v);
            cp16(d + A8SZ, p2, v);
        }
        // B: 128 rows x 4 granules, x2 digits
#pragma unroll
        for (int i = 0; i < 2; i++) {
            int idx = tid + i * 256;
            int r = idx >> 2, c = idx & 3;
            int gn = col0 + r;
            bool v = gn < N;
            const signed char* p1 = v ? (q1B + (size_t)gn * ldb + (size_t)ck * 64 + c * 16) : q1B;
            const signed char* p2 = v ? (q2B + (size_t)gn * ldb + (size_t)ck * 64 + c * 16) : q2B;
            uint32_t d = base + 2 * A8SZ + (uint32_t)r * RS8 + (uint32_t)c * 16u;
            cp16(d, p1, v);
            cp16(d + A8SZ, p2, v);
        }
        cpcommit();
    };

    auto compute = [&](int bsel) {
        uint32_t base = s0 + bsel * BUF8;
        uint32_t a1 = base, a2 = base + A8SZ, b1 = base + 2 * A8SZ, b2 = base + 3 * A8SZ;
#pragma unroll
        for (int ks = 0; ks < 2; ks++) {   // 32 int8 of K per step
            uint32_t aq1[4][4], aq2[4][4];
#pragma unroll
            for (int mt = 0; mt < 4; mt++) {
                uint32_t off = a_lane + (uint32_t)mt * (16 * RS8) + (uint32_t)ks * 32u;
                ldsm4(aq1[mt], a1 + off);
                ldsm4(aq2[mt], a2 + off);
            }
            uint32_t bq1[2][4], bq2[2][4];
#pragma unroll
            for (int np = 0; np < 2; np++) {
                uint32_t off = b_lane + (uint32_t)np * (16 * RS8) + (uint32_t)ks * 32u;
                ldsm4(bq1[np], b1 + off);
                ldsm4(bq2[np], b2 + off);
            }
#pragma unroll
            for (int mt = 0; mt < 4; mt++)
#pragma unroll
                for (int nt = 0; nt < 4; nt++) {
                    const uint32_t* B1 = &bq1[nt >> 1][(nt & 1) * 2];
                    const uint32_t* B2 = &bq2[nt >> 1][(nt & 1) * 2];
                    mma_s8(lead[mt][nt], aq1[mt], B1);
                    mma_s8(cross[mt][nt], aq1[mt], B2);
                    mma_s8(cross[mt][nt], aq2[mt], B1);
                }
        }
    };

    load_chunk(0, 0);
    for (int ck = 0; ck < NC; ck++) {
        if (ck + 1 < NC) { load_chunk(ck + 1, (ck + 1) & 1); cpwait1(); }
        else             { cpwait0(); }
        __syncthreads();
        compute(ck & 1);
        __syncthreads();
    }

#pragma unroll
    for (int mt = 0; mt < 4; mt++) {
#pragma unroll
        for (int nt = 0; nt < 4; nt++) {
            int r0 = row0 + wm0 + mt * 16 + (lane >> 2);
            int c0 = col0 + wn0 + nt * 8 + (lane & 3) * 2;
            int* ld4 = lead[mt][nt];
            int* cr4 = cross[mt][nt];
            float db0 = dsB[c0], db1 = dsB[c0 + 1];
#pragma unroll
            for (int h = 0; h < 2; h++) {
                int gm = r0 + h * 8;
                if (gm >= M) continue;
                float da = dsA[gm];
                float v0 = ((float)ld4[h * 2]     + (float)cr4[h * 2]     * 0.00390625f) * da * db0;
                float v1 = ((float)ld4[h * 2 + 1] + (float)cr4[h * 2 + 1] * 0.00390625f) * da * db1;
                if (EPI == 0) {
                    if (bias) { v0 += bias[c0]; v1 += bias[c0 + 1]; }
                    if (res) {
                        v0 += res[(size_t)gm * ldc + c0];
                        v1 += res[(size_t)gm * ldc + c0 + 1];
                    }
                    Cf[(size_t)gm * ldc + c0]     = v0;
                    Cf[(size_t)gm * ldc + c0 + 1] = v1;
                } else {
                    if (bias) { v0 += bias[c0]; v1 += bias[c0 + 1]; }
                    if (EPI == 2) { v0 = geluf(v0); v1 = geluf(v1); }
                    uint32_t lo, hi = packsplit_hi(v0, v1, lo);
                    *reinterpret_cast<uint32_t*>(Chi + (size_t)gm * ldc + c0) = hi;
                    *reinterpret_cast<uint32_t*>(Clo + (size_t)gm * ldc + c0) = lo;
                }
            }
        }
    }
}

template <int EPI>
static void igemm(const signed char* q1A, const signed char* q2A, const float* dsA, int lda,
                  const signed char* q1B, const signed char* q2B, const float* dsB, int ldb,
                  float* Cf, bf16* Ch, bf16* Cl, int ldc,
                  const float* bias, const float* res, int M, int N, int K) {
    int smem = 2 * BUF8;
    cudaFuncSetAttribute(i8_gemm<EPI>, cudaFuncAttributeMaxDynamicSharedMemorySize, smem);
    dim3 grid(N / 128, (M + 127) / 128, 1);
    i8_gemm<EPI><<<grid, 256, smem>>>(q1A, q2A, dsA, lda, q1B, q2B, dsB, ldb,
                                      Cf, Ch, Cl, ldc, bias, res, M, N, K / 64);
}

extern "C" void kernel_launch(void* const* d_in, const int* in_sizes, int n_in,
                              void* d_out, int out_size) {
    const float* x       = (const float*)d_in[0];
    const float* conv_w  = (const float*)d_in[1];
    const float* conv_b  = (const float*)d_in[2];
    const float* cls_tok = (const float*)d_in[3];
    const float* pos_emb = (const float*)d_in[4];
    const float* ln1_g   = (const float*)d_in[5];
    const float* ln1_b   = (const float*)d_in[6];
    const float* qkv_w   = (const float*)d_in[7];
    const float* qkv_b   = (const float*)d_in[8];
    const float* proj_w  = (const float*)d_in[9];
    const float* proj_b  = (const float*)d_in[10];
    const float* ln2_g   = (const float*)d_in[11];
    const float* ln2_b   = (const float*)d_in[12];
    const float* mlp_w1  = (const float*)d_in[13];
    const float* mlp_b1  = (const float*)d_in[14];
    const float* mlp_w2  = (const float*)d_in[15];
    const float* mlp_b2  = (const float*)d_in[16];
    const float* lnf_g   = (const float*)d_in[17];
    const float* lnf_b   = (const float*)d_in[18];
    float* out = (float*)d_out;

    signed char *wq1, *wq2, *cq1, *cq2, *qp1, *qp2, *qx1, *qx2, *qm1, *qm2;
    float *sbw, *sbc, *sap, *dsx, *dsm, *ph, *ptmp;
    bf16 *yhi, *ylo, *qhi, *qlo, *mhi, *mlo, *vthi, *vtlo;
    cudaGetSymbolAddress((void**)&wq1, g_wq1);
    cudaGetSymbolAddress((void**)&wq2, g_wq2);
    cudaGetSymbolAddress((void**)&sbw, g_sbw);
    cudaGetSymbolAddress((void**)&cq1, g_cq1);
    cudaGetSymbolAddress((void**)&cq2, g_cq2);
    cudaGetSymbolAddress((void**)&sbc, g_sbc);
    cudaGetSymbolAddress((void**)&qp1, g_qp1);
    cudaGetSymbolAddress((void**)&qp2, g_qp2);
    cudaGetSymbolAddress((void**)&sap, g_sap);
    cudaGetSymbolAddress((void**)&qx1, g_qx1);
    cudaGetSymbolAddress((void**)&qx2, g_qx2);
    cudaGetSymbolAddress((void**)&dsx, g_dsx);
    cudaGetSymbolAddress((void**)&qm1, g_qm1);
    cudaGetSymbolAddress((void**)&qm2, g_qm2);
    cudaGetSymbolAddress((void**)&dsm, g_dsm);
    cudaGetSymbolAddress((void**)&ph, g_h);
    cudaGetSymbolAddress((void**)&ptmp, g_ptmp);
    cudaGetSymbolAddress((void**)&yhi, g_yhi);
    cudaGetSymbolAddress((void**)&ylo, g_ylo);
    cudaGetSymbolAddress((void**)&qhi, g_qhi);
    cudaGetSymbolAddress((void**)&qlo, g_qlo);
    cudaGetSymbolAddress((void**)&mhi, g_mhi);
    cudaGetSymbolAddress((void**)&mlo, g_mlo);
    cudaGetSymbolAddress((void**)&vthi, g_vthi);
    cudaGetSymbolAddress((void**)&vtlo, g_vtlo);

    dim3 tb(32, 8);

    // ---- weight prep: colmax + transpose-quant ----
    rowquant768<<<DM, 256>>>(conv_w, cq1, cq2, sbc);
    for (int l = 0; l < LAYERS; l++) {
        long long wo = (long long)l * LW;
        float* sb = sbw + l * SBL;
        const float* qw = qkv_w + (size_t)l * DM * 3 * DM;
        const float* pw = proj_w + (size_t)l * DM * DM;
        const float* w1 = mlp_w1 + (size_t)l * DM * 4 * DM;
        const float* w2 = mlp_w2 + (size_t)l * 4 * DM * DM;
        colmax_k<<<2304 / 256, 256>>>(qw, sb, DM, 3 * DM);
        colmax_k<<<768 / 256, 256>>>(pw, sb + 2304, DM, DM);
        colmax_k<<<3072 / 256, 256>>>(w1, sb + 3072, DM, 4 * DM);
        colmax_k<<<768 / 256, 256>>>(w2, sb + 6144, 4 * DM, DM);
        wt_transq<<<dim3(2304 / 32, 768 / 32), tb>>>(qw, sb, wq1 + wo, wq2 + wo, DM, 3 * DM);
        wt_transq<<<dim3(768 / 32, 768 / 32), tb>>>(pw, sb + 2304, wq1 + wo + 1769472,
                                                    wq2 + wo + 1769472, DM, DM);
        wt_transq<<<dim3(3072 / 32, 768 / 32), tb>>>(w1, sb + 3072, wq1 + wo + 2359296,
                                                     wq2 + wo + 2359296, DM, 4 * DM);
        wt_transq<<<dim3(768 / 32, 3072 / 32), tb>>>(w2, sb + 6144, wq1 + wo + 4718592,
                                                     wq2 + wo + 4718592, 4 * DM, DM);
    }

    // ---- patch embed ----
    im2col_quant<<<MPATCH, 256>>>(x, qp1, qp2, sap);
    igemm<0>(qp1, qp2, sap, DM, cq1, cq2, sbc, DM, ptmp, nullptr, nullptr, DM,
             conv_b, nullptr, MPATCH, DM, DM);
    assemble_kernel<<<(MTOK * DM + 255) / 256, 256>>>(ptmp, cls_tok, pos_emb, ph);

    cudaFuncSetAttribute(fused_attn, cudaFuncAttributeMaxDynamicSharedMemorySize, FA_SMEM);

    for (int l = 0; l < LAYERS; l++) {
        long long wo = (long long)l * LW;
        const signed char* qkvw1 = wq1 + wo;           const signed char* qkvw2 = wq2 + wo;
        const signed char* pjw1 = wq1 + wo + 1769472;  const signed char* pjw2 = wq2 + wo + 1769472;
        const signed char* m1w1 = wq1 + wo + 2359296;  const signed char* m1w2 = wq2 + wo + 2359296;
        const signed char* m2w1 = wq1 + wo + 4718592;  const signed char* m2w2 = wq2 + wo + 4718592;
        const float* sb = sbw + l * SBL;
        const float* l1g = ln1_g + (size_t)l * DM;
        const float* l1b = ln1_b + (size_t)l * DM;
        const float* qb  = qkv_b + (size_t)l * 3 * DM;
        const float* pb  = proj_b + (size_t)l * DM;
        const float* l2g = ln2_g + (size_t)l * DM;
        const float* l2b = ln2_b + (size_t)l * DM;
        const float* b1  = mlp_b1 + (size_t)l * 4 * DM;
        const float* b2  = mlp_b2 + (size_t)l * DM;

        // LN1 -> int8 pair
        ln_quant<<<MTOK, 256>>>(ph, l1g, l1b, qx1, qx2, dsx);
        // QKV -> bf16 hi/lo (attention input)
        igemm<1>(qx1, qx2, dsx, DM, qkvw1, qkvw2, sb, DM, nullptr, qhi, qlo, 3 * DM,
                 qb, nullptr, MTOK, 3 * DM, DM);
        // V transpose
        {
            size_t n = (size_t)BATCH * HEADS * 64 * SPAD;
            vt_split<<<(unsigned)((n + 255) / 256), 256>>>(qhi, qlo, vthi, vtlo);
        }
        // fused attention -> y bf16 hi/lo
        fused_attn<<<dim3(NCHUNK, BATCH * HEADS), 256, FA_SMEM>>>(qhi, qlo, vthi, vtlo,
                                                                  yhi, ylo);
        // quantize attention output for proj
        quant_rows<<<MTOK, 256>>>(yhi, ylo, qx1, qx2, dsx, DM);
        // proj + bias + residual -> h
        igemm<0>(qx1, qx2, dsx, DM, pjw1, pjw2, sb + 2304, DM, ph, nullptr, nullptr, DM,
                 pb, ph, MTOK, DM, DM);
        // LN2 -> int8 pair
        ln_quant<<<MTOK, 256>>>(ph, l2g, l2b, qx1, qx2, dsx);
        // MLP1 + gelu -> mid bf16 hi/lo
        igemm<2>(qx1, qx2, dsx, DM, m1w1, m1w2, sb + 3072, DM, nullptr, mhi, mlo, 4 * DM,
                 b1, nullptr, MTOK, 4 * DM, DM);
        // quantize mid
        quant_rows<<<MTOK, 256>>>(mhi, mlo, qm1, qm2, dsm, 4 * DM);
        // MLP2 + bias + residual -> h
        igemm<0>(qm1, qm2, dsm, 4 * DM, m2w1, m2w2, sb + 6144, 4 * DM, ph, nullptr, nullptr, DM,
                 b2, ph, MTOK, DM, 4 * DM);
    }

    // final LN on CLS rows -> out [8,768]
    ln_kernel<<<BATCH, 256>>>(ph, lnf_g, lnf_b, out, (long long)NTOK * DM, DM);
}

// round 10
// speedup vs baseline: 2.3357x; 2.3357x over previous
#include <cuda_runtime.h>
#include <cuda_bf16.h>
#include <cuda_fp16.h>
#include <math.h>
#include <stdint.h>

using bf16 = __nv_bfloat16;
using f16 = __half;

// ---------------- problem constants ----------------
static constexpr int BATCH  = 8;
static constexpr int DM     = 768;
static constexpr int HEADS  = 12;
static constexpr int LAYERS = 12;
static constexpr int NTOK   = 785;
static constexpr int NPATCH = 784;
static constexpr int MTOK   = BATCH * NTOK;    // 6280
static constexpr int MPATCH = BATCH * NPATCH;  // 6272
static constexpr int IMG    = 448;
static constexpr int PSZ    = 16;
static constexpr int GRID28 = 28;
static constexpr int SPAD   = 896;
static constexpr long long LW = 7077888LL;

// ---------------- device scratch ----------------
__device__ f16  g_wh[(size_t)LAYERS * LW];
__device__ f16  g_wl[(size_t)LAYERS * LW];
__device__ f16  g_cwh[DM * DM];
__device__ f16  g_cwl[DM * DM];
__device__ f16  g_pxh[(size_t)MPATCH * DM];
__device__ f16  g_pxl[(size_t)MPATCH * DM];
__device__ f16  g_xh[(size_t)MTOK * DM];       // LN out (GEMM A)
__device__ f16  g_xl[(size_t)MTOK * DM];
__device__ f16  g_ah[(size_t)MTOK * DM];       // attn out (GEMM A)
__device__ f16  g_al[(size_t)MTOK * DM];
__device__ f16  g_mh[(size_t)MTOK * 4 * DM];   // mlp mid
__device__ f16  g_ml[(size_t)MTOK * 4 * DM];
__device__ float g_h[(size_t)MTOK * DM];
__device__ float g_ptmp[(size_t)MPATCH * DM];
__device__ bf16  g_qhi[(size_t)MTOK * 3 * DM];
__device__ bf16  g_qlo[(size_t)MTOK * 3 * DM];
__device__ bf16  g_vthi[(size_t)BATCH * HEADS * 64 * SPAD];
__device__ bf16  g_vtlo[(size_t)BATCH * HEADS * 64 * SPAD];

// ---------------- small helpers ----------------
__device__ __forceinline__ void split2(float v, bf16& h, bf16& l) {
    h = __float2bfloat16(v);
    l = __float2bfloat16(v - __bfloat162float(h));
}
__device__ __forceinline__ float geluf(float v) {
    return 0.5f * v * (1.0f + erff(v * 0.70710678118654752f));
}
__device__ __forceinline__ float warpSum(float v) {
#pragma unroll
    for (int o = 16; o > 0; o >>= 1) v += __shfl_xor_sync(0xffffffffu, v, o);
    return v;
}
__device__ __forceinline__ float blockSum256(float v, float* sh) {
    int lane = threadIdx.x & 31, w = threadIdx.x >> 5;
    v = warpSum(v);
    if (lane == 0) sh[w] = v;
    __syncthreads();
    float r = (threadIdx.x < 8) ? sh[threadIdx.x] : 0.f;
    if (w == 0) { r = warpSum(r); if (lane == 0) sh[0] = r; }
    __syncthreads();
    r = sh[0];
    __syncthreads();
    return r;
}

// ---------------- PTX wrappers ----------------
__device__ __forceinline__ uint32_t s2u(const void* p) {
    uint32_t a;
    asm("{ .reg .u64 t; cvta.to.shared.u64 t, %1; cvt.u32.u64 %0, t; }" : "=r"(a) : "l"(p));
    return a;
}
__device__ __forceinline__ void cp16(uint32_t d, const void* s, bool pred) {
    int sz = pred ? 16 : 0;
    asm volatile("cp.async.cg.shared.global [%0], [%1], 16, %2;" :: "r"(d), "l"(s), "r"(sz));
}
__device__ __forceinline__ void cpcommit() { asm volatile("cp.async.commit_group;" ::: "memory"); }
__device__ __forceinline__ void cpwait0()  { asm volatile("cp.async.wait_group 0;" ::: "memory"); }
__device__ __forceinline__ void cpwait1()  { asm volatile("cp.async.wait_group 1;" ::: "memory"); }
__device__ __forceinline__ void ldsm4(uint32_t* r, uint32_t addr) {
    asm volatile("ldmatrix.sync.aligned.m8n8.x4.shared.b16 {%0,%1,%2,%3}, [%4];"
                 : "=r"(r[0]), "=r"(r[1]), "=r"(r[2]), "=r"(r[3]) : "r"(addr));
}
// bf16 operands, f32 acc (validated; attention only)
__device__ __forceinline__ void mma16816(float* c, const uint32_t* a, const uint32_t* b) {
    asm volatile(
        "mma.sync.aligned.m16n8k16.row.col.f32.bf16.bf16.f32 "
        "{%0,%1,%2,%3}, {%4,%5,%6,%7}, {%8,%9}, {%0,%1,%2,%3};"
        : "+f"(c[0]), "+f"(c[1]), "+f"(c[2]), "+f"(c[3])
        : "r"(a[0]), "r"(a[1]), "r"(a[2]), "r"(a[3]), "r"(b[0]), "r"(b[1]));
}
// f16 operands, f32 acc (lead term)
__device__ __forceinline__ void mma_h_f32(float* c, const uint32_t* a, const uint32_t* b) {
    asm volatile(
        "mma.sync.aligned.m16n8k16.row.col.f32.f16.f16.f32 "
        "{%0,%1,%2,%3}, {%4,%5,%6,%7}, {%8,%9}, {%0,%1,%2,%3};"
        : "+f"(c[0]), "+f"(c[1]), "+f"(c[2]), "+f"(c[3])
        : "r"(a[0]), "r"(a[1]), "r"(a[2]), "r"(a[3]), "r"(b[0]), "r"(b[1]));
}
// f16 operands, f16 acc (cross terms; 2 C regs)
__device__ __forceinline__ void mma_h_f16(uint32_t* c, const uint32_t* a, const uint32_t* b) {
    asm volatile(
        "mma.sync.aligned.m16n8k16.row.col.f16.f16.f16.f16 "
        "{%0,%1}, {%2,%3,%4,%5}, {%6,%7}, {%0,%1};"
        : "+r"(c[0]), "+r"(c[1])
        : "r"(a[0]), "r"(a[1]), "r"(a[2]), "r"(a[3]), "r"(b[0]), "r"(b[1]));
}
// bf16 split pack (attention internals; validated)
__device__ __forceinline__ uint32_t packsplit_hi(float a, float b, uint32_t& lo) {
    bf16 ah, al, bh, bl;
    split2(a, ah, al);
    split2(b, bh, bl);
    __nv_bfloat162 h2; h2.x = ah; h2.y = bh;
    __nv_bfloat162 l2; l2.x = al; l2.y = bl;
    lo = *reinterpret_cast<uint32_t*>(&l2);
    return *reinterpret_cast<uint32_t*>(&h2);
}
// fp16 split pack: hi = rn(x), lo = (x - hi) * 2048 (normal-range)
__device__ __forceinline__ uint32_t packsplit_h(float a, float b, uint32_t& lo) {
    f16 ah = __float2half(a), bh = __float2half(b);
    float ar = (a - __half2float(ah)) * 2048.f;
    float br = (b - __half2float(bh)) * 2048.f;
    __half2 h2 = __halves2half2(ah, bh);
    __half2 l2 = __halves2half2(__float2half(ar), __float2half(br));
    lo = *reinterpret_cast<uint32_t*>(&l2);
    return *reinterpret_cast<uint32_t*>(&h2);
}
__device__ __forceinline__ void splith(float v, f16& h, f16& l) {
    h = __float2half(v);
    l = __float2half((v - __half2float(h)) * 2048.f);
}

// ---------------- elementwise / prep kernels ----------------
__global__ void im2col_h(const float* __restrict__ x, f16* __restrict__ Ph,
                         f16* __restrict__ Pl) {
    int idx = blockIdx.x * blockDim.x + threadIdx.x;
    if (idx >= MPATCH * DM) return;
    int k = idx % DM, m = idx / DM;
    int b = m / NPATCH, t = m % NPATCH;
    int py = t / GRID28, px = t % GRID28;
    int c = k >> 8, rem = k & 255, i = rem >> 4, j = rem & 15;
    size_t src = (((size_t)(b * 3 + c) * IMG) + (size_t)(py * PSZ + i)) * IMG + (px * PSZ + j);
    f16 h, l;
    splith(x[src], h, l);
    Ph[idx] = h; Pl[idx] = l;
}

__global__ void split_h(const float* __restrict__ W, f16* __restrict__ Oh,
                        f16* __restrict__ Ol, int n) {
    int idx = blockIdx.x * blockDim.x + threadIdx.x;
    if (idx >= n) return;
    f16 h, l;
    splith(W[idx], h, l);
    Oh[idx] = h; Ol[idx] = l;
}

// W[K,N] row-major -> out[n*K + k] (transpose + fp16 split)
__global__ void wt_trans_h(const float* __restrict__ W, f16* __restrict__ Oh,
                           f16* __restrict__ Ol, int K, int N) {
    __shared__ float tile[32][33];
    int kb = blockIdx.y * 32, nb = blockIdx.x * 32;
    int tx = threadIdx.x, ty = threadIdx.y;  // 32 x 8
#pragma unroll
    for (int i = 0; i < 32; i += 8) {
        int k = kb + ty + i, n = nb + tx;
        tile[ty + i][tx] = (k < K && n < N) ? W[(size_t)k * N + n] : 0.f;
    }
    __syncthreads();
#pragma unroll
    for (int i = 0; i < 32; i += 8) {
        int n = nb + ty + i, k = kb + tx;
        if (n < N && k < K) {
            f16 h, l;
            splith(tile[tx][ty + i], h, l);
            Oh[(size_t)n * K + k] = h;
            Ol[(size_t)n * K + k] = l;
        }
    }
}

__global__ void assemble_kernel(const float* __restrict__ tok, const float* __restrict__ cls,
                                const float* __restrict__ pos, float* __restrict__ H) {
    int idx = blockIdx.x * blockDim.x + threadIdx.x;
    if (idx >= MTOK * DM) return;
    int d = idx % DM;
    int r = idx / DM;
    int n = r % NTOK, b = r / NTOK;
    float v;
    if (n == 0) v = cls[d] + pos[d];
    else        v = tok[((size_t)b * NPATCH + (n - 1)) * DM + d] + pos[(size_t)n * DM + d];
    H[idx] = v;
}

__global__ void ln_kernel(const float* __restrict__ X, const float* __restrict__ g,
                          const float* __restrict__ bb, float* __restrict__ Y,
                          long long inStride, long long outStride) {
    const float* x = X + (long long)blockIdx.x * inStride;
    float* y = Y + (long long)blockIdx.x * outStride;
    int t = threadIdx.x;
    __shared__ float sh[8];
    float v0 = x[t], v1 = x[t + 256], v2 = x[t + 512];
    float mu = blockSum256(v0 + v1 + v2, sh) * (1.0f / 768.0f);
    float d0 = v0 - mu, d1 = v1 - mu, d2 = v2 - mu;
    float var = blockSum256(d0 * d0 + d1 * d1 + d2 * d2, sh) * (1.0f / 768.0f);
    float rs = rsqrtf(var + 1e-5f);
    y[t]       = d0 * rs * g[t]       + bb[t];
    y[t + 256] = d1 * rs * g[t + 256] + bb[t + 256];
    y[t + 512] = d2 * rs * g[t + 512] + bb[t + 512];
}

// LN -> fp16 split pair
__global__ void ln_split_h(const float* __restrict__ X, const float* __restrict__ g,
                           const float* __restrict__ bb, f16* __restrict__ Yh,
                           f16* __restrict__ Yl) {
    const float* x = X + (size_t)blockIdx.x * DM;
    f16* yh = Yh + (size_t)blockIdx.x * DM;
    f16* yl = Yl + (size_t)blockIdx.x * DM;
    int t = threadIdx.x;
    __shared__ float sh[8];
    float v0 = x[t], v1 = x[t + 256], v2 = x[t + 512];
    float mu = blockSum256(v0 + v1 + v2, sh) * (1.0f / 768.0f);
    float d0 = v0 - mu, d1 = v1 - mu, d2 = v2 - mu;
    float var = blockSum256(d0 * d0 + d1 * d1 + d2 * d2, sh) * (1.0f / 768.0f);
    float rs = rsqrtf(var + 1e-5f);
    float o0 = d0 * rs * g[t] + bb[t];
    float o1 = d1 * rs * g[t + 256] + bb[t + 256];
    float o2 = d2 * rs * g[t + 512] + bb[t + 512];
    f16 h, l;
    splith(o0, h, l); yh[t] = h;       yl[t] = l;
    splith(o1, h, l); yh[t + 256] = h; yl[t + 256] = l;
    splith(o2, h, l); yh[t + 512] = h; yl[t + 512] = l;
}

// vT[z][d][t] = qkv[b*785+t][1536 + h*64 + d]  (validated)
__global__ void vt_split(const bf16* __restrict__ Qh, const bf16* __restrict__ Ql,
                         bf16* __restrict__ Vh, bf16* __restrict__ Vl) {
    size_t idx = (size_t)blockIdx.x * blockDim.x + threadIdx.x;
    if (idx >= (size_t)BATCH * HEADS * 64 * SPAD) return;
    int t = (int)(idx % SPAD);
    int d = (int)((idx / SPAD) % 64);
    int z = (int)(idx / ((size_t)SPAD * 64));
    int b = z / HEADS, h = z % HEADS;
    bf16 vh = __float2bfloat16(0.f), vl = vh;
    if (t < NTOK) {
        size_t src = ((size_t)(b * NTOK + t)) * (3 * DM) + 2 * DM + h * 64 + d;
        vh = Qh[src]; vl = Ql[src];
    }
    Vh[idx] = vh; Vl[idx] = vl;
}

// ---------------- fused flash attention (round-8 validated; fp16-pair output) ----------------
static constexpr int ARS    = 144;
static constexpr int KTILE  = 128 * ARS;
static constexpr int VRS    = 272;
static constexpr int VTILE  = 64 * VRS;
static constexpr int KVBUF  = 2 * KTILE + 2 * VTILE;
static constexpr int PRS2   = 272;
static constexpr int SPTILE = 128 * PRS2;
static constexpr int OFF_SPH = 2 * KVBUF;
static constexpr int OFF_SPL = OFF_SPH + SPTILE;
static constexpr int OFF_M  = OFF_SPL + SPTILE;
static constexpr int OFF_L  = OFF_M + 512;
static constexpr int OFF_CA = OFF_L + 512;
static constexpr int OFF_T  = OFF_CA + 512;
static constexpr int FA_SMEM = OFF_T + 1024;
static constexpr int NCHUNK = 7;

__global__ void __launch_bounds__(256, 1)
fused_attn(const bf16* __restrict__ qkvh, const bf16* __restrict__ qkvl,
           const bf16* __restrict__ vth, const bf16* __restrict__ vtl,
           f16* __restrict__ yh, f16* __restrict__ yl) {
    extern __shared__ __align__(16) char smem[];
    uint32_t s0 = s2u(smem);
    const int tid = threadIdx.x, lane = tid & 31, warp = tid >> 5;
    const int qt = blockIdx.x;
    const int z = blockIdx.y;
    const int b = z / HEADS, h = z % HEADS;
    const float SC = 0.125f;

    const int wm0 = warp * 16;
    const uint32_t a_lane  = (uint32_t)(wm0 + (lane & 15)) * ARS + (uint32_t)(lane >> 4) * 16u;
    const uint32_t b_lane  = (uint32_t)((lane & 7) + ((lane >> 4) << 3)) * ARS +
                             (uint32_t)((lane >> 3) & 1) * 16u;
    const uint32_t vb_lane = (uint32_t)((lane & 7) + ((lane >> 4) << 3)) * VRS +
                             (uint32_t)((lane >> 3) & 1) * 16u;
    const uint32_t ap_lane = (uint32_t)(wm0 + (lane & 15)) * PRS2 + (uint32_t)(lane >> 4) * 16u;

    float* mrow = reinterpret_cast<float*>(smem + OFF_M);
    float* lrow = reinterpret_cast<float*>(smem + OFF_L);
    float* crow = reinterpret_cast<float*>(smem + OFF_CA);
    float* tred = reinterpret_cast<float*>(smem + OFF_T);

    auto load_qk = [&](int rowbase, int colbase, uint32_t dsth, uint32_t dstl) {
#pragma unroll
        for (int i = 0; i < 4; i++) {
            int idx = tid + i * 256;
            int r = idx >> 3, g = idx & 7;
            bool v = (rowbase + r) < NTOK;
            size_t off = ((size_t)(b * NTOK + rowbase + r)) * (3 * DM) + colbase + g * 8;
            const bf16* sh2 = v ? (qkvh + off) : qkvh;
            const bf16* sl2 = v ? (qkvl + off) : qkvl;
            uint32_t d = (uint32_t)r * ARS + (uint32_t)g * 16u;
            cp16(dsth + d, sh2, v);
            cp16(dstl + d, sl2, v);
        }
    };
    auto load_vt = [&](int c, uint32_t dsth, uint32_t dstl) {
        const bf16* bh2 = vth + (size_t)z * 64 * SPAD + (size_t)c * 128;
        const bf16* bl2 = vtl + (size_t)z * 64 * SPAD + (size_t)c * 128;
#pragma unroll
        for (int i = 0; i < 4; i++) {
            int idx = tid + i * 256;
            int r = idx >> 4, g = idx & 15;
            size_t off = (size_t)r * SPAD + g * 8;
            uint32_t d = (uint32_t)r * VRS + (uint32_t)g * 16u;
            cp16(dsth + d, bh2 + off, true);
            cp16(dstl + d, bl2 + off, true);
        }
    };
    auto load_chunk = [&](int c, int bsel) {
        uint32_t base = s0 + bsel * KVBUF;
        load_qk(c * 128, DM + h * 64, base, base + KTILE);
        load_vt(c, base + 2 * KTILE, base + 2 * KTILE + VTILE);
        cpcommit();
    };

    load_qk(qt * 128, h * 64, s0 + OFF_SPH, s0 + OFF_SPH + KTILE);
    cpcommit();
    cpwait0();
    __syncthreads();
    uint32_t aQh[4][4], aQl[4][4];
#pragma unroll
    for (int ks = 0; ks < 4; ks++) {
        ldsm4(aQh[ks], s0 + OFF_SPH + a_lane + ks * 32);
        ldsm4(aQl[ks], s0 + OFF_SPH + KTILE + a_lane + ks * 32);
    }
    if (tid < 128) { mrow[tid] = -1e30f; lrow[tid] = 0.f; }
    __syncthreads();

    float o[8][4];
#pragma unroll
    for (int i = 0; i < 8; i++)
#pragma unroll
        for (int j = 0; j < 4; j++) o[i][j] = 0.f;

    load_chunk(0, 0);
    for (int c = 0; c < NCHUNK; c++) {
        if (c + 1 < NCHUNK) { load_chunk(c + 1, (c + 1) & 1); cpwait1(); }
        else                { cpwait0(); }
        __syncthreads();
        uint32_t kvb = s0 + (c & 1) * KVBUF;
        uint32_t Kh = kvb, Kl = kvb + KTILE;
        uint32_t Vh = kvb + 2 * KTILE, Vl = kvb + 2 * KTILE + VTILE;

        float s[16][4];
#pragma unroll
        for (int j = 0; j < 16; j++)
#pragma unroll
            for (int q = 0; q < 4; q++) s[j][q] = 0.f;
#pragma unroll
        for (int ks = 0; ks < 4; ks++) {
#pragma unroll
            for (int jp = 0; jp < 8; jp++) {
                uint32_t kh[4], kl[4];
                uint32_t koff = b_lane + (uint32_t)jp * (16 * ARS) + (uint32_t)ks * 32u;
                ldsm4(kh, Kh + koff);
                ldsm4(kl, Kl + koff);
#pragma unroll
                for (int hf = 0; hf < 2; hf++) {
                    int j = jp * 2 + hf;
                    mma16816(s[j], aQh[ks], &kh[hf * 2]);
                    mma16816(s[j], aQh[ks], &kl[hf * 2]);
                    mma16816(s[j], aQl[ks], &kh[hf * 2]);
                }
            }
        }

        {
            char* smp = smem;
            int r0 = wm0 + (lane >> 2);
            int c0 = 2 * (lane & 3);
#pragma unroll
            for (int j = 0; j < 16; j++) {
                int cc = j * 8 + c0;
                uint32_t loA, hiA = packsplit_hi(s[j][0], s[j][1], loA);
                uint32_t loB, hiB = packsplit_hi(s[j][2], s[j][3], loB);
                *(uint32_t*)(smp + OFF_SPH + (uint32_t)r0 * PRS2 + cc * 2) = hiA;
                *(uint32_t*)(smp + OFF_SPL + (uint32_t)r0 * PRS2 + cc * 2) = loA;
                *(uint32_t*)(smp + OFF_SPH + (uint32_t)(r0 + 8) * PRS2 + cc * 2) = hiB;
                *(uint32_t*)(smp + OFF_SPL + (uint32_t)(r0 + 8) * PRS2 + cc * 2) = loB;
            }
        }
        __syncthreads();

        const int r = tid >> 1, half = tid & 1;
        char* smp = smem;
        const uint32_t rowoff = (uint32_t)r * PRS2 + (uint32_t)half * 128u;
        const int colbase = c * 128 + half * 64;
        const int nvalid0 = NTOK - colbase;
        const int nvalid = nvalid0 < 0 ? 0 : (nvalid0 > 64 ? 64 : nvalid0);

        float chmax = -1e30f;
#pragma unroll 8
        for (int k = 0; k < 64; k += 2) {
            uint32_t hi = *(uint32_t*)(smp + OFF_SPH + rowoff + k * 2);
            uint32_t lo = *(uint32_t*)(smp + OFF_SPL + rowoff + k * 2);
            __nv_bfloat162 h2 = *reinterpret_cast<__nv_bfloat162*>(&hi);
            __nv_bfloat162 l2 = *reinterpret_cast<__nv_bfloat162*>(&lo);
            float v0 = __bfloat162float(h2.x) + __bfloat162float(l2.x);
            float v1 = __bfloat162float(h2.y) + __bfloat162float(l2.y);
            if (k < nvalid)     chmax = fmaxf(chmax, v0);
            if (k + 1 < nvalid) chmax = fmaxf(chmax, v1);
        }
        tred[tid] = chmax;
        __syncthreads();
        float m_old = mrow[r];
        float rmax = fmaxf(tred[2 * r], tred[2 * r + 1]);
        float m_new = fmaxf(m_old, rmax);
        float ca = __expf(SC * (m_old - m_new));
        __syncthreads();

        float esum = 0.f;
#pragma unroll 8
        for (int k = 0; k < 64; k += 2) {
            uint32_t hi = *(uint32_t*)(smp + OFF_SPH + rowoff + k * 2);
            uint32_t lo = *(uint32_t*)(smp + OFF_SPL + rowoff + k * 2);
            __nv_bfloat162 h2 = *reinterpret_cast<__nv_bfloat162*>(&hi);
            __nv_bfloat162 l2 = *reinterpret_cast<__nv_bfloat162*>(&lo);
            float v0 = __bfloat162float(h2.x) + __bfloat162float(l2.x);
            float v1 = __bfloat162float(h2.y) + __bfloat162float(l2.y);
            float e0 = (k < nvalid)     ? __expf(SC * (v0 - m_new)) : 0.f;
            float e1 = (k + 1 < nvalid) ? __expf(SC * (v1 - m_new)) : 0.f;
            esum += e0 + e1;
            uint32_t plo, phi = packsplit_hi(e0, e1, plo);
            *(uint32_t*)(smp + OFF_SPH + rowoff + k * 2) = phi;
            *(uint32_t*)(smp + OFF_SPL + rowoff + k * 2) = plo;
        }
        tred[tid] = esum;
        __syncthreads();
        if (half == 0) {
            lrow[r] = lrow[r] * ca + tred[2 * r] + tred[2 * r + 1];
            mrow[r] = m_new;
            crow[r] = ca;
        }
        __syncthreads();

        float caA = crow[wm0 + (lane >> 2)];
        float caB = crow[wm0 + 8 + (lane >> 2)];
#pragma unroll
        for (int nt = 0; nt < 8; nt++) {
            o[nt][0] *= caA; o[nt][1] *= caA;
            o[nt][2] *= caB; o[nt][3] *= caB;
        }

#pragma unroll
        for (int kt = 0; kt < 8; kt++) {
            uint32_t pa[4], pb[4];
            ldsm4(pa, s0 + OFF_SPH + ap_lane + (uint32_t)kt * 32u);
            ldsm4(pb, s0 + OFF_SPL + ap_lane + (uint32_t)kt * 32u);
#pragma unroll
            for (int dp = 0; dp < 4; dp++) {
                uint32_t vh[4], vl[4];
                uint32_t voff = vb_lane + (uint32_t)dp * (16 * VRS) + (uint32_t)kt * 32u;
                ldsm4(vh, Vh + voff);
                ldsm4(vl, Vl + voff);
#pragma unroll
                for (int hf = 0; hf < 2; hf++) {
                    int nt = dp * 2 + hf;
                    mma16816(o[nt], pa, &vh[hf * 2]);
                    mma16816(o[nt], pa, &vl[hf * 2]);
                    mma16816(o[nt], pb, &vh[hf * 2]);
                }
            }
        }
        __syncthreads();
    }

    // normalize + store fp16 split pair (consumed by proj GEMM)
    float la = lrow[wm0 + (lane >> 2)];
    float lb = lrow[wm0 + 8 + (lane >> 2)];
    float ia = 1.0f / la, ib = 1.0f / lb;
    int ra = qt * 128 + wm0 + (lane >> 2);
    int rb = ra + 8;
#pragma unroll
    for (int nt = 0; nt < 8; nt++) {
        int col = h * 64 + nt * 8 + 2 * (lane & 3);
        if (ra < NTOK) {
            size_t p = (size_t)(b * NTOK + ra) * DM + col;
            uint32_t lo, hi = packsplit_h(o[nt][0] * ia, o[nt][1] * ia, lo);
            *reinterpret_cast<uint32_t*>(yh + p) = hi;
            *reinterpret_cast<uint32_t*>(yl + p) = lo;
        }
        if (rb < NTOK) {
            size_t p = (size_t)(b * NTOK + rb) * DM + col;
            uint32_t lo, hi = packsplit_h(o[nt][2] * ib, o[nt][3] * ib, lo);
            *reinterpret_cast<uint32_t*>(yh + p) = hi;
            *reinterpret_cast<uint32_t*>(yl + p) = lo;
        }
    }
}

// ---------------- fp16 split GEMM: lead f32-acc + shared f16-acc cross ----------------
// C = (Ah+Al/2048)(Bh+Bl/2048) ~= AhBh [f32 acc] + (AhBl' + Al'Bh) [f16 acc] / 2048
// BM=128, BN=128, BK=64, 8 warps (64x32 each), double-buffered cp.async.
// EPI: 0 fp32 (+bias?+res?), 1 bf16 split (+bias) [qkv], 2 fp16 split gelu (+bias)
template <int EPI>
__global__ void __launch_bounds__(256, 1)
h16_gemm(const f16* __restrict__ Ahi, const f16* __restrict__ Alo, int lda,
         const f16* __restrict__ Bhi, const f16* __restrict__ Blo, int ldb,
         float* __restrict__ Cf, bf16* __restrict__ Cbh, bf16* __restrict__ Cbl,
         f16* __restrict__ Chh, f16* __restrict__ Chl, int ldc,
         const float* __restrict__ bias, const float* __restrict__ res,
         int M, int N, int NC) {
    constexpr int RS  = 144;
    constexpr int ASZ = 128 * RS;
    constexpr int BUF = 4 * ASZ;     // Ah,Al,Bh,Bl

    extern __shared__ __align__(16) char smem[];
    uint32_t s0 = s2u(smem);

    const int tid = threadIdx.x, lane = tid & 31, warp = tid >> 5;
    const int wm0 = (warp / 4) * 64;
    const int wn0 = (warp % 4) * 32;
    const int row0 = blockIdx.y * 128, col0 = blockIdx.x * 128;

    float lead[4][4][4];
    uint32_t cross[4][4][2];
#pragma unroll
    for (int i = 0; i < 4; i++)
#pragma unroll
        for (int j = 0; j < 4; j++) {
#pragma unroll
            for (int k = 0; k < 4; k++) lead[i][j][k] = 0.f;
            cross[i][j][0] = 0u; cross[i][j][1] = 0u;
        }

    const uint32_t a_lane = (uint32_t)(wm0 + (lane & 15)) * RS + (uint32_t)(lane >> 4) * 16u;
    const uint32_t b_lane = (uint32_t)(wn0 + (lane & 7) + ((lane >> 4) << 3)) * RS +
                            (uint32_t)((lane >> 3) & 1) * 16u;

    auto load_chunk = [&](int ck, int bsel) {
        uint32_t base = s0 + bsel * BUF;
#pragma unroll
        for (int i = 0; i < 4; i++) {
            int idx = tid + i * 256;
            int r = idx >> 3, c = idx & 7;
            int gm = row0 + r;
            bool v = gm < M;
            const f16* ph = v ? (Ahi + (size_t)gm * lda + (size_t)ck * 64 + c * 8) : Ahi;
            const f16* pl = v ? (Alo + (size_t)gm * lda + (size_t)ck * 64 + c * 8) : Alo;
            uint32_t d = base + (uint32_t)r * RS + (uint32_t)c * 16u;
            cp16(d, ph, v);
            cp16(d + ASZ, pl, v);
        }
#pragma unroll
        for (int i = 0; i < 4; i++) {
            int idx = tid + i * 256;
            int r = idx >> 3, c = idx & 7;
            int gn = col0 + r;
            bool v = gn < N;
            const f16* ph = v ? (Bhi + (size_t)gn * ldb + (size_t)ck * 64 + c * 8) : Bhi;
            const f16* pl = v ? (Blo + (size_t)gn * ldb + (size_t)ck * 64 + c * 8) : Blo;
            uint32_t d = base + 2 * ASZ + (uint32_t)r * RS + (uint32_t)c * 16u;
            cp16(d, ph, v);
            cp16(d + ASZ, pl, v);
        }
        cpcommit();
    };

    auto compute = [&](int bsel) {
        uint32_t base = s0 + bsel * BUF;
        uint32_t ah = base, al = base + ASZ, bh = base + 2 * ASZ, bl = base + 3 * ASZ;
#pragma unroll
        for (int ks = 0; ks < 4; ks++) {
            uint32_t afh[4][4], afl[4][4];
#pragma unroll
            for (int mt = 0; mt < 4; mt++) {
                uint32_t off = a_lane + (uint32_t)mt * (16 * RS) + (uint32_t)ks * 32u;
                ldsm4(afh[mt], ah + off);
                ldsm4(afl[mt], al + off);
            }
            uint32_t bfh[2][4], bfl[2][4];
#pragma unroll
            for (int np = 0; np < 2; np++) {
                uint32_t off = b_lane + (uint32_t)np * (16 * RS) + (uint32_t)ks * 32u;
                ldsm4(bfh[np], bh + off);
                ldsm4(bfl[np], bl + off);
            }
#pragma unroll
            for (int mt = 0; mt < 4; mt++)
#pragma unroll
                for (int nt = 0; nt < 4; nt++) {
                    const uint32_t* Bh2 = &bfh[nt >> 1][(nt & 1) * 2];
                    const uint32_t* Bl2 = &bfl[nt >> 1][(nt & 1) * 2];
                    mma_h_f32(lead[mt][nt], afh[mt], Bh2);
                    mma_h_f16(cross[mt][nt], afh[mt], Bl2);
                    mma_h_f16(cross[mt][nt], afl[mt], Bh2);
                }
        }
    };

    load_chunk(0, 0);
    for (int ck = 0; ck < NC; ck++) {
        if (ck + 1 < NC) { load_chunk(ck + 1, (ck + 1) & 1); cpwait1(); }
        else             { cpwait0(); }
        __syncthreads();
        compute(ck & 1);
        __syncthreads();
    }

    const float INV = 1.0f / 2048.0f;
#pragma unroll
    for (int mt = 0; mt < 4; mt++) {
#pragma unroll
        for (int nt = 0; nt < 4; nt++) {
            int r0 = row0 + wm0 + mt * 16 + (lane >> 2);
            int c0 = col0 + wn0 + nt * 8 + (lane & 3) * 2;
            float* a4 = lead[mt][nt];
#pragma unroll
            for (int h = 0; h < 2; h++) {
                int gm = r0 + h * 8;
                if (gm >= M) continue;
                __half2 cx = *reinterpret_cast<__half2*>(&cross[mt][nt][h]);
                float v0 = a4[h * 2]     + __half2float(cx.x) * INV;
                float v1 = a4[h * 2 + 1] + __half2float(cx.y) * INV;
                if (bias) { v0 += bias[c0]; v1 += bias[c0 + 1]; }
                if (EPI == 0) {
                    if (res) {
                        v0 += res[(size_t)gm * ldc + c0];
                        v1 += res[(size_t)gm * ldc + c0 + 1];
                    }
                    Cf[(size_t)gm * ldc + c0]     = v0;
                    Cf[(size_t)gm * ldc + c0 + 1] = v1;
                } else if (EPI == 1) {
                    uint32_t lo, hi = packsplit_hi(v0, v1, lo);
                    *reinterpret_cast<uint32_t*>(Cbh + (size_t)gm * ldc + c0) = hi;
                    *reinterpret_cast<uint32_t*>(Cbl + (size_t)gm * ldc + c0) = lo;
                } else {
                    v0 = geluf(v0); v1 = geluf(v1);
                    uint32_t lo, hi = packsplit_h(v0, v1, lo);
                    *reinterpret_cast<uint32_t*>(Chh + (size_t)gm * ldc + c0) = hi;
                    *reinterpret_cast<uint32_t*>(Chl + (size_t)gm * ldc + c0) = lo;
                }
            }
        }
    }
}

template <int EPI>
static void hgemm(const f16* Ah, const f16* Al, int lda,
                  const f16* Bh, const f16* Bl, int ldb,
                  float* Cf, bf16* Cbh, bf16* Cbl, f16* Chh, f16* Chl, int ldc,
                  const float* bias, const float* res, int M, int N, int K) {
    constexpr int BUF = 4 * 128 * 144;
    int smem = 2 * BUF;
    cudaFuncSetAttribute(h16_gemm<EPI>, cudaFuncAttributeMaxDynamicSharedMemorySize, smem);
    dim3 grid(N / 128, (M + 127) / 128, 1);
    h16_gemm<EPI><<<grid, 256, smem>>>(Ah, Al, lda, Bh, Bl, ldb, Cf, Cbh, Cbl, Chh, Chl,
                                       ldc, bias, res, M, N, K / 64);
}

extern "C" void kernel_launch(void* const* d_in, const int* in_sizes, int n_in,
                              void* d_out, int out_size) {
    const float* x       = (const float*)d_in[0];
    const float* conv_w  = (const float*)d_in[1];
    const float* conv_b  = (const float*)d_in[2];
    const float* cls_tok = (const float*)d_in[3];
    const float* pos_emb = (const float*)d_in[4];
    const float* ln1_g   = (const float*)d_in[5];
    const float* ln1_b   = (const float*)d_in[6];
    const float* qkv_w   = (const float*)d_in[7];
    const float* qkv_b   = (const float*)d_in[8];
    const float* proj_w  = (const float*)d_in[9];
    const float* proj_b  = (const float*)d_in[10];
    const float* ln2_g   = (const float*)d_in[11];
    const float* ln2_b   = (const float*)d_in[12];
    const float* mlp_w1  = (const float*)d_in[13];
    const float* mlp_b1  = (const float*)d_in[14];
    const float* mlp_w2  = (const float*)d_in[15];
    const float* mlp_b2  = (const float*)d_in[16];
    const float* lnf_g   = (const float*)d_in[17];
    const float* lnf_b   = (const float*)d_in[18];
    float* out = (float*)d_out;

    f16 *wh, *wl, *cwh, *cwl, *pxh, *pxl, *xh, *xl, *ahp, *alp, *mh, *ml;
    float *ph, *ptmp;
    bf16 *qhi, *qlo, *vthi, *vtlo;
    cudaGetSymbolAddress((void**)&wh, g_wh);
    cudaGetSymbolAddress((void**)&wl, g_wl);
    cudaGetSymbolAddress((void**)&cwh, g_cwh);
    cudaGetSymbolAddress((void**)&cwl, g_cwl);
    cudaGetSymbolAddress((void**)&pxh, g_pxh);
    cudaGetSymbolAddress((void**)&pxl, g_pxl);
    cudaGetSymbolAddress((void**)&xh, g_xh);
    cudaGetSymbolAddress((void**)&xl, g_xl);
    cudaGetSymbolAddress((void**)&ahp, g_ah);
    cudaGetSymbolAddress((void**)&alp, g_al);
    cudaGetSymbolAddress((void**)&mh, g_mh);
    cudaGetSymbolAddress((void**)&ml, g_ml);
    cudaGetSymbolAddress((void**)&ph, g_h);
    cudaGetSymbolAddress((void**)&ptmp, g_ptmp);
    cudaGetSymbolAddress((void**)&qhi, g_qhi);
    cudaGetSymbolAddress((void**)&qlo, g_qlo);
    cudaGetSymbolAddress((void**)&vthi, g_vthi);
    cudaGetSymbolAddress((void**)&vtlo, g_vtlo);

    dim3 tb(32, 8);

    // ---- weight prep (fp16 split) ----
    split_h<<<(DM * DM + 255) / 256, 256>>>(conv_w, cwh, cwl, DM * DM);
    for (int l = 0; l < LAYERS; l++) {
        long long wo = (long long)l * LW;
        wt_trans_h<<<dim3(2304 / 32, 768 / 32), tb>>>(qkv_w + (size_t)l * DM * 3 * DM,
                                                      wh + wo, wl + wo, DM, 3 * DM);
        wt_trans_h<<<dim3(768 / 32, 768 / 32), tb>>>(proj_w + (size_t)l * DM * DM,
                                                     wh + wo + 1769472, wl + wo + 1769472, DM, DM);
        wt_trans_h<<<dim3(3072 / 32, 768 / 32), tb>>>(mlp_w1 + (size_t)l * DM * 4 * DM,
                                                      wh + wo + 2359296, wl + wo + 2359296, DM, 4 * DM);
        wt_trans_h<<<dim3(768 / 32, 3072 / 32), tb>>>(mlp_w2 + (size_t)l * 4 * DM * DM,
                                                      wh + wo + 4718592, wl + wo + 4718592, 4 * DM, DM);
    }

    // ---- patch embed ----
    im2col_h<<<(MPATCH * DM + 255) / 256, 256>>>(x, pxh, pxl);
    hgemm<0>(pxh, pxl, DM, cwh, cwl, DM, ptmp, nullptr, nullptr, nullptr, nullptr, DM,
             conv_b, nullptr, MPATCH, DM, DM);
    assemble_kernel<<<(MTOK * DM + 255) / 256, 256>>>(ptmp, cls_tok, pos_emb, ph);

    cudaFuncSetAttribute(fused_attn, cudaFuncAttributeMaxDynamicSharedMemorySize, FA_SMEM);

    for (int l = 0; l < LAYERS; l++) {
        long long wo = (long long)l * LW;
        const f16* qwT_h = wh + wo;            const f16* qwT_l = wl + wo;
        const f16* pwT_h = wh + wo + 1769472;  const f16* pwT_l = wl + wo + 1769472;
        const f16* w1T_h = wh + wo + 2359296;  const f16* w1T_l = wl + wo + 2359296;
        const f16* w2T_h = wh + wo + 4718592;  const f16* w2T_l = wl + wo + 4718592;
        const float* l1g = ln1_g + (size_t)l * DM;
        const float* l1b = ln1_b + (size_t)l * DM;
        const float* qb  = qkv_b + (size_t)l * 3 * DM;
        const float* pb  = proj_b + (size_t)l * DM;
        const float* l2g = ln2_g + (size_t)l * DM;
        const float* l2b = ln2_b + (size_t)l * DM;
        const float* b1  = mlp_b1 + (size_t)l * 4 * DM;
        const float* b2  = mlp_b2 + (size_t)l * DM;

        // LN1 -> fp16 pair
        ln_split_h<<<MTOK, 256>>>(ph, l1g, l1b, xh, xl);
        // QKV -> bf16 pair (attention input)
        hgemm<1>(xh, xl, DM, qwT_h, qwT_l, DM, nullptr, qhi, qlo, nullptr, nullptr, 3 * DM,
                 qb, nullptr, MTOK, 3 * DM, DM);
        // V transpose (validated)
        {
            size_t n = (size_t)BATCH * HEADS * 64 * SPAD;
            vt_split<<<(unsigned)((n + 255) / 256), 256>>>(qhi, qlo, vthi, vtlo);
        }
        // fused attention -> fp16 pair
        fused_attn<<<dim3(NCHUNK, BATCH * HEADS), 256, FA_SMEM>>>(qhi, qlo, vthi, vtlo,
                                                                  ahp, alp);
        // proj + bias + residual -> h
        hgemm<0>(ahp, alp, DM, pwT_h, pwT_l, DM, ph, nullptr, nullptr, nullptr, nullptr, DM,
                 pb, ph, MTOK, DM, DM);
        // LN2 -> fp16 pair
        ln_split_h<<<MTOK, 256>>>(ph, l2g, l2b, xh, xl);
        // MLP1 + gelu -> fp16 pair
        hgemm<2>(xh, xl, DM, w1T_h, w1T_l, DM, nullptr, nullptr, nullptr, mh, ml, 4 * DM,
                 b1, nullptr, MTOK, 4 * DM, DM);
        // MLP2 + bias + residual -> h
        hgemm<0>(mh, ml, 4 * DM, w2T_h, w2T_l, 4 * DM, ph, nullptr, nullptr, nullptr, nullptr, DM,
                 b2, ph, MTOK, DM, 4 * DM);
    }

    // final LN on CLS rows -> out [8,768]
    ln_kernel<<<BATCH, 256>>>(ph, lnf_g, lnf_b, out, (long long)NTOK * DM, DM);
}

// round 11
// speedup vs baseline: 2.4992x; 1.0700x over previous
#include <cuda_runtime.h>
#include <cuda_bf16.h>
#include <cuda_fp16.h>
#include <math.h>
#include <stdint.h>

using bf16 = __nv_bfloat16;
using f16 = __half;

// ---------------- problem constants ----------------
static constexpr int BATCH  = 8;
static constexpr int DM     = 768;
static constexpr int HEADS  = 12;
static constexpr int LAYERS = 12;
static constexpr int NTOK   = 785;
static constexpr int NPATCH = 784;
static constexpr int MTOK   = BATCH * NTOK;    // 6280
static constexpr int MPATCH = BATCH * NPATCH;  // 6272
static constexpr int IMG    = 448;
static constexpr int PSZ    = 16;
static constexpr int GRID28 = 28;
static constexpr int SPAD   = 896;
static constexpr long long LW = 7077888LL;

// ---------------- device scratch ----------------
__device__ f16  g_wh[(size_t)LAYERS * LW];
__device__ f16  g_wl[(size_t)LAYERS * LW];
__device__ f16  g_cwh[DM * DM];
__device__ f16  g_cwl[DM * DM];
__device__ f16  g_pxh[(size_t)MPATCH * DM];
__device__ f16  g_pxl[(size_t)MPATCH * DM];
__device__ f16  g_xh[(size_t)MTOK * DM];       // LN out (GEMM A)
__device__ f16  g_xl[(size_t)MTOK * DM];
__device__ f16  g_ah[(size_t)MTOK * DM];       // attn out (GEMM A)
__device__ f16  g_al[(size_t)MTOK * DM];
__device__ f16  g_mh[(size_t)MTOK * 4 * DM];   // mlp mid
__device__ f16  g_ml[(size_t)MTOK * 4 * DM];
__device__ float g_h[(size_t)MTOK * DM];
__device__ float g_ptmp[(size_t)MPATCH * DM];
__device__ bf16  g_qhi[(size_t)MTOK * 3 * DM];
__device__ bf16  g_qlo[(size_t)MTOK * 3 * DM];
__device__ bf16  g_vthi[(size_t)BATCH * HEADS * 64 * SPAD];
__device__ bf16  g_vtlo[(size_t)BATCH * HEADS * 64 * SPAD];

// ---------------- small helpers ----------------
__device__ __forceinline__ void split2(float v, bf16& h, bf16& l) {
    h = __float2bfloat16(v);
    l = __float2bfloat16(v - __bfloat162float(h));
}
__device__ __forceinline__ float geluf(float v) {
    return 0.5f * v * (1.0f + erff(v * 0.70710678118654752f));
}
__device__ __forceinline__ float warpSum(float v) {
#pragma unroll
    for (int o = 16; o > 0; o >>= 1) v += __shfl_xor_sync(0xffffffffu, v, o);
    return v;
}
__device__ __forceinline__ float blockSum256(float v, float* sh) {
    int lane = threadIdx.x & 31, w = threadIdx.x >> 5;
    v = warpSum(v);
    if (lane == 0) sh[w] = v;
    __syncthreads();
    float r = (threadIdx.x < 8) ? sh[threadIdx.x] : 0.f;
    if (w == 0) { r = warpSum(r); if (lane == 0) sh[0] = r; }
    __syncthreads();
    r = sh[0];
    __syncthreads();
    return r;
}

// ---------------- PTX wrappers ----------------
__device__ __forceinline__ uint32_t s2u(const void* p) {
    uint32_t a;
    asm("{ .reg .u64 t; cvta.to.shared.u64 t, %1; cvt.u32.u64 %0, t; }" : "=r"(a) : "l"(p));
    return a;
}
__device__ __forceinline__ void cp16(uint32_t d, const void* s, bool pred) {
    int sz = pred ? 16 : 0;
    asm volatile("cp.async.cg.shared.global [%0], [%1], 16, %2;" :: "r"(d), "l"(s), "r"(sz));
}
__device__ __forceinline__ void cpcommit() { asm volatile("cp.async.commit_group;" ::: "memory"); }
__device__ __forceinline__ void cpwait0()  { asm volatile("cp.async.wait_group 0;" ::: "memory"); }
__device__ __forceinline__ void cpwait1()  { asm volatile("cp.async.wait_group 1;" ::: "memory"); }
__device__ __forceinline__ void ldsm4(uint32_t* r, uint32_t addr) {
    asm volatile("ldmatrix.sync.aligned.m8n8.x4.shared.b16 {%0,%1,%2,%3}, [%4];"
                 : "=r"(r[0]), "=r"(r[1]), "=r"(r[2]), "=r"(r[3]) : "r"(addr));
}
// bf16 operands, f32 acc (validated; attention only)
__device__ __forceinline__ void mma16816(float* c, const uint32_t* a, const uint32_t* b) {
    asm volatile(
        "mma.sync.aligned.m16n8k16.row.col.f32.bf16.bf16.f32 "
        "{%0,%1,%2,%3}, {%4,%5,%6,%7}, {%8,%9}, {%0,%1,%2,%3};"
        : "+f"(c[0]), "+f"(c[1]), "+f"(c[2]), "+f"(c[3])
        : "r"(a[0]), "r"(a[1]), "r"(a[2]), "r"(a[3]), "r"(b[0]), "r"(b[1]));
}
// f16 operands, f32 acc (lead term)
__device__ __forceinline__ void mma_h_f32(float* c, const uint32_t* a, const uint32_t* b) {
    asm volatile(
        "mma.sync.aligned.m16n8k16.row.col.f32.f16.f16.f32 "
        "{%0,%1,%2,%3}, {%4,%5,%6,%7}, {%8,%9}, {%0,%1,%2,%3};"
        : "+f"(c[0]), "+f"(c[1]), "+f"(c[2]), "+f"(c[3])
        : "r"(a[0]), "r"(a[1]), "r"(a[2]), "r"(a[3]), "r"(b[0]), "r"(b[1]));
}
// f16 operands, f16 acc (cross terms; 2 C regs)
__device__ __forceinline__ void mma_h_f16(uint32_t* c, const uint32_t* a, const uint32_t* b) {
    asm volatile(
        "mma.sync.aligned.m16n8k16.row.col.f16.f16.f16.f16 "
        "{%0,%1}, {%2,%3,%4,%5}, {%6,%7}, {%0,%1};"
        : "+r"(c[0]), "+r"(c[1])
        : "r"(a[0]), "r"(a[1]), "r"(a[2]), "r"(a[3]), "r"(b[0]), "r"(b[1]));
}
// bf16 split pack (attention internals; validated)
__device__ __forceinline__ uint32_t packsplit_hi(float a, float b, uint32_t& lo) {
    bf16 ah, al, bh, bl;
    split2(a, ah, al);
    split2(b, bh, bl);
    __nv_bfloat162 h2; h2.x = ah; h2.y = bh;
    __nv_bfloat162 l2; l2.x = al; l2.y = bl;
    lo = *reinterpret_cast<uint32_t*>(&l2);
    return *reinterpret_cast<uint32_t*>(&h2);
}
// fp16 split pack: hi = rn(x), lo = (x - hi) * 2048 (normal-range)
__device__ __forceinline__ uint32_t packsplit_h(float a, float b, uint32_t& lo) {
    f16 ah = __float2half(a), bh = __float2half(b);
    float ar = (a - __half2float(ah)) * 2048.f;
    float br = (b - __half2float(bh)) * 2048.f;
    __half2 h2 = __halves2half2(ah, bh);
    __half2 l2 = __halves2half2(__float2half(ar), __float2half(br));
    lo = *reinterpret_cast<uint32_t*>(&l2);
    return *reinterpret_cast<uint32_t*>(&h2);
}
__device__ __forceinline__ void splith(float v, f16& h, f16& l) {
    h = __float2half(v);
    l = __float2half((v - __half2float(h)) * 2048.f);
}

// ---------------- elementwise / prep kernels ----------------
__global__ void im2col_h(const float* __restrict__ x, f16* __restrict__ Ph,
                         f16* __restrict__ Pl) {
    int idx = blockIdx.x * blockDim.x + threadIdx.x;
    if (idx >= MPATCH * DM) return;
    int k = idx % DM, m = idx / DM;
    int b = m / NPATCH, t = m % NPATCH;
    int py = t / GRID28, px = t % GRID28;
    int c = k >> 8, rem = k & 255, i = rem >> 4, j = rem & 15;
    size_t src = (((size_t)(b * 3 + c) * IMG) + (size_t)(py * PSZ + i)) * IMG + (px * PSZ + j);
    f16 h, l;
    splith(x[src], h, l);
    Ph[idx] = h; Pl[idx] = l;
}

__global__ void split_h(const float* __restrict__ W, f16* __restrict__ Oh,
                        f16* __restrict__ Ol, int n) {
    int idx = blockIdx.x * blockDim.x + threadIdx.x;
    if (idx >= n) return;
    f16 h, l;
    splith(W[idx], h, l);
    Oh[idx] = h; Ol[idx] = l;
}

// W[K,N] row-major -> out[n*K + k] (transpose + fp16 split)
__global__ void wt_trans_h(const float* __restrict__ W, f16* __restrict__ Oh,
                           f16* __restrict__ Ol, int K, int N) {
    __shared__ float tile[32][33];
    int kb = blockIdx.y * 32, nb = blockIdx.x * 32;
    int tx = threadIdx.x, ty = threadIdx.y;  // 32 x 8
#pragma unroll
    for (int i = 0; i < 32; i += 8) {
        int k = kb + ty + i, n = nb + tx;
        tile[ty + i][tx] = (k < K && n < N) ? W[(size_t)k * N + n] : 0.f;
    }
    __syncthreads();
#pragma unroll
    for (int i = 0; i < 32; i += 8) {
        int n = nb + ty + i, k = kb + tx;
        if (n < N && k < K) {
            f16 h, l;
            splith(tile[tx][ty + i], h, l);
            Oh[(size_t)n * K + k] = h;
            Ol[(size_t)n * K + k] = l;
        }
    }
}

__global__ void assemble_kernel(const float* __restrict__ tok, const float* __restrict__ cls,
                                const float* __restrict__ pos, float* __restrict__ H) {
    int idx = blockIdx.x * blockDim.x + threadIdx.x;
    if (idx >= MTOK * DM) return;
    int d = idx % DM;
    int r = idx / DM;
    int n = r % NTOK, b = r / NTOK;
    float v;
    if (n == 0) v = cls[d] + pos[d];
    else        v = tok[((size_t)b * NPATCH + (n - 1)) * DM + d] + pos[(size_t)n * DM + d];
    H[idx] = v;
}

__global__ void ln_kernel(const float* __restrict__ X, const float* __restrict__ g,
                          const float* __restrict__ bb, float* __restrict__ Y,
                          long long inStride, long long outStride) {
    const float* x = X + (long long)blockIdx.x * inStride;
    float* y = Y + (long long)blockIdx.x * outStride;
    int t = threadIdx.x;
    __shared__ float sh[8];
    float v0 = x[t], v1 = x[t + 256], v2 = x[t + 512];
    float mu = blockSum256(v0 + v1 + v2, sh) * (1.0f / 768.0f);
    float d0 = v0 - mu, d1 = v1 - mu, d2 = v2 - mu;
    float var = blockSum256(d0 * d0 + d1 * d1 + d2 * d2, sh) * (1.0f / 768.0f);
    float rs = rsqrtf(var + 1e-5f);
    y[t]       = d0 * rs * g[t]       + bb[t];
    y[t + 256] = d1 * rs * g[t + 256] + bb[t + 256];
    y[t + 512] = d2 * rs * g[t + 512] + bb[t + 512];
}

// LN -> fp16 split pair
__global__ void ln_split_h(const float* __restrict__ X, const float* __restrict__ g,
                           const float* __restrict__ bb, f16* __restrict__ Yh,
                           f16* __restrict__ Yl) {
    const float* x = X + (size_t)blockIdx.x * DM;
    f16* yh = Yh + (size_t)blockIdx.x * DM;
    f16* yl = Yl + (size_t)blockIdx.x * DM;
    int t = threadIdx.x;
    __shared__ float sh[8];
    float v0 = x[t], v1 = x[t + 256], v2 = x[t + 512];
    float mu = blockSum256(v0 + v1 + v2, sh) * (1.0f / 768.0f);
    float d0 = v0 - mu, d1 = v1 - mu, d2 = v2 - mu;
    float var = blockSum256(d0 * d0 + d1 * d1 + d2 * d2, sh) * (1.0f / 768.0f);
    float rs = rsqrtf(var + 1e-5f);
    float o0 = d0 * rs * g[t] + bb[t];
    float o1 = d1 * rs * g[t + 256] + bb[t + 256];
    float o2 = d2 * rs * g[t + 512] + bb[t + 512];
    f16 h, l;
    splith(o0, h, l); yh[t] = h;       yl[t] = l;
    splith(o1, h, l); yh[t + 256] = h; yl[t + 256] = l;
    splith(o2, h, l); yh[t + 512] = h; yl[t + 512] = l;
}

// vT[z][d][t] = qkv[b*785+t][1536 + h*64 + d]  (validated)
__global__ void vt_split(const bf16* __restrict__ Qh, const bf16* __restrict__ Ql,
                         bf16* __restrict__ Vh, bf16* __restrict__ Vl) {
    size_t idx = (size_t)blockIdx.x * blockDim.x + threadIdx.x;
    if (idx >= (size_t)BATCH * HEADS * 64 * SPAD) return;
    int t = (int)(idx % SPAD);
    int d = (int)((idx / SPAD) % 64);
    int z = (int)(idx / ((size_t)SPAD * 64));
    int b = z / HEADS, h = z % HEADS;
    bf16 vh = __float2bfloat16(0.f), vl = vh;
    if (t < NTOK) {
        size_t src = ((size_t)(b * NTOK + t)) * (3 * DM) + 2 * DM + h * 64 + d;
        vh = Qh[src]; vl = Ql[src];
    }
    Vh[idx] = vh; Vl[idx] = vl;
}

// ---------------- fused flash attention (round-8 validated; fp16-pair output) ----------------
static constexpr int ARS    = 144;
static constexpr int KTILE  = 128 * ARS;
static constexpr int VRS    = 272;
static constexpr int VTILE  = 64 * VRS;
static constexpr int KVBUF  = 2 * KTILE + 2 * VTILE;
static constexpr int PRS2   = 272;
static constexpr int SPTILE = 128 * PRS2;
static constexpr int OFF_SPH = 2 * KVBUF;
static constexpr int OFF_SPL = OFF_SPH + SPTILE;
static constexpr int OFF_M  = OFF_SPL + SPTILE;
static constexpr int OFF_L  = OFF_M + 512;
static constexpr int OFF_CA = OFF_L + 512;
static constexpr int OFF_T  = OFF_CA + 512;
static constexpr int FA_SMEM = OFF_T + 1024;
static constexpr int NCHUNK = 7;

__global__ void __launch_bounds__(256, 1)
fused_attn(const bf16* __restrict__ qkvh, const bf16* __restrict__ qkvl,
           const bf16* __restrict__ vth, const bf16* __restrict__ vtl,
           f16* __restrict__ yh, f16* __restrict__ yl) {
    extern __shared__ __align__(16) char smem[];
    uint32_t s0 = s2u(smem);
    const int tid = threadIdx.x, lane = tid & 31, warp = tid >> 5;
    const int qt = blockIdx.x;
    const int z = blockIdx.y;
    const int b = z / HEADS, h = z % HEADS;
    const float SC = 0.125f;

    const int wm0 = warp * 16;
    const uint32_t a_lane  = (uint32_t)(wm0 + (lane & 15)) * ARS + (uint32_t)(lane >> 4) * 16u;
    const uint32_t b_lane  = (uint32_t)((lane & 7) + ((lane >> 4) << 3)) * ARS +
                             (uint32_t)((lane >> 3) & 1) * 16u;
    const uint32_t vb_lane = (uint32_t)((lane & 7) + ((lane >> 4) << 3)) * VRS +
                             (uint32_t)((lane >> 3) & 1) * 16u;
    const uint32_t ap_lane = (uint32_t)(wm0 + (lane & 15)) * PRS2 + (uint32_t)(lane >> 4) * 16u;

    float* mrow = reinterpret_cast<float*>(smem + OFF_M);
    float* lrow = reinterpret_cast<float*>(smem + OFF_L);
    float* crow = reinterpret_cast<float*>(smem + OFF_CA);
    float* tred = reinterpret_cast<float*>(smem + OFF_T);

    auto load_qk = [&](int rowbase, int colbase, uint32_t dsth, uint32_t dstl) {
#pragma unroll
        for (int i = 0; i < 4; i++) {
            int idx = tid + i * 256;
            int r = idx >> 3, g = idx & 7;
            bool v = (rowbase + r) < NTOK;
            size_t off = ((size_t)(b * NTOK + rowbase + r)) * (3 * DM) + colbase + g * 8;
            const bf16* sh2 = v ? (qkvh + off) : qkvh;
            const bf16* sl2 = v ? (qkvl + off) : qkvl;
            uint32_t d = (uint32_t)r * ARS + (uint32_t)g * 16u;
            cp16(dsth + d, sh2, v);
            cp16(dstl + d, sl2, v);
        }
    };
    auto load_vt = [&](int c, uint32_t dsth, uint32_t dstl) {
        const bf16* bh2 = vth + (size_t)z * 64 * SPAD + (size_t)c * 128;
        const bf16* bl2 = vtl + (size_t)z * 64 * SPAD + (size_t)c * 128;
#pragma unroll
        for (int i = 0; i < 4; i++) {
            int idx = tid + i * 256;
            int r = idx >> 4, g = idx & 15;
            size_t off = (size_t)r * SPAD + g * 8;
            uint32_t d = (uint32_t)r * VRS + (uint32_t)g * 16u;
            cp16(dsth + d, bh2 + off, true);
            cp16(dstl + d, bl2 + off, true);
        }
    };
    auto load_chunk = [&](int c, int bsel) {
        uint32_t base = s0 + bsel * KVBUF;
        load_qk(c * 128, DM + h * 64, base, base + KTILE);
        load_vt(c, base + 2 * KTILE, base + 2 * KTILE + VTILE);
        cpcommit();
    };

    load_qk(qt * 128, h * 64, s0 + OFF_SPH, s0 + OFF_SPH + KTILE);
    cpcommit();
    cpwait0();
    __syncthreads();
    uint32_t aQh[4][4], aQl[4][4];
#pragma unroll
    for (int ks = 0; ks < 4; ks++) {
        ldsm4(aQh[ks], s0 + OFF_SPH + a_lane + ks * 32);
        ldsm4(aQl[ks], s0 + OFF_SPH + KTILE + a_lane + ks * 32);
    }
    if (tid < 128) { mrow[tid] = -1e30f; lrow[tid] = 0.f; }
    __syncthreads();

    float o[8][4];
#pragma unroll
    for (int i = 0; i < 8; i++)
#pragma unroll
        for (int j = 0; j < 4; j++) o[i][j] = 0.f;

    load_chunk(0, 0);
    for (int c = 0; c < NCHUNK; c++) {
        if (c + 1 < NCHUNK) { load_chunk(c + 1, (c + 1) & 1); cpwait1(); }
        else                { cpwait0(); }
        __syncthreads();
        uint32_t kvb = s0 + (c & 1) * KVBUF;
        uint32_t Kh = kvb, Kl = kvb + KTILE;
        uint32_t Vh = kvb + 2 * KTILE, Vl = kvb + 2 * KTILE + VTILE;

        float s[16][4];
#pragma unroll
        for (int j = 0; j < 16; j++)
#pragma unroll
            for (int q = 0; q < 4; q++) s[j][q] = 0.f;
#pragma unroll
        for (int ks = 0; ks < 4; ks++) {
#pragma unroll
            for (int jp = 0; jp < 8; jp++) {
                uint32_t kh[4], kl[4];
                uint32_t koff = b_lane + (uint32_t)jp * (16 * ARS) + (uint32_t)ks * 32u;
                ldsm4(kh, Kh + koff);
                ldsm4(kl, Kl + koff);
#pragma unroll
                for (int hf = 0; hf < 2; hf++) {
                    int j = jp * 2 + hf;
                    mma16816(s[j], aQh[ks], &kh[hf * 2]);
                    mma16816(s[j], aQh[ks], &kl[hf * 2]);
                    mma16816(s[j], aQl[ks], &kh[hf * 2]);
                }
            }
        }

        {
            char* smp = smem;
            int r0 = wm0 + (lane >> 2);
            int c0 = 2 * (lane & 3);
#pragma unroll
            for (int j = 0; j < 16; j++) {
                int cc = j * 8 + c0;
                uint32_t loA, hiA = packsplit_hi(s[j][0], s[j][1], loA);
                uint32_t loB, hiB = packsplit_hi(s[j][2], s[j][3], loB);
                *(uint32_t*)(smp + OFF_SPH + (uint32_t)r0 * PRS2 + cc * 2) = hiA;
                *(uint32_t*)(smp + OFF_SPL + (uint32_t)r0 * PRS2 + cc * 2) = loA;
                *(uint32_t*)(smp + OFF_SPH + (uint32_t)(r0 + 8) * PRS2 + cc * 2) = hiB;
                *(uint32_t*)(smp + OFF_SPL + (uint32_t)(r0 + 8) * PRS2 + cc * 2) = loB;
            }
        }
        __syncthreads();

        const int r = tid >> 1, half = tid & 1;
        char* smp = smem;
        const uint32_t rowoff = (uint32_t)r * PRS2 + (uint32_t)half * 128u;
        const int colbase = c * 128 + half * 64;
        const int nvalid0 = NTOK - colbase;
        const int nvalid = nvalid0 < 0 ? 0 : (nvalid0 > 64 ? 64 : nvalid0);

        float chmax = -1e30f;
#pragma unroll 8
        for (int k = 0; k < 64; k += 2) {
            uint32_t hi = *(uint32_t*)(smp + OFF_SPH + rowoff + k * 2);
            uint32_t lo = *(uint32_t*)(smp + OFF_SPL + rowoff + k * 2);
            __nv_bfloat162 h2 = *reinterpret_cast<__nv_bfloat162*>(&hi);
            __nv_bfloat162 l2 = *reinterpret_cast<__nv_bfloat162*>(&lo);
            float v0 = __bfloat162float(h2.x) + __bfloat162float(l2.x);
            float v1 = __bfloat162float(h2.y) + __bfloat162float(l2.y);
            if (k < nvalid)     chmax = fmaxf(chmax, v0);
            if (k + 1 < nvalid) chmax = fmaxf(chmax, v1);
        }
        tred[tid] = chmax;
        __syncthreads();
        float m_old = mrow[r];
        float rmax = fmaxf(tred[2 * r], tred[2 * r + 1]);
        float m_new = fmaxf(m_old, rmax);
        float ca = __expf(SC * (m_old - m_new));
        __syncthreads();

        float esum = 0.f;
#pragma unroll 8
        for (int k = 0; k < 64; k += 2) {
            uint32_t hi = *(uint32_t*)(smp + OFF_SPH + rowoff + k * 2);
            uint32_t lo = *(uint32_t*)(smp + OFF_SPL + rowoff + k * 2);
            __nv_bfloat162 h2 = *reinterpret_cast<__nv_bfloat162*>(&hi);
            __nv_bfloat162 l2 = *reinterpret_cast<__nv_bfloat162*>(&lo);
            float v0 = __bfloat162float(h2.x) + __bfloat162float(l2.x);
            float v1 = __bfloat162float(h2.y) + __bfloat162float(l2.y);
            float e0 = (k < nvalid)     ? __expf(SC * (v0 - m_new)) : 0.f;
            float e1 = (k + 1 < nvalid) ? __expf(SC * (v1 - m_new)) : 0.f;
            esum += e0 + e1;
            uint32_t plo, phi = packsplit_hi(e0, e1, plo);
            *(uint32_t*)(smp + OFF_SPH + rowoff + k * 2) = phi;
            *(uint32_t*)(smp + OFF_SPL + rowoff + k * 2) = plo;
        }
        tred[tid] = esum;
        __syncthreads();
        if (half == 0) {
            lrow[r] = lrow[r] * ca + tred[2 * r] + tred[2 * r + 1];
            mrow[r] = m_new;
            crow[r] = ca;
        }
        __syncthreads();

        float caA = crow[wm0 + (lane >> 2)];
        float caB = crow[wm0 + 8 + (lane >> 2)];
#pragma unroll
        for (int nt = 0; nt < 8; nt++) {
            o[nt][0] *= caA; o[nt][1] *= caA;
            o[nt][2] *= caB; o[nt][3] *= caB;
        }

#pragma unroll
        for (int kt = 0; kt < 8; kt++) {
            uint32_t pa[4], pb[4];
            ldsm4(pa, s0 + OFF_SPH + ap_lane + (uint32_t)kt * 32u);
            ldsm4(pb, s0 + OFF_SPL + ap_lane + (uint32_t)kt * 32u);
#pragma unroll
            for (int dp = 0; dp < 4; dp++) {
                uint32_t vh[4], vl[4];
                uint32_t voff = vb_lane + (uint32_t)dp * (16 * VRS) + (uint32_t)kt * 32u;
                ldsm4(vh, Vh + voff);
                ldsm4(vl, Vl + voff);
#pragma unroll
                for (int hf = 0; hf < 2; hf++) {
                    int nt = dp * 2 + hf;
                    mma16816(o[nt], pa, &vh[hf * 2]);
                    mma16816(o[nt], pa, &vl[hf * 2]);
                    mma16816(o[nt], pb, &vh[hf * 2]);
                }
            }
        }
        __syncthreads();
    }

    // normalize + store fp16 split pair (consumed by proj GEMM)
    float la = lrow[wm0 + (lane >> 2)];
    float lb = lrow[wm0 + 8 + (lane >> 2)];
    float ia = 1.0f / la, ib = 1.0f / lb;
    int ra = qt * 128 + wm0 + (lane >> 2);
    int rb = ra + 8;
#pragma unroll
    for (int nt = 0; nt < 8; nt++) {
        int col = h * 64 + nt * 8 + 2 * (lane & 3);
        if (ra < NTOK) {
            size_t p = (size_t)(b * NTOK + ra) * DM + col;
            uint32_t lo, hi = packsplit_h(o[nt][0] * ia, o[nt][1] * ia, lo);
            *reinterpret_cast<uint32_t*>(yh + p) = hi;
            *reinterpret_cast<uint32_t*>(yl + p) = lo;
        }
        if (rb < NTOK) {
            size_t p = (size_t)(b * NTOK + rb) * DM + col;
            uint32_t lo, hi = packsplit_h(o[nt][2] * ib, o[nt][3] * ib, lo);
            *reinterpret_cast<uint32_t*>(yh + p) = hi;
            *reinterpret_cast<uint32_t*>(yl + p) = lo;
        }
    }
}

// ---------------- fp16 split GEMM, BM=64 x BN=128, occupancy 2 ----------------
// C = (Ah+Al/2048)(Bh+Bl/2048) ~= AhBh [f32 acc] + (AhBl' + Al'Bh) [f16 acc] / 2048
// 8 warps, warp tile 32x32 (MT=2), BK=64, double-buffered cp.async, 2 CTAs/SM.
// EPI: 0 fp32 (+bias?+res?), 1 bf16 split (+bias) [qkv], 2 fp16 split gelu (+bias)
static constexpr int GRS   = 144;              // smem row stride bytes
static constexpr int GASZ  = 64 * GRS;         // A plane 9216
static constexpr int GBSZ  = 128 * GRS;        // B plane 18432
static constexpr int GBUF  = 2 * GASZ + 2 * GBSZ;  // 55296

template <int EPI>
__global__ void __launch_bounds__(256, 2)
h16_gemm(const f16* __restrict__ Ahi, const f16* __restrict__ Alo, int lda,
         const f16* __restrict__ Bhi, const f16* __restrict__ Blo, int ldb,
         float* __restrict__ Cf, bf16* __restrict__ Cbh, bf16* __restrict__ Cbl,
         f16* __restrict__ Chh, f16* __restrict__ Chl, int ldc,
         const float* __restrict__ bias, const float* __restrict__ res,
         int M, int N, int NC) {
    extern __shared__ __align__(16) char smem[];
    uint32_t s0 = s2u(smem);

    const int tid = threadIdx.x, lane = tid & 31, warp = tid >> 5;
    const int wm0 = (warp >> 2) * 32;     // 2 warp-rows
    const int wn0 = (warp & 3) * 32;      // 4 warp-cols
    const int row0 = blockIdx.y * 64, col0 = blockIdx.x * 128;

    float lead[2][4][4];
    uint32_t cross[2][4][2];
#pragma unroll
    for (int i = 0; i < 2; i++)
#pragma unroll
        for (int j = 0; j < 4; j++) {
#pragma unroll
            for (int k = 0; k < 4; k++) lead[i][j][k] = 0.f;
            cross[i][j][0] = 0u; cross[i][j][1] = 0u;
        }

    const uint32_t a_lane = (uint32_t)(wm0 + (lane & 15)) * GRS + (uint32_t)(lane >> 4) * 16u;
    const uint32_t b_lane = (uint32_t)(wn0 + (lane & 7) + ((lane >> 4) << 3)) * GRS +
                            (uint32_t)((lane >> 3) & 1) * 16u;

    auto load_chunk = [&](int ck, int bsel) {
        uint32_t base = s0 + bsel * GBUF;
        // A: 64 rows x 8 granules (hi+lo)
#pragma unroll
        for (int i = 0; i < 2; i++) {
            int idx = tid + i * 256;
            int r = idx >> 3, c = idx & 7;
            int gm = row0 + r;
            bool v = gm < M;
            const f16* ph = v ? (Ahi + (size_t)gm * lda + (size_t)ck * 64 + c * 8) : Ahi;
            const f16* pl = v ? (Alo + (size_t)gm * lda + (size_t)ck * 64 + c * 8) : Alo;
            uint32_t d = base + (uint32_t)r * GRS + (uint32_t)c * 16u;
            cp16(d, ph, v);
            cp16(d + GASZ, pl, v);
        }
        // B: 128 rows x 8 granules (hi+lo)
#pragma unroll
        for (int i = 0; i < 4; i++) {
            int idx = tid + i * 256;
            int r = idx >> 3, c = idx & 7;
            int gn = col0 + r;
            bool v = gn < N;
            const f16* ph = v ? (Bhi + (size_t)gn * ldb + (size_t)ck * 64 + c * 8) : Bhi;
            const f16* pl = v ? (Blo + (size_t)gn * ldb + (size_t)ck * 64 + c * 8) : Blo;
            uint32_t d = base + 2 * GASZ + (uint32_t)r * GRS + (uint32_t)c * 16u;
            cp16(d, ph, v);
            cp16(d + GBSZ, pl, v);
        }
        cpcommit();
    };

    auto compute = [&](int bsel) {
        uint32_t base = s0 + bsel * GBUF;
        uint32_t ah = base, al = base + GASZ;
        uint32_t bh = base + 2 * GASZ, bl = base + 2 * GASZ + GBSZ;
#pragma unroll
        for (int ks = 0; ks < 4; ks++) {
            uint32_t afh[2][4], afl[2][4];
#pragma unroll
            for (int mt = 0; mt < 2; mt++) {
                uint32_t off = a_lane + (uint32_t)mt * (16 * GRS) + (uint32_t)ks * 32u;
                ldsm4(afh[mt], ah + off);
                ldsm4(afl[mt], al + off);
            }
            uint32_t bfh[2][4], bfl[2][4];
#pragma unroll
            for (int np = 0; np < 2; np++) {
                uint32_t off = b_lane + (uint32_t)np * (16 * GRS) + (uint32_t)ks * 32u;
                ldsm4(bfh[np], bh + off);
                ldsm4(bfl[np], bl + off);
            }
#pragma unroll
            for (int mt = 0; mt < 2; mt++)
#pragma unroll
                for (int nt = 0; nt < 4; nt++) {
                    const uint32_t* Bh2 = &bfh[nt >> 1][(nt & 1) * 2];
                    const uint32_t* Bl2 = &bfl[nt >> 1][(nt & 1) * 2];
                    mma_h_f32(lead[mt][nt], afh[mt], Bh2);
                    mma_h_f16(cross[mt][nt], afh[mt], Bl2);
                    mma_h_f16(cross[mt][nt], afl[mt], Bh2);
                }
        }
    };

    load_chunk(0, 0);
    for (int ck = 0; ck < NC; ck++) {
        if (ck + 1 < NC) { load_chunk(ck + 1, (ck + 1) & 1); cpwait1(); }
        else             { cpwait0(); }
        __syncthreads();
        compute(ck & 1);
        __syncthreads();
    }

    const float INV = 1.0f / 2048.0f;
#pragma unroll
    for (int mt = 0; mt < 2; mt++) {
#pragma unroll
        for (int nt = 0; nt < 4; nt++) {
            int r0 = row0 + wm0 + mt * 16 + (lane >> 2);
            int c0 = col0 + wn0 + nt * 8 + (lane & 3) * 2;
            float* a4 = lead[mt][nt];
#pragma unroll
            for (int h = 0; h < 2; h++) {
                int gm = r0 + h * 8;
                if (gm >= M) continue;
                __half2 cx = *reinterpret_cast<__half2*>(&cross[mt][nt][h]);
                float v0 = a4[h * 2]     + __half2float(cx.x) * INV;
                float v1 = a4[h * 2 + 1] + __half2float(cx.y) * INV;
                if (bias) { v0 += bias[c0]; v1 += bias[c0 + 1]; }
                if (EPI == 0) {
                    if (res) {
                        v0 += res[(size_t)gm * ldc + c0];
                        v1 += res[(size_t)gm * ldc + c0 + 1];
                    }
                    Cf[(size_t)gm * ldc + c0]     = v0;
                    Cf[(size_t)gm * ldc + c0 + 1] = v1;
                } else if (EPI == 1) {
                    uint32_t lo, hi = packsplit_hi(v0, v1, lo);
                    *reinterpret_cast<uint32_t*>(Cbh + (size_t)gm * ldc + c0) = hi;
                    *reinterpret_cast<uint32_t*>(Cbl + (size_t)gm * ldc + c0) = lo;
                } else {
                    v0 = geluf(v0); v1 = geluf(v1);
                    uint32_t lo, hi = packsplit_h(v0, v1, lo);
                    *reinterpret_cast<uint32_t*>(Chh + (size_t)gm * ldc + c0) = hi;
                    *reinterpret_cast<uint32_t*>(Chl + (size_t)gm * ldc + c0) = lo;
                }
            }
        }
    }
}

template <int EPI>
static void hgemm(const f16* Ah, const f16* Al, int lda,
                  const f16* Bh, const f16* Bl, int ldb,
                  float* Cf, bf16* Cbh, bf16* Cbl, f16* Chh, f16* Chl, int ldc,
                  const float* bias, const float* res, int M, int N, int K) {
    int smem = 2 * GBUF;   // 110592
    cudaFuncSetAttribute(h16_gemm<EPI>, cudaFuncAttributeMaxDynamicSharedMemorySize, smem);
    dim3 grid(N / 128, (M + 63) / 64, 1);
    h16_gemm<EPI><<<grid, 256, smem>>>(Ah, Al, lda, Bh, Bl, ldb, Cf, Cbh, Cbl, Chh, Chl,
                                       ldc, bias, res, M, N, K / 64);
}

extern "C" void kernel_launch(void* const* d_in, const int* in_sizes, int n_in,
                              void* d_out, int out_size) {
    const float* x       = (const float*)d_in[0];
    const float* conv_w  = (const float*)d_in[1];
    const float* conv_b  = (const float*)d_in[2];
    const float* cls_tok = (const float*)d_in[3];
    const float* pos_emb = (const float*)d_in[4];
    const float* ln1_g   = (const float*)d_in[5];
    const float* ln1_b   = (const float*)d_in[6];
    const float* qkv_w   = (const float*)d_in[7];
    const float* qkv_b   = (const float*)d_in[8];
    const float* proj_w  = (const float*)d_in[9];
    const float* proj_b  = (const float*)d_in[10];
    const float* ln2_g   = (const float*)d_in[11];
    const float* ln2_b   = (const float*)d_in[12];
    const float* mlp_w1  = (const float*)d_in[13];
    const float* mlp_b1  = (const float*)d_in[14];
    const float* mlp_w2  = (const float*)d_in[15];
    const float* mlp_b2  = (const float*)d_in[16];
    const float* lnf_g   = (const float*)d_in[17];
    const float* lnf_b   = (const float*)d_in[18];
    float* out = (float*)d_out;

    f16 *wh, *wl, *cwh, *cwl, *pxh, *pxl, *xh, *xl, *ahp, *alp, *mh, *ml;
    float *ph, *ptmp;
    bf16 *qhi, *qlo, *vthi, *vtlo;
    cudaGetSymbolAddress((void**)&wh, g_wh);
    cudaGetSymbolAddress((void**)&wl, g_wl);
    cudaGetSymbolAddress((void**)&cwh, g_cwh);
    cudaGetSymbolAddress((void**)&cwl, g_cwl);
    cudaGetSymbolAddress((void**)&pxh, g_pxh);
    cudaGetSymbolAddress((void**)&pxl, g_pxl);
    cudaGetSymbolAddress((void**)&xh, g_xh);
    cudaGetSymbolAddress((void**)&xl, g_xl);
    cudaGetSymbolAddress((void**)&ahp, g_ah);
    cudaGetSymbolAddress((void**)&alp, g_al);
    cudaGetSymbolAddress((void**)&mh, g_mh);
    cudaGetSymbolAddress((void**)&ml, g_ml);
    cudaGetSymbolAddress((void**)&ph, g_h);
    cudaGetSymbolAddress((void**)&ptmp, g_ptmp);
    cudaGetSymbolAddress((void**)&qhi, g_qhi);
    cudaGetSymbolAddress((void**)&qlo, g_qlo);
    cudaGetSymbolAddress((void**)&vthi, g_vthi);
    cudaGetSymbolAddress((void**)&vtlo, g_vtlo);

    dim3 tb(32, 8);

    // ---- weight prep (fp16 split) ----
    split_h<<<(DM * DM + 255) / 256, 256>>>(conv_w, cwh, cwl, DM * DM);
    for (int l = 0; l < LAYERS; l++) {
        long long wo = (long long)l * LW;
        wt_trans_h<<<dim3(2304 / 32, 768 / 32), tb>>>(qkv_w + (size_t)l * DM * 3 * DM,
                                                      wh + wo, wl + wo, DM, 3 * DM);
        wt_trans_h<<<dim3(768 / 32, 768 / 32), tb>>>(proj_w + (size_t)l * DM * DM,
                                                     wh + wo + 1769472, wl + wo + 1769472, DM, DM);
        wt_trans_h<<<dim3(3072 / 32, 768 / 32), tb>>>(mlp_w1 + (size_t)l * DM * 4 * DM,
                                                      wh + wo + 2359296, wl + wo + 2359296, DM, 4 * DM);
        wt_trans_h<<<dim3(768 / 32, 3072 / 32), tb>>>(mlp_w2 + (size_t)l * 4 * DM * DM,
                                                      wh + wo + 4718592, wl + wo + 4718592, 4 * DM, DM);
    }

    // ---- patch embed ----
    im2col_h<<<(MPATCH * DM + 255) / 256, 256>>>(x, pxh, pxl);
    hgemm<0>(pxh, pxl, DM, cwh, cwl, DM, ptmp, nullptr, nullptr, nullptr, nullptr, DM,
             conv_b, nullptr, MPATCH, DM, DM);
    assemble_kernel<<<(MTOK * DM + 255) / 256, 256>>>(ptmp, cls_tok, pos_emb, ph);

    cudaFuncSetAttribute(fused_attn, cudaFuncAttributeMaxDynamicSharedMemorySize, FA_SMEM);

    for (int l = 0; l < LAYERS; l++) {
        long long wo = (long long)l * LW;
        const f16* qwT_h = wh + wo;            const f16* qwT_l = wl + wo;
        const f16* pwT_h = wh + wo + 1769472;  const f16* pwT_l = wl + wo + 1769472;
        const f16* w1T_h = wh + wo + 2359296;  const f16* w1T_l = wl + wo + 2359296;
        const f16* w2T_h = wh + wo + 4718592;  const f16* w2T_l = wl + wo + 4718592;
        const float* l1g = ln1_g + (size_t)l * DM;
        const float* l1b = ln1_b + (size_t)l * DM;
        const float* qb  = qkv_b + (size_t)l * 3 * DM;
        const float* pb  = proj_b + (size_t)l * DM;
        const float* l2g = ln2_g + (size_t)l * DM;
        const float* l2b = ln2_b + (size_t)l * DM;
        const float* b1  = mlp_b1 + (size_t)l * 4 * DM;
        const float* b2  = mlp_b2 + (size_t)l * DM;

        // LN1 -> fp16 pair
        ln_split_h<<<MTOK, 256>>>(ph, l1g, l1b, xh, xl);
        // QKV -> bf16 pair (attention input)
        hgemm<1>(xh, xl, DM, qwT_h, qwT_l, DM, nullptr, qhi, qlo, nullptr, nullptr, 3 * DM,
                 qb, nullptr, MTOK, 3 * DM, DM);
        // V transpose (validated)
        {
            size_t n = (size_t)BATCH * HEADS * 64 * SPAD;
            vt_split<<<(unsigned)((n + 255) / 256), 256>>>(qhi, qlo, vthi, vtlo);
        }
        // fused attention -> fp16 pair
        fused_attn<<<dim3(NCHUNK, BATCH * HEADS), 256, FA_SMEM>>>(qhi, qlo, vthi, vtlo,
                                                                  ahp, alp);
        // proj + bias + residual -> h
        hgemm<0>(ahp, alp, DM, pwT_h, pwT_l, DM, ph, nullptr, nullptr, nullptr, nullptr, DM,
                 pb, ph, MTOK, DM, DM);
        // LN2 -> fp16 pair
        ln_split_h<<<MTOK, 256>>>(ph, l2g, l2b, xh, xl);
        // MLP1 + gelu -> fp16 pair
        hgemm<2>(xh, xl, DM, w1T_h, w1T_l, DM, nullptr, nullptr, nullptr, mh, ml, 4 * DM,
                 b1, nullptr, MTOK, 4 * DM, DM);
        // MLP2 + bias + residual -> h
        hgemm<0>(mh, ml, 4 * DM, w2T_h, w2T_l, 4 * DM, ph, nullptr, nullptr, nullptr, nullptr, DM,
                 b2, ph, MTOK, DM, 4 * DM);
    }

    // final LN on CLS rows -> out [8,768]
    ln_kernel<<<BATCH, 256>>>(ph, lnf_g, lnf_b, out, (long long)NTOK * DM, DM);
}

// round 12
// speedup vs baseline: 2.9654x; 1.1865x over previous
#include <cuda_runtime.h>
#include <cuda_bf16.h>
#include <cuda_fp16.h>
#include <math.h>
#include <stdint.h>

using bf16 = __nv_bfloat16;
using f16 = __half;

// ---------------- problem constants ----------------
static constexpr int BATCH  = 8;
static constexpr int DM     = 768;
static constexpr int HEADS  = 12;
static constexpr int LAYERS = 12;
static constexpr int NTOK   = 785;
static constexpr int NPATCH = 784;
static constexpr int MTOK   = BATCH * NTOK;    // 6280
static constexpr int MPATCH = BATCH * NPATCH;  // 6272
static constexpr int IMG    = 448;
static constexpr int PSZ    = 16;
static constexpr int GRID28 = 28;
static constexpr int SPAD   = 896;
static constexpr long long LW = 7077888LL;

// ---------------- device scratch ----------------
__device__ f16  g_wh[(size_t)LAYERS * LW];     // weights hi (split kept)
__device__ f16  g_wl[(size_t)LAYERS * LW];     // weights lo
__device__ f16  g_cwh[DM * DM];
__device__ f16  g_cwl[DM * DM];
__device__ f16  g_pxh[(size_t)MPATCH * DM];    // patches (single fp16)
__device__ f16  g_xh[(size_t)MTOK * DM];       // LN out (single fp16)
__device__ f16  g_ah[(size_t)MTOK * DM];       // attn out (single fp16)
__device__ f16  g_mh[(size_t)MTOK * 4 * DM];   // mlp mid (single fp16)
__device__ float g_h[(size_t)MTOK * DM];
__device__ float g_ptmp[(size_t)MPATCH * DM];
__device__ bf16  g_qhi[(size_t)MTOK * 3 * DM];
__device__ bf16  g_qlo[(size_t)MTOK * 3 * DM];
__device__ bf16  g_vthi[(size_t)BATCH * HEADS * 64 * SPAD];
__device__ bf16  g_vtlo[(size_t)BATCH * HEADS * 64 * SPAD];

// ---------------- small helpers ----------------
__device__ __forceinline__ void split2(float v, bf16& h, bf16& l) {
    h = __float2bfloat16(v);
    l = __float2bfloat16(v - __bfloat162float(h));
}
__device__ __forceinline__ float geluf(float v) {
    return 0.5f * v * (1.0f + erff(v * 0.70710678118654752f));
}
__device__ __forceinline__ float warpSum(float v) {
#pragma unroll
    for (int o = 16; o > 0; o >>= 1) v += __shfl_xor_sync(0xffffffffu, v, o);
    return v;
}
__device__ __forceinline__ float blockSum256(float v, float* sh) {
    int lane = threadIdx.x & 31, w = threadIdx.x >> 5;
    v = warpSum(v);
    if (lane == 0) sh[w] = v;
    __syncthreads();
    float r = (threadIdx.x < 8) ? sh[threadIdx.x] : 0.f;
    if (w == 0) { r = warpSum(r); if (lane == 0) sh[0] = r; }
    __syncthreads();
    r = sh[0];
    __syncthreads();
    return r;
}

// ---------------- PTX wrappers ----------------
__device__ __forceinline__ uint32_t s2u(const void* p) {
    uint32_t a;
    asm("{ .reg .u64 t; cvta.to.shared.u64 t, %1; cvt.u32.u64 %0, t; }" : "=r"(a) : "l"(p));
    return a;
}
__device__ __forceinline__ void cp16(uint32_t d, const void* s, bool pred) {
    int sz = pred ? 16 : 0;
    asm volatile("cp.async.cg.shared.global [%0], [%1], 16, %2;" :: "r"(d), "l"(s), "r"(sz));
}
__device__ __forceinline__ void cpcommit() { asm volatile("cp.async.commit_group;" ::: "memory"); }
__device__ __forceinline__ void cpwait0()  { asm volatile("cp.async.wait_group 0;" ::: "memory"); }
__device__ __forceinline__ void cpwait1()  { asm volatile("cp.async.wait_group 1;" ::: "memory"); }
__device__ __forceinline__ void ldsm4(uint32_t* r, uint32_t addr) {
    asm volatile("ldmatrix.sync.aligned.m8n8.x4.shared.b16 {%0,%1,%2,%3}, [%4];"
                 : "=r"(r[0]), "=r"(r[1]), "=r"(r[2]), "=r"(r[3]) : "r"(addr));
}
// bf16 operands, f32 acc (validated; attention only)
__device__ __forceinline__ void mma16816(float* c, const uint32_t* a, const uint32_t* b) {
    asm volatile(
        "mma.sync.aligned.m16n8k16.row.col.f32.bf16.bf16.f32 "
        "{%0,%1,%2,%3}, {%4,%5,%6,%7}, {%8,%9}, {%0,%1,%2,%3};"
        : "+f"(c[0]), "+f"(c[1]), "+f"(c[2]), "+f"(c[3])
        : "r"(a[0]), "r"(a[1]), "r"(a[2]), "r"(a[3]), "r"(b[0]), "r"(b[1]));
}
// f16 operands, f32 acc (lead term)
__device__ __forceinline__ void mma_h_f32(float* c, const uint32_t* a, const uint32_t* b) {
    asm volatile(
        "mma.sync.aligned.m16n8k16.row.col.f32.f16.f16.f32 "
        "{%0,%1,%2,%3}, {%4,%5,%6,%7}, {%8,%9}, {%0,%1,%2,%3};"
        : "+f"(c[0]), "+f"(c[1]), "+f"(c[2]), "+f"(c[3])
        : "r"(a[0]), "r"(a[1]), "r"(a[2]), "r"(a[3]), "r"(b[0]), "r"(b[1]));
}
// f16 operands, f16 acc (cross term; 2 C regs)
__device__ __forceinline__ void mma_h_f16(uint32_t* c, const uint32_t* a, const uint32_t* b) {
    asm volatile(
        "mma.sync.aligned.m16n8k16.row.col.f16.f16.f16.f16 "
        "{%0,%1}, {%2,%3,%4,%5}, {%6,%7}, {%0,%1};"
        : "+r"(c[0]), "+r"(c[1])
        : "r"(a[0]), "r"(a[1]), "r"(a[2]), "r"(a[3]), "r"(b[0]), "r"(b[1]));
}
// bf16 split pack (attention internals; validated)
__device__ __forceinline__ uint32_t packsplit_hi(float a, float b, uint32_t& lo) {
    bf16 ah, al, bh, bl;
    split2(a, ah, al);
    split2(b, bh, bl);
    __nv_bfloat162 h2; h2.x = ah; h2.y = bh;
    __nv_bfloat162 l2; l2.x = al; l2.y = bl;
    lo = *reinterpret_cast<uint32_t*>(&l2);
    return *reinterpret_cast<uint32_t*>(&h2);
}
__device__ __forceinline__ uint32_t packh2(float a, float b) {
    __half2 h2 = __halves2half2(__float2half(a), __float2half(b));
    return *reinterpret_cast<uint32_t*>(&h2);
}
__device__ __forceinline__ void splith(float v, f16& h, f16& l) {
    h = __float2half(v);
    l = __float2half((v - __half2float(h)) * 2048.f);
}

// ---------------- elementwise / prep kernels ----------------
__global__ void im2col_h(const float* __restrict__ x, f16* __restrict__ Ph) {
    int idx = blockIdx.x * blockDim.x + threadIdx.x;
    if (idx >= MPATCH * DM) return;
    int k = idx % DM, m = idx / DM;
    int b = m / NPATCH, t = m % NPATCH;
    int py = t / GRID28, px = t % GRID28;
    int c = k >> 8, rem = k & 255, i = rem >> 4, j = rem & 15;
    size_t src = (((size_t)(b * 3 + c) * IMG) + (size_t)(py * PSZ + i)) * IMG + (px * PSZ + j);
    Ph[idx] = __float2half(x[src]);
}

__global__ void split_h(const float* __restrict__ W, f16* __restrict__ Oh,
                        f16* __restrict__ Ol, int n) {
    int idx = blockIdx.x * blockDim.x + threadIdx.x;
    if (idx >= n) return;
    f16 h, l;
    splith(W[idx], h, l);
    Oh[idx] = h; Ol[idx] = l;
}

// W[K,N] row-major -> out[n*K + k] (transpose + fp16 split)
__global__ void wt_trans_h(const float* __restrict__ W, f16* __restrict__ Oh,
                           f16* __restrict__ Ol, int K, int N) {
    __shared__ float tile[32][33];
    int kb = blockIdx.y * 32, nb = blockIdx.x * 32;
    int tx = threadIdx.x, ty = threadIdx.y;  // 32 x 8
#pragma unroll
    for (int i = 0; i < 32; i += 8) {
        int k = kb + ty + i, n = nb + tx;
        tile[ty + i][tx] = (k < K && n < N) ? W[(size_t)k * N + n] : 0.f;
    }
    __syncthreads();
#pragma unroll
    for (int i = 0; i < 32; i += 8) {
        int n = nb + ty + i, k = kb + tx;
        if (n < N && k < K) {
            f16 h, l;
            splith(tile[tx][ty + i], h, l);
            Oh[(size_t)n * K + k] = h;
            Ol[(size_t)n * K + k] = l;
        }
    }
}

__global__ void assemble_kernel(const float* __restrict__ tok, const float* __restrict__ cls,
                                const float* __restrict__ pos, float* __restrict__ H) {
    int idx = blockIdx.x * blockDim.x + threadIdx.x;
    if (idx >= MTOK * DM) return;
    int d = idx % DM;
    int r = idx / DM;
    int n = r % NTOK, b = r / NTOK;
    float v;
    if (n == 0) v = cls[d] + pos[d];
    else        v = tok[((size_t)b * NPATCH + (n - 1)) * DM + d] + pos[(size_t)n * DM + d];
    H[idx] = v;
}

__global__ void ln_kernel(const float* __restrict__ X, const float* __restrict__ g,
                          const float* __restrict__ bb, float* __restrict__ Y,
                          long long inStride, long long outStride) {
    const float* x = X + (long long)blockIdx.x * inStride;
    float* y = Y + (long long)blockIdx.x * outStride;
    int t = threadIdx.x;
    __shared__ float sh[8];
    float v0 = x[t], v1 = x[t + 256], v2 = x[t + 512];
    float mu = blockSum256(v0 + v1 + v2, sh) * (1.0f / 768.0f);
    float d0 = v0 - mu, d1 = v1 - mu, d2 = v2 - mu;
    float var = blockSum256(d0 * d0 + d1 * d1 + d2 * d2, sh) * (1.0f / 768.0f);
    float rs = rsqrtf(var + 1e-5f);
    y[t]       = d0 * rs * g[t]       + bb[t];
    y[t + 256] = d1 * rs * g[t + 256] + bb[t + 256];
    y[t + 512] = d2 * rs * g[t + 512] + bb[t + 512];
}

// LN -> single fp16
__global__ void ln_h(const float* __restrict__ X, const float* __restrict__ g,
                     const float* __restrict__ bb, f16* __restrict__ Yh) {
    const float* x = X + (size_t)blockIdx.x * DM;
    f16* yh = Yh + (size_t)blockIdx.x * DM;
    int t = threadIdx.x;
    __shared__ float sh[8];
    float v0 = x[t], v1 = x[t + 256], v2 = x[t + 512];
    float mu = blockSum256(v0 + v1 + v2, sh) * (1.0f / 768.0f);
    float d0 = v0 - mu, d1 = v1 - mu, d2 = v2 - mu;
    float var = blockSum256(d0 * d0 + d1 * d1 + d2 * d2, sh) * (1.0f / 768.0f);
    float rs = rsqrtf(var + 1e-5f);
    yh[t]       = __float2half(d0 * rs * g[t]       + bb[t]);
    yh[t + 256] = __float2half(d1 * rs * g[t + 256] + bb[t + 256]);
    yh[t + 512] = __float2half(d2 * rs * g[t + 512] + bb[t + 512]);
}

// vT[z][d][t] = qkv[b*785+t][1536 + h*64 + d]  (validated)
__global__ void vt_split(const bf16* __restrict__ Qh, const bf16* __restrict__ Ql,
                         bf16* __restrict__ Vh, bf16* __restrict__ Vl) {
    size_t idx = (size_t)blockIdx.x * blockDim.x + threadIdx.x;
    if (idx >= (size_t)BATCH * HEADS * 64 * SPAD) return;
    int t = (int)(idx % SPAD);
    int d = (int)((idx / SPAD) % 64);
    int z = (int)(idx / ((size_t)SPAD * 64));
    int b = z / HEADS, h = z % HEADS;
    bf16 vh = __float2bfloat16(0.f), vl = vh;
    if (t < NTOK) {
        size_t src = ((size_t)(b * NTOK + t)) * (3 * DM) + 2 * DM + h * 64 + d;
        vh = Qh[src]; vl = Ql[src];
    }
    Vh[idx] = vh; Vl[idx] = vl;
}

// ---------------- fused flash attention (validated; single-fp16 output) ----------------
static constexpr int ARS    = 144;
static constexpr int KTILE  = 128 * ARS;
static constexpr int VRS    = 272;
static constexpr int VTILE  = 64 * VRS;
static constexpr int KVBUF  = 2 * KTILE + 2 * VTILE;
static constexpr int PRS2   = 272;
static constexpr int SPTILE = 128 * PRS2;
static constexpr int OFF_SPH = 2 * KVBUF;
static constexpr int OFF_SPL = OFF_SPH + SPTILE;
static constexpr int OFF_M  = OFF_SPL + SPTILE;
static constexpr int OFF_L  = OFF_M + 512;
static constexpr int OFF_CA = OFF_L + 512;
static constexpr int OFF_T  = OFF_CA + 512;
static constexpr int FA_SMEM = OFF_T + 1024;
static constexpr int NCHUNK = 7;

__global__ void __launch_bounds__(256, 1)
fused_attn(const bf16* __restrict__ qkvh, const bf16* __restrict__ qkvl,
           const bf16* __restrict__ vth, const bf16* __restrict__ vtl,
           f16* __restrict__ yh) {
    extern __shared__ __align__(16) char smem[];
    uint32_t s0 = s2u(smem);
    const int tid = threadIdx.x, lane = tid & 31, warp = tid >> 5;
    const int qt = blockIdx.x;
    const int z = blockIdx.y;
    const int b = z / HEADS, h = z % HEADS;
    const float SC = 0.125f;

    const int wm0 = warp * 16;
    const uint32_t a_lane  = (uint32_t)(wm0 + (lane & 15)) * ARS + (uint32_t)(lane >> 4) * 16u;
    const uint32_t b_lane  = (uint32_t)((lane & 7) + ((lane >> 4) << 3)) * ARS +
                             (uint32_t)((lane >> 3) & 1) * 16u;
    const uint32_t vb_lane = (uint32_t)((lane & 7) + ((lane >> 4) << 3)) * VRS +
                             (uint32_t)((lane >> 3) & 1) * 16u;
    const uint32_t ap_lane = (uint32_t)(wm0 + (lane & 15)) * PRS2 + (uint32_t)(lane >> 4) * 16u;

    float* mrow = reinterpret_cast<float*>(smem + OFF_M);
    float* lrow = reinterpret_cast<float*>(smem + OFF_L);
    float* crow = reinterpret_cast<float*>(smem + OFF_CA);
    float* tred = reinterpret_cast<float*>(smem + OFF_T);

    auto load_qk = [&](int rowbase, int colbase, uint32_t dsth, uint32_t dstl) {
#pragma unroll
        for (int i = 0; i < 4; i++) {
            int idx = tid + i * 256;
            int r = idx >> 3, g = idx & 7;
            bool v = (rowbase + r) < NTOK;
            size_t off = ((size_t)(b * NTOK + rowbase + r)) * (3 * DM) + colbase + g * 8;
            const bf16* sh2 = v ? (qkvh + off) : qkvh;
            const bf16* sl2 = v ? (qkvl + off) : qkvl;
            uint32_t d = (uint32_t)r * ARS + (uint32_t)g * 16u;
            cp16(dsth + d, sh2, v);
            cp16(dstl + d, sl2, v);
        }
    };
    auto load_vt = [&](int c, uint32_t dsth, uint32_t dstl) {
        const bf16* bh2 = vth + (size_t)z * 64 * SPAD + (size_t)c * 128;
        const bf16* bl2 = vtl + (size_t)z * 64 * SPAD + (size_t)c * 128;
#pragma unroll
        for (int i = 0; i < 4; i++) {
            int idx = tid + i * 256;
            int r = idx >> 4, g = idx & 15;
            size_t off = (size_t)r * SPAD + g * 8;
            uint32_t d = (uint32_t)r * VRS + (uint32_t)g * 16u;
            cp16(dsth + d, bh2 + off, true);
            cp16(dstl + d, bl2 + off, true);
        }
    };
    auto load_chunk = [&](int c, int bsel) {
        uint32_t base = s0 + bsel * KVBUF;
        load_qk(c * 128, DM + h * 64, base, base + KTILE);
        load_vt(c, base + 2 * KTILE, base + 2 * KTILE + VTILE);
        cpcommit();
    };

    load_qk(qt * 128, h * 64, s0 + OFF_SPH, s0 + OFF_SPH + KTILE);
    cpcommit();
    cpwait0();
    __syncthreads();
    uint32_t aQh[4][4], aQl[4][4];
#pragma unroll
    for (int ks = 0; ks < 4; ks++) {
        ldsm4(aQh[ks], s0 + OFF_SPH + a_lane + ks * 32);
        ldsm4(aQl[ks], s0 + OFF_SPH + KTILE + a_lane + ks * 32);
    }
    if (tid < 128) { mrow[tid] = -1e30f; lrow[tid] = 0.f; }
    __syncthreads();

    float o[8][4];
#pragma unroll
    for (int i = 0; i < 8; i++)
#pragma unroll
        for (int j = 0; j < 4; j++) o[i][j] = 0.f;

    load_chunk(0, 0);
    for (int c = 0; c < NCHUNK; c++) {
        if (c + 1 < NCHUNK) { load_chunk(c + 1, (c + 1) & 1); cpwait1(); }
        else                { cpwait0(); }
        __syncthreads();
        uint32_t kvb = s0 + (c & 1) * KVBUF;
        uint32_t Kh = kvb, Kl = kvb + KTILE;
        uint32_t Vh = kvb + 2 * KTILE, Vl = kvb + 2 * KTILE + VTILE;

        float s[16][4];
#pragma unroll
        for (int j = 0; j < 16; j++)
#pragma unroll
            for (int q = 0; q < 4; q++) s[j][q] = 0.f;
#pragma unroll
        for (int ks = 0; ks < 4; ks++) {
#pragma unroll
            for (int jp = 0; jp < 8; jp++) {
                uint32_t kh[4], kl[4];
                uint32_t koff = b_lane + (uint32_t)jp * (16 * ARS) + (uint32_t)ks * 32u;
                ldsm4(kh, Kh + koff);
                ldsm4(kl, Kl + koff);
#pragma unroll
                for (int hf = 0; hf < 2; hf++) {
                    int j = jp * 2 + hf;
                    mma16816(s[j], aQh[ks], &kh[hf * 2]);
                    mma16816(s[j], aQh[ks], &kl[hf * 2]);
                    mma16816(s[j], aQl[ks], &kh[hf * 2]);
                }
            }
        }

        {
            char* smp = smem;
            int r0 = wm0 + (lane >> 2);
            int c0 = 2 * (lane & 3);
#pragma unroll
            for (int j = 0; j < 16; j++) {
                int cc = j * 8 + c0;
                uint32_t loA, hiA = packsplit_hi(s[j][0], s[j][1], loA);
                uint32_t loB, hiB = packsplit_hi(s[j][2], s[j][3], loB);
                *(uint32_t*)(smp + OFF_SPH + (uint32_t)r0 * PRS2 + cc * 2) = hiA;
                *(uint32_t*)(smp + OFF_SPL + (uint32_t)r0 * PRS2 + cc * 2) = loA;
                *(uint32_t*)(smp + OFF_SPH + (uint32_t)(r0 + 8) * PRS2 + cc * 2) = hiB;
                *(uint32_t*)(smp + OFF_SPL + (uint32_t)(r0 + 8) * PRS2 + cc * 2) = loB;
            }
        }
        __syncthreads();

        const int r = tid >> 1, half = tid & 1;
        char* smp = smem;
        const uint32_t rowoff = (uint32_t)r * PRS2 + (uint32_t)half * 128u;
        const int colbase = c * 128 + half * 64;
        const int nvalid0 = NTOK - colbase;
        const int nvalid = nvalid0 < 0 ? 0 : (nvalid0 > 64 ? 64 : nvalid0);

        float chmax = -1e30f;
#pragma unroll 8
        for (int k = 0; k < 64; k += 2) {
            uint32_t hi = *(uint32_t*)(smp + OFF_SPH + rowoff + k * 2);
            uint32_t lo = *(uint32_t*)(smp + OFF_SPL + rowoff + k * 2);
            __nv_bfloat162 h2 = *reinterpret_cast<__nv_bfloat162*>(&hi);
            __nv_bfloat162 l2 = *reinterpret_cast<__nv_bfloat162*>(&lo);
            float v0 = __bfloat162float(h2.x) + __bfloat162float(l2.x);
            float v1 = __bfloat162float(h2.y) + __bfloat162float(l2.y);
            if (k < nvalid)     chmax = fmaxf(chmax, v0);
            if (k + 1 < nvalid) chmax = fmaxf(chmax, v1);
        }
        tred[tid] = chmax;
        __syncthreads();
        float m_old = mrow[r];
        float rmax = fmaxf(tred[2 * r], tred[2 * r + 1]);
        float m_new = fmaxf(m_old, rmax);
        float ca = __expf(SC * (m_old - m_new));
        __syncthreads();

        float esum = 0.f;
#pragma unroll 8
        for (int k = 0; k < 64; k += 2) {
            uint32_t hi = *(uint32_t*)(smp + OFF_SPH + rowoff + k * 2);
            uint32_t lo = *(uint32_t*)(smp + OFF_SPL + rowoff + k * 2);
            __nv_bfloat162 h2 = *reinterpret_cast<__nv_bfloat162*>(&hi);
            __nv_bfloat162 l2 = *reinterpret_cast<__nv_bfloat162*>(&lo);
            float v0 = __bfloat162float(h2.x) + __bfloat162float(l2.x);
            float v1 = __bfloat162float(h2.y) + __bfloat162float(l2.y);
            float e0 = (k < nvalid)     ? __expf(SC * (v0 - m_new)) : 0.f;
            float e1 = (k + 1 < nvalid) ? __expf(SC * (v1 - m_new)) : 0.f;
            esum += e0 + e1;
            uint32_t plo, phi = packsplit_hi(e0, e1, plo);
            *(uint32_t*)(smp + OFF_SPH + rowoff + k * 2) = phi;
            *(uint32_t*)(smp + OFF_SPL + rowoff + k * 2) = plo;
        }
        tred[tid] = esum;
        __syncthreads();
        if (half == 0) {
            lrow[r] = lrow[r] * ca + tred[2 * r] + tred[2 * r + 1];
            mrow[r] = m_new;
            crow[r] = ca;
        }
        __syncthreads();

        float caA = crow[wm0 + (lane >> 2)];
        float caB = crow[wm0 + 8 + (lane >> 2)];
#pragma unroll
        for (int nt = 0; nt < 8; nt++) {
            o[nt][0] *= caA; o[nt][1] *= caA;
            o[nt][2] *= caB; o[nt][3] *= caB;
        }

#pragma unroll
        for (int kt = 0; kt < 8; kt++) {
            uint32_t pa[4], pb[4];
            ldsm4(pa, s0 + OFF_SPH + ap_lane + (uint32_t)kt * 32u);
            ldsm4(pb, s0 + OFF_SPL + ap_lane + (uint32_t)kt * 32u);
#pragma unroll
            for (int dp = 0; dp < 4; dp++) {
                uint32_t vh[4], vl[4];
                uint32_t voff = vb_lane + (uint32_t)dp * (16 * VRS) + (uint32_t)kt * 32u;
                ldsm4(vh, Vh + voff);
                ldsm4(vl, Vl + voff);
#pragma unroll
                for (int hf = 0; hf < 2; hf++) {
                    int nt = dp * 2 + hf;
                    mma16816(o[nt], pa, &vh[hf * 2]);
                    mma16816(o[nt], pa, &vl[hf * 2]);
                    mma16816(o[nt], pb, &vh[hf * 2]);
                }
            }
        }
        __syncthreads();
    }

    // normalize + store single fp16 (consumed by proj GEMM as A)
    float la = lrow[wm0 + (lane >> 2)];
    float lb = lrow[wm0 + 8 + (lane >> 2)];
    float ia = 1.0f / la, ib = 1.0f / lb;
    int ra = qt * 128 + wm0 + (lane >> 2);
    int rb = ra + 8;
#pragma unroll
    for (int nt = 0; nt < 8; nt++) {
        int col = h * 64 + nt * 8 + 2 * (lane & 3);
        if (ra < NTOK) {
            size_t p = (size_t)(b * NTOK + ra) * DM + col;
            *reinterpret_cast<uint32_t*>(yh + p) = packh2(o[nt][0] * ia, o[nt][1] * ia);
        }
        if (rb < NTOK) {
            size_t p = (size_t)(b * NTOK + rb) * DM + col;
            *reinterpret_cast<uint32_t*>(yh + p) = packh2(o[nt][2] * ib, o[nt][3] * ib);
        }
    }
}

// ---------------- 2-term fp16 GEMM: A single fp16, B split pair ----------------
// C = A*(Bh + Bl/2048) = A*Bh [f32 acc] + A*Bl [f16 acc] / 2048
// BM=64 x BN=128, 8 warps (32x32 each), BK=64, double-buffered, occupancy 2.
// EPI: 0 fp32 (+bias?+res?), 1 bf16 split (+bias) [qkv], 2 fp16 single gelu (+bias)
static constexpr int GRS   = 144;
static constexpr int GASZ  = 64 * GRS;             // A plane 9216 (single)
static constexpr int GBSZ  = 128 * GRS;            // B plane 18432
static constexpr int GBUF  = GASZ + 2 * GBSZ;      // 46080

template <int EPI>
__global__ void __launch_bounds__(256, 2)
h16_gemm(const f16* __restrict__ A, int lda,
         const f16* __restrict__ Bhi, const f16* __restrict__ Blo, int ldb,
         float* __restrict__ Cf, bf16* __restrict__ Cbh, bf16* __restrict__ Cbl,
         f16* __restrict__ Chh, int ldc,
         const float* __restrict__ bias, const float* __restrict__ res,
         int M, int N, int NC) {
    extern __shared__ __align__(16) char smem[];
    uint32_t s0 = s2u(smem);

    const int tid = threadIdx.x, lane = tid & 31, warp = tid >> 5;
    const int wm0 = (warp >> 2) * 32;
    const int wn0 = (warp & 3) * 32;
    const int row0 = blockIdx.y * 64, col0 = blockIdx.x * 128;

    float lead[2][4][4];
    uint32_t cross[2][4][2];
#pragma unroll
    for (int i = 0; i < 2; i++)
#pragma unroll
        for (int j = 0; j < 4; j++) {
#pragma unroll
            for (int k = 0; k < 4; k++) lead[i][j][k] = 0.f;
            cross[i][j][0] = 0u; cross[i][j][1] = 0u;
        }

    const uint32_t a_lane = (uint32_t)(wm0 + (lane & 15)) * GRS + (uint32_t)(lane >> 4) * 16u;
    const uint32_t b_lane = (uint32_t)(wn0 + (lane & 7) + ((lane >> 4) << 3)) * GRS +
                            (uint32_t)((lane >> 3) & 1) * 16u;

    auto load_chunk = [&](int ck, int bsel) {
        uint32_t base = s0 + bsel * GBUF;
        // A: 64 rows x 8 granules (single plane)
#pragma unroll
        for (int i = 0; i < 2; i++) {
            int idx = tid + i * 256;
            int r = idx >> 3, c = idx & 7;
            int gm = row0 + r;
            bool v = gm < M;
            const f16* pa = v ? (A + (size_t)gm * lda + (size_t)ck * 64 + c * 8) : A;
            cp16(base + (uint32_t)r * GRS + (uint32_t)c * 16u, pa, v);
        }
        // B: 128 rows x 8 granules (hi+lo)
#pragma unroll
        for (int i = 0; i < 4; i++) {
            int idx = tid + i * 256;
            int r = idx >> 3, c = idx & 7;
            int gn = col0 + r;
            bool v = gn < N;
            const f16* ph = v ? (Bhi + (size_t)gn * ldb + (size_t)ck * 64 + c * 8) : Bhi;
            const f16* pl = v ? (Blo + (size_t)gn * ldb + (size_t)ck * 64 + c * 8) : Blo;
            uint32_t d = base + GASZ + (uint32_t)r * GRS + (uint32_t)c * 16u;
            cp16(d, ph, v);
            cp16(d + GBSZ, pl, v);
        }
        cpcommit();
    };

    auto compute = [&](int bsel) {
        uint32_t base = s0 + bsel * GBUF;
        uint32_t ah = base;
        uint32_t bh = base + GASZ, bl = base + GASZ + GBSZ;
#pragma unroll
        for (int ks = 0; ks < 4; ks++) {
            uint32_t af[2][4];
#pragma unroll
            for (int mt = 0; mt < 2; mt++) {
                uint32_t off = a_lane + (uint32_t)mt * (16 * GRS) + (uint32_t)ks * 32u;
                ldsm4(af[mt], ah + off);
            }
            uint32_t bfh[2][4], bfl[2][4];
#pragma unroll
            for (int np = 0; np < 2; np++) {
                uint32_t off = b_lane + (uint32_t)np * (16 * GRS) + (uint32_t)ks * 32u;
                ldsm4(bfh[np], bh + off);
                ldsm4(bfl[np], bl + off);
            }
#pragma unroll
            for (int mt = 0; mt < 2; mt++)
#pragma unroll
                for (int nt = 0; nt < 4; nt++) {
                    const uint32_t* Bh2 = &bfh[nt >> 1][(nt & 1) * 2];
                    const uint32_t* Bl2 = &bfl[nt >> 1][(nt & 1) * 2];
                    mma_h_f32(lead[mt][nt], af[mt], Bh2);
                    mma_h_f16(cross[mt][nt], af[mt], Bl2);
                }
        }
    };

    load_chunk(0, 0);
    for (int ck = 0; ck < NC; ck++) {
        if (ck + 1 < NC) { load_chunk(ck + 1, (ck + 1) & 1); cpwait1(); }
        else             { cpwait0(); }
        __syncthreads();
        compute(ck & 1);
        __syncthreads();
    }

    const float INV = 1.0f / 2048.0f;
#pragma unroll
    for (int mt = 0; mt < 2; mt++) {
#pragma unroll
        for (int nt = 0; nt < 4; nt++) {
            int r0 = row0 + wm0 + mt * 16 + (lane >> 2);
            int c0 = col0 + wn0 + nt * 8 + (lane & 3) * 2;
            float* a4 = lead[mt][nt];
#pragma unroll
            for (int h = 0; h < 2; h++) {
                int gm = r0 + h * 8;
                if (gm >= M) continue;
                __half2 cx = *reinterpret_cast<__half2*>(&cross[mt][nt][h]);
                float v0 = a4[h * 2]     + __half2float(cx.x) * INV;
                float v1 = a4[h * 2 + 1] + __half2float(cx.y) * INV;
                if (bias) { v0 += bias[c0]; v1 += bias[c0 + 1]; }
                if (EPI == 0) {
                    if (res) {
                        v0 += res[(size_t)gm * ldc + c0];
                        v1 += res[(size_t)gm * ldc + c0 + 1];
                    }
                    Cf[(size_t)gm * ldc + c0]     = v0;
                    Cf[(size_t)gm * ldc + c0 + 1] = v1;
                } else if (EPI == 1) {
                    uint32_t lo, hi = packsplit_hi(v0, v1, lo);
                    *reinterpret_cast<uint32_t*>(Cbh + (size_t)gm * ldc + c0) = hi;
                    *reinterpret_cast<uint32_t*>(Cbl + (size_t)gm * ldc + c0) = lo;
                } else {
                    *reinterpret_cast<uint32_t*>(Chh + (size_t)gm * ldc + c0) =
                        packh2(geluf(v0), geluf(v1));
                }
            }
        }
    }
}

template <int EPI>
static void hgemm(const f16* A, int lda,
                  const f16* Bh, const f16* Bl, int ldb,
                  float* Cf, bf16* Cbh, bf16* Cbl, f16* Chh, int ldc,
                  const float* bias, const float* res, int M, int N, int K) {
    int smem = 2 * GBUF;   // 92160
    cudaFuncSetAttribute(h16_gemm<EPI>, cudaFuncAttributeMaxDynamicSharedMemorySize, smem);
    dim3 grid(N / 128, (M + 63) / 64, 1);
    h16_gemm<EPI><<<grid, 256, smem>>>(A, lda, Bh, Bl, ldb, Cf, Cbh, Cbl, Chh,
                                       ldc, bias, res, M, N, K / 64);
}

extern "C" void kernel_launch(void* const* d_in, const int* in_sizes, int n_in,
                              void* d_out, int out_size) {
    const float* x       = (const float*)d_in[0];
    const float* conv_w  = (const float*)d_in[1];
    const float* conv_b  = (const float*)d_in[2];
    const float* cls_tok = (const float*)d_in[3];
    const float* pos_emb = (const float*)d_in[4];
    const float* ln1_g   = (const float*)d_in[5];
    const float* ln1_b   = (const float*)d_in[6];
    const float* qkv_w   = (const float*)d_in[7];
    const float* qkv_b   = (const float*)d_in[8];
    const float* proj_w  = (const float*)d_in[9];
    const float* proj_b  = (const float*)d_in[10];
    const float* ln2_g   = (const float*)d_in[11];
    const float* ln2_b   = (const float*)d_in[12];
    const float* mlp_w1  = (const float*)d_in[13];
    const float* mlp_b1  = (const float*)d_in[14];
    const float* mlp_w2  = (const float*)d_in[15];
    const float* mlp_b2  = (const float*)d_in[16];
    const float* lnf_g   = (const float*)d_in[17];
    const float* lnf_b   = (const float*)d_in[18];
    float* out = (float*)d_out;

    f16 *wh, *wl, *cwh, *cwl, *pxh, *xh, *ahp, *mh;
    float *ph, *ptmp;
    bf16 *qhi, *qlo, *vthi, *vtlo;
    cudaGetSymbolAddress((void**)&wh, g_wh);
    cudaGetSymbolAddress((void**)&wl, g_wl);
    cudaGetSymbolAddress((void**)&cwh, g_cwh);
    cudaGetSymbolAddress((void**)&cwl, g_cwl);
    cudaGetSymbolAddress((void**)&pxh, g_pxh);
    cudaGetSymbolAddress((void**)&xh, g_xh);
    cudaGetSymbolAddress((void**)&ahp, g_ah);
    cudaGetSymbolAddress((void**)&mh, g_mh);
    cudaGetSymbolAddress((void**)&ph, g_h);
    cudaGetSymbolAddress((void**)&ptmp, g_ptmp);
    cudaGetSymbolAddress((void**)&qhi, g_qhi);
    cudaGetSymbolAddress((void**)&qlo, g_qlo);
    cudaGetSymbolAddress((void**)&vthi, g_vthi);
    cudaGetSymbolAddress((void**)&vtlo, g_vtlo);

    dim3 tb(32, 8);

    // ---- weight prep (fp16 split) ----
    split_h<<<(DM * DM + 255) / 256, 256>>>(conv_w, cwh, cwl, DM * DM);
    for (int l = 0; l < LAYERS; l++) {
        long long wo = (long long)l * LW;
        wt_trans_h<<<dim3(2304 / 32, 768 / 32), tb>>>(qkv_w + (size_t)l * DM * 3 * DM,
                                                      wh + wo, wl + wo, DM, 3 * DM);
        wt_trans_h<<<dim3(768 / 32, 768 / 32), tb>>>(proj_w + (size_t)l * DM * DM,
                                                     wh + wo + 1769472, wl + wo + 1769472, DM, DM);
        wt_trans_h<<<dim3(3072 / 32, 768 / 32), tb>>>(mlp_w1 + (size_t)l * DM * 4 * DM,
                                                      wh + wo + 2359296, wl + wo + 2359296, DM, 4 * DM);
        wt_trans_h<<<dim3(768 / 32, 3072 / 32), tb>>>(mlp_w2 + (size_t)l * 4 * DM * DM,
                                                      wh + wo + 4718592, wl + wo + 4718592, 4 * DM, DM);
    }

    // ---- patch embed ----
    im2col_h<<<(MPATCH * DM + 255) / 256, 256>>>(x, pxh);
    hgemm<0>(pxh, DM, cwh, cwl, DM, ptmp, nullptr, nullptr, nullptr, DM,
             conv_b, nullptr, MPATCH, DM, DM);
    assemble_kernel<<<(MTOK * DM + 255) / 256, 256>>>(ptmp, cls_tok, pos_emb, ph);

    cudaFuncSetAttribute(fused_attn, cudaFuncAttributeMaxDynamicSharedMemorySize, FA_SMEM);

    for (int l = 0; l < LAYERS; l++) {
        long long wo = (long long)l * LW;
        const f16* qwT_h = wh + wo;            const f16* qwT_l = wl + wo;
        const f16* pwT_h = wh + wo + 1769472;  const f16* pwT_l = wl + wo + 1769472;
        const f16* w1T_h = wh + wo + 2359296;  const f16* w1T_l = wl + wo + 2359296;
        const f16* w2T_h = wh + wo + 4718592;  const f16* w2T_l = wl + wo + 4718592;
        const float* l1g = ln1_g + (size_t)l * DM;
        const float* l1b = ln1_b + (size_t)l * DM;
        const float* qb  = qkv_b + (size_t)l * 3 * DM;
        const float* pb  = proj_b + (size_t)l * DM;
        const float* l2g = ln2_g + (size_t)l * DM;
        const float* l2b = ln2_b + (size_t)l * DM;
        const float* b1  = mlp_b1 + (size_t)l * 4 * DM;
        const float* b2  = mlp_b2 + (size_t)l * DM;

        // LN1 -> single fp16
        ln_h<<<MTOK, 256>>>(ph, l1g, l1b, xh);
        // QKV -> bf16 pair (attention input)
        hgemm<1>(xh, DM, qwT_h, qwT_l, DM, nullptr, qhi, qlo, nullptr, 3 * DM,
                 qb, nullptr, MTOK, 3 * DM, DM);
        // V transpose (validated)
        {
            size_t n = (size_t)BATCH * HEADS * 64 * SPAD;
            vt_split<<<(unsigned)((n + 255) / 256), 256>>>(qhi, qlo, vthi, vtlo);
        }
        // fused attention -> single fp16
        fused_attn<<<dim3(NCHUNK, BATCH * HEADS), 256, FA_SMEM>>>(qhi, qlo, vthi, vtlo, ahp);
        // proj + bias + residual -> h
        hgemm<0>(ahp, DM, pwT_h, pwT_l, DM, ph, nullptr, nullptr, nullptr, DM,
                 pb, ph, MTOK, DM, DM);
        // LN2 -> single fp16
        ln_h<<<MTOK, 256>>>(ph, l2g, l2b, xh);
        // MLP1 + gelu -> single fp16
        hgemm<2>(xh, DM, w1T_h, w1T_l, DM, nullptr, nullptr, nullptr, mh, 4 * DM,
                 b1, nullptr, MTOK, 4 * DM, DM);
        // MLP2 + bias + residual -> h
        hgemm<0>(mh, 4 * DM, w2T_h, w2T_l, 4 * DM, ph, nullptr, nullptr, nullptr, DM,
                 b2, ph, MTOK, DM, 4 * DM);
    }

    // final LN on CLS rows -> out [8,768]
    ln_kernel<<<BATCH, 256>>>(ph, lnf_g, lnf_b, out, (long long)NTOK * DM, DM);
}

// round 13
// speedup vs baseline: 3.4754x; 1.1720x over previous
#include <cuda_runtime.h>
#include <cuda_bf16.h>
#include <cuda_fp16.h>
#include <math.h>
#include <stdint.h>

using bf16 = __nv_bfloat16;
using f16 = __half;

// ---------------- problem constants ----------------
static constexpr int BATCH  = 8;
static constexpr int DM     = 768;
static constexpr int HEADS  = 12;
static constexpr int LAYERS = 12;
static constexpr int NTOK   = 785;
static constexpr int NPATCH = 784;
static constexpr int MTOK   = BATCH * NTOK;    // 6280
static constexpr int MPATCH = BATCH * NPATCH;  // 6272
static constexpr int IMG    = 448;
static constexpr int PSZ    = 16;
static constexpr int GRID28 = 28;
static constexpr int SPAD   = 896;
static constexpr long long LW = 7077888LL;

// ---------------- device scratch ----------------
__device__ f16  g_wh[(size_t)LAYERS * LW];     // weights hi
__device__ f16  g_wl[(size_t)LAYERS * LW];     // weights lo (qkv/proj use; mlp ignores)
__device__ f16  g_cwh[DM * DM];
__device__ f16  g_cwl[DM * DM];
__device__ f16  g_pxh[(size_t)MPATCH * DM];
__device__ f16  g_xh[(size_t)MTOK * DM];
__device__ f16  g_ah[(size_t)MTOK * DM];
__device__ f16  g_mh[(size_t)MTOK * 4 * DM];
__device__ float g_h[(size_t)MTOK * DM];
__device__ float g_ptmp[(size_t)MPATCH * DM];
__device__ bf16  g_qhi[(size_t)MTOK * 3 * DM];
__device__ bf16  g_qlo[(size_t)MTOK * 3 * DM];
__device__ bf16  g_vthi[(size_t)BATCH * HEADS * 64 * SPAD];
__device__ bf16  g_vtlo[(size_t)BATCH * HEADS * 64 * SPAD];

// ---------------- small helpers ----------------
__device__ __forceinline__ void split2(float v, bf16& h, bf16& l) {
    h = __float2bfloat16(v);
    l = __float2bfloat16(v - __bfloat162float(h));
}
__device__ __forceinline__ float geluf(float v) {
    return 0.5f * v * (1.0f + erff(v * 0.70710678118654752f));
}
__device__ __forceinline__ float warpSum(float v) {
#pragma unroll
    for (int o = 16; o > 0; o >>= 1) v += __shfl_xor_sync(0xffffffffu, v, o);
    return v;
}
__device__ __forceinline__ float blockSum256(float v, float* sh) {
    int lane = threadIdx.x & 31, w = threadIdx.x >> 5;
    v = warpSum(v);
    if (lane == 0) sh[w] = v;
    __syncthreads();
    float r = (threadIdx.x < 8) ? sh[threadIdx.x] : 0.f;
    if (w == 0) { r = warpSum(r); if (lane == 0) sh[0] = r; }
    __syncthreads();
    r = sh[0];
    __syncthreads();
    return r;
}

// ---------------- PTX wrappers ----------------
__device__ __forceinline__ uint32_t s2u(const void* p) {
    uint32_t a;
    asm("{ .reg .u64 t; cvta.to.shared.u64 t, %1; cvt.u32.u64 %0, t; }" : "=r"(a) : "l"(p));
    return a;
}
__device__ __forceinline__ void cp16(uint32_t d, const void* s, bool pred) {
    int sz = pred ? 16 : 0;
    asm volatile("cp.async.cg.shared.global [%0], [%1], 16, %2;" :: "r"(d), "l"(s), "r"(sz));
}
__device__ __forceinline__ void cpcommit() { asm volatile("cp.async.commit_group;" ::: "memory"); }
__device__ __forceinline__ void cpwait0()  { asm volatile("cp.async.wait_group 0;" ::: "memory"); }
__device__ __forceinline__ void cpwait1()  { asm volatile("cp.async.wait_group 1;" ::: "memory"); }
__device__ __forceinline__ void ldsm4(uint32_t* r, uint32_t addr) {
    asm volatile("ldmatrix.sync.aligned.m8n8.x4.shared.b16 {%0,%1,%2,%3}, [%4];"
                 : "=r"(r[0]), "=r"(r[1]), "=r"(r[2]), "=r"(r[3]) : "r"(addr));
}
// bf16 operands, f32 acc (validated; attention only)
__device__ __forceinline__ void mma16816(float* c, const uint32_t* a, const uint32_t* b) {
    asm volatile(
        "mma.sync.aligned.m16n8k16.row.col.f32.bf16.bf16.f32 "
        "{%0,%1,%2,%3}, {%4,%5,%6,%7}, {%8,%9}, {%0,%1,%2,%3};"
        : "+f"(c[0]), "+f"(c[1]), "+f"(c[2]), "+f"(c[3])
        : "r"(a[0]), "r"(a[1]), "r"(a[2]), "r"(a[3]), "r"(b[0]), "r"(b[1]));
}
// f16 operands, f32 acc (lead term)
__device__ __forceinline__ void mma_h_f32(float* c, const uint32_t* a, const uint32_t* b) {
    asm volatile(
        "mma.sync.aligned.m16n8k16.row.col.f32.f16.f16.f32 "
        "{%0,%1,%2,%3}, {%4,%5,%6,%7}, {%8,%9}, {%0,%1,%2,%3};"
        : "+f"(c[0]), "+f"(c[1]), "+f"(c[2]), "+f"(c[3])
        : "r"(a[0]), "r"(a[1]), "r"(a[2]), "r"(a[3]), "r"(b[0]), "r"(b[1]));
}
// f16 operands, f16 acc (cross term; 2 C regs)
__device__ __forceinline__ void mma_h_f16(uint32_t* c, const uint32_t* a, const uint32_t* b) {
    asm volatile(
        "mma.sync.aligned.m16n8k16.row.col.f16.f16.f16.f16 "
        "{%0,%1}, {%2,%3,%4,%5}, {%6,%7}, {%0,%1};"
        : "+r"(c[0]), "+r"(c[1])
        : "r"(a[0]), "r"(a[1]), "r"(a[2]), "r"(a[3]), "r"(b[0]), "r"(b[1]));
}
// bf16 split pack (attention internals; validated)
__device__ __forceinline__ uint32_t packsplit_hi(float a, float b, uint32_t& lo) {
    bf16 ah, al, bh, bl;
    split2(a, ah, al);
    split2(b, bh, bl);
    __nv_bfloat162 h2; h2.x = ah; h2.y = bh;
    __nv_bfloat162 l2; l2.x = al; l2.y = bl;
    lo = *reinterpret_cast<uint32_t*>(&l2);
    return *reinterpret_cast<uint32_t*>(&h2);
}
__device__ __forceinline__ uint32_t packh2(float a, float b) {
    __half2 h2 = __halves2half2(__float2half(a), __float2half(b));
    return *reinterpret_cast<uint32_t*>(&h2);
}
__device__ __forceinline__ void splith(float v, f16& h, f16& l) {
    h = __float2half(v);
    l = __float2half((v - __half2float(h)) * 2048.f);
}

// ---------------- elementwise / prep kernels ----------------
__global__ void im2col_h(const float* __restrict__ x, f16* __restrict__ Ph) {
    int idx = blockIdx.x * blockDim.x + threadIdx.x;
    if (idx >= MPATCH * DM) return;
    int k = idx % DM, m = idx / DM;
    int b = m / NPATCH, t = m % NPATCH;
    int py = t / GRID28, px = t % GRID28;
    int c = k >> 8, rem = k & 255, i = rem >> 4, j = rem & 15;
    size_t src = (((size_t)(b * 3 + c) * IMG) + (size_t)(py * PSZ + i)) * IMG + (px * PSZ + j);
    Ph[idx] = __float2half(x[src]);
}

__global__ void split_h(const float* __restrict__ W, f16* __restrict__ Oh,
                        f16* __restrict__ Ol, int n) {
    int idx = blockIdx.x * blockDim.x + threadIdx.x;
    if (idx >= n) return;
    f16 h, l;
    splith(W[idx], h, l);
    Oh[idx] = h; Ol[idx] = l;
}

// W[K,N] row-major -> out[n*K + k] (transpose + fp16 split)
__global__ void wt_trans_h(const float* __restrict__ W, f16* __restrict__ Oh,
                           f16* __restrict__ Ol, int K, int N) {
    __shared__ float tile[32][33];
    int kb = blockIdx.y * 32, nb = blockIdx.x * 32;
    int tx = threadIdx.x, ty = threadIdx.y;  // 32 x 8
#pragma unroll
    for (int i = 0; i < 32; i += 8) {
        int k = kb + ty + i, n = nb + tx;
        tile[ty + i][tx] = (k < K && n < N) ? W[(size_t)k * N + n] : 0.f;
    }
    __syncthreads();
#pragma unroll
    for (int i = 0; i < 32; i += 8) {
        int n = nb + ty + i, k = kb + tx;
        if (n < N && k < K) {
            f16 h, l;
            splith(tile[tx][ty + i], h, l);
            Oh[(size_t)n * K + k] = h;
            Ol[(size_t)n * K + k] = l;
        }
    }
}

// transpose, single fp16 out (MLP weights)
__global__ void wt_trans_h1(const float* __restrict__ W, f16* __restrict__ Oh,
                            int K, int N) {
    __shared__ float tile[32][33];
    int kb = blockIdx.y * 32, nb = blockIdx.x * 32;
    int tx = threadIdx.x, ty = threadIdx.y;  // 32 x 8
#pragma unroll
    for (int i = 0; i < 32; i += 8) {
        int k = kb + ty + i, n = nb + tx;
        tile[ty + i][tx] = (k < K && n < N) ? W[(size_t)k * N + n] : 0.f;
    }
    __syncthreads();
#pragma unroll
    for (int i = 0; i < 32; i += 8) {
        int n = nb + ty + i, k = kb + tx;
        if (n < N && k < K)
            Oh[(size_t)n * K + k] = __float2half(tile[tx][ty + i]);
    }
}

__global__ void assemble_kernel(const float* __restrict__ tok, const float* __restrict__ cls,
                                const float* __restrict__ pos, float* __restrict__ H) {
    int idx = blockIdx.x * blockDim.x + threadIdx.x;
    if (idx >= MTOK * DM) return;
    int d = idx % DM;
    int r = idx / DM;
    int n = r % NTOK, b = r / NTOK;
    float v;
    if (n == 0) v = cls[d] + pos[d];
    else        v = tok[((size_t)b * NPATCH + (n - 1)) * DM + d] + pos[(size_t)n * DM + d];
    H[idx] = v;
}

__global__ void ln_kernel(const float* __restrict__ X, const float* __restrict__ g,
                          const float* __restrict__ bb, float* __restrict__ Y,
                          long long inStride, long long outStride) {
    const float* x = X + (long long)blockIdx.x * inStride;
    float* y = Y + (long long)blockIdx.x * outStride;
    int t = threadIdx.x;
    __shared__ float sh[8];
    float v0 = x[t], v1 = x[t + 256], v2 = x[t + 512];
    float mu = blockSum256(v0 + v1 + v2, sh) * (1.0f / 768.0f);
    float d0 = v0 - mu, d1 = v1 - mu, d2 = v2 - mu;
    float var = blockSum256(d0 * d0 + d1 * d1 + d2 * d2, sh) * (1.0f / 768.0f);
    float rs = rsqrtf(var + 1e-5f);
    y[t]       = d0 * rs * g[t]       + bb[t];
    y[t + 256] = d1 * rs * g[t + 256] + bb[t + 256];
    y[t + 512] = d2 * rs * g[t + 512] + bb[t + 512];
}

// LN -> single fp16
__global__ void ln_h(const float* __restrict__ X, const float* __restrict__ g,
                     const float* __restrict__ bb, f16* __restrict__ Yh) {
    const float* x = X + (size_t)blockIdx.x * DM;
    f16* yh = Yh + (size_t)blockIdx.x * DM;
    int t = threadIdx.x;
    __shared__ float sh[8];
    float v0 = x[t], v1 = x[t + 256], v2 = x[t + 512];
    float mu = blockSum256(v0 + v1 + v2, sh) * (1.0f / 768.0f);
    float d0 = v0 - mu, d1 = v1 - mu, d2 = v2 - mu;
    float var = blockSum256(d0 * d0 + d1 * d1 + d2 * d2, sh) * (1.0f / 768.0f);
    float rs = rsqrtf(var + 1e-5f);
    yh[t]       = __float2half(d0 * rs * g[t]       + bb[t]);
    yh[t + 256] = __float2half(d1 * rs * g[t + 256] + bb[t + 256]);
    yh[t + 512] = __float2half(d2 * rs * g[t + 512] + bb[t + 512]);
}

// vT[z][d][t] = qkv[b*785+t][1536 + h*64 + d]  (validated)
__global__ void vt_split(const bf16* __restrict__ Qh, const bf16* __restrict__ Ql,
                         bf16* __restrict__ Vh, bf16* __restrict__ Vl) {
    size_t idx = (size_t)blockIdx.x * blockDim.x + threadIdx.x;
    if (idx >= (size_t)BATCH * HEADS * 64 * SPAD) return;
    int t = (int)(idx % SPAD);
    int d = (int)((idx / SPAD) % 64);
    int z = (int)(idx / ((size_t)SPAD * 64));
    int b = z / HEADS, h = z % HEADS;
    bf16 vh = __float2bfloat16(0.f), vl = vh;
    if (t < NTOK) {
        size_t src = ((size_t)(b * NTOK + t)) * (3 * DM) + 2 * DM + h * 64 + d;
        vh = Qh[src]; vl = Ql[src];
    }
    Vh[idx] = vh; Vl[idx] = vl;
}

// ---------------- fused flash attention (validated; single-fp16 output) ----------------
static constexpr int ARS    = 144;
static constexpr int KTILE  = 128 * ARS;
static constexpr int VRS    = 272;
static constexpr int VTILE  = 64 * VRS;
static constexpr int KVBUF  = 2 * KTILE + 2 * VTILE;
static constexpr int PRS2   = 272;
static constexpr int SPTILE = 128 * PRS2;
static constexpr int OFF_SPH = 2 * KVBUF;
static constexpr int OFF_SPL = OFF_SPH + SPTILE;
static constexpr int OFF_M  = OFF_SPL + SPTILE;
static constexpr int OFF_L  = OFF_M + 512;
static constexpr int OFF_CA = OFF_L + 512;
static constexpr int OFF_T  = OFF_CA + 512;
static constexpr int FA_SMEM = OFF_T + 1024;
static constexpr int NCHUNK = 7;

__global__ void __launch_bounds__(256, 1)
fused_attn(const bf16* __restrict__ qkvh, const bf16* __restrict__ qkvl,
           const bf16* __restrict__ vth, const bf16* __restrict__ vtl,
           f16* __restrict__ yh) {
    extern __shared__ __align__(16) char smem[];
    uint32_t s0 = s2u(smem);
    const int tid = threadIdx.x, lane = tid & 31, warp = tid >> 5;
    const int qt = blockIdx.x;
    const int z = blockIdx.y;
    const int b = z / HEADS, h = z % HEADS;
    const float SC = 0.125f;

    const int wm0 = warp * 16;
    const uint32_t a_lane  = (uint32_t)(wm0 + (lane & 15)) * ARS + (uint32_t)(lane >> 4) * 16u;
    const uint32_t b_lane  = (uint32_t)((lane & 7) + ((lane >> 4) << 3)) * ARS +
                             (uint32_t)((lane >> 3) & 1) * 16u;
    const uint32_t vb_lane = (uint32_t)((lane & 7) + ((lane >> 4) << 3)) * VRS +
                             (uint32_t)((lane >> 3) & 1) * 16u;
    const uint32_t ap_lane = (uint32_t)(wm0 + (lane & 15)) * PRS2 + (uint32_t)(lane >> 4) * 16u;

    float* mrow = reinterpret_cast<float*>(smem + OFF_M);
    float* lrow = reinterpret_cast<float*>(smem + OFF_L);
    float* crow = reinterpret_cast<float*>(smem + OFF_CA);
    float* tred = reinterpret_cast<float*>(smem + OFF_T);

    auto load_qk = [&](int rowbase, int colbase, uint32_t dsth, uint32_t dstl) {
#pragma unroll
        for (int i = 0; i < 4; i++) {
            int idx = tid + i * 256;
            int r = idx >> 3, g = idx & 7;
            bool v = (rowbase + r) < NTOK;
            size_t off = ((size_t)(b * NTOK + rowbase + r)) * (3 * DM) + colbase + g * 8;
            const bf16* sh2 = v ? (qkvh + off) : qkvh;
            const bf16* sl2 = v ? (qkvl + off) : qkvl;
            uint32_t d = (uint32_t)r * ARS + (uint32_t)g * 16u;
            cp16(dsth + d, sh2, v);
            cp16(dstl + d, sl2, v);
        }
    };
    auto load_vt = [&](int c, uint32_t dsth, uint32_t dstl) {
        const bf16* bh2 = vth + (size_t)z * 64 * SPAD + (size_t)c * 128;
        const bf16* bl2 = vtl + (size_t)z * 64 * SPAD + (size_t)c * 128;
#pragma unroll
        for (int i = 0; i < 4; i++) {
            int idx = tid + i * 256;
            int r = idx >> 4, g = idx & 15;
            size_t off = (size_t)r * SPAD + g * 8;
            uint32_t d = (uint32_t)r * VRS + (uint32_t)g * 16u;
            cp16(dsth + d, bh2 + off, true);
            cp16(dstl + d, bl2 + off, true);
        }
    };
    auto load_chunk = [&](int c, int bsel) {
        uint32_t base = s0 + bsel * KVBUF;
        load_qk(c * 128, DM + h * 64, base, base + KTILE);
        load_vt(c, base + 2 * KTILE, base + 2 * KTILE + VTILE);
        cpcommit();
    };

    load_qk(qt * 128, h * 64, s0 + OFF_SPH, s0 + OFF_SPH + KTILE);
    cpcommit();
    cpwait0();
    __syncthreads();
    uint32_t aQh[4][4], aQl[4][4];
#pragma unroll
    for (int ks = 0; ks < 4; ks++) {
        ldsm4(aQh[ks], s0 + OFF_SPH + a_lane + ks * 32);
        ldsm4(aQl[ks], s0 + OFF_SPH + KTILE + a_lane + ks * 32);
    }
    if (tid < 128) { mrow[tid] = -1e30f; lrow[tid] = 0.f; }
    __syncthreads();

    float o[8][4];
#pragma unroll
    for (int i = 0; i < 8; i++)
#pragma unroll
        for (int j = 0; j < 4; j++) o[i][j] = 0.f;

    load_chunk(0, 0);
    for (int c = 0; c < NCHUNK; c++) {
        if (c + 1 < NCHUNK) { load_chunk(c + 1, (c + 1) & 1); cpwait1(); }
        else                { cpwait0(); }
        __syncthreads();
        uint32_t kvb = s0 + (c & 1) * KVBUF;
        uint32_t Kh = kvb, Kl = kvb + KTILE;
        uint32_t Vh = kvb + 2 * KTILE, Vl = kvb + 2 * KTILE + VTILE;

        float s[16][4];
#pragma unroll
        for (int j = 0; j < 16; j++)
#pragma unroll
            for (int q = 0; q < 4; q++) s[j][q] = 0.f;
#pragma unroll
        for (int ks = 0; ks < 4; ks++) {
#pragma unroll
            for (int jp = 0; jp < 8; jp++) {
                uint32_t kh[4], kl[4];
                uint32_t koff = b_lane + (uint32_t)jp * (16 * ARS) + (uint32_t)ks * 32u;
                ldsm4(kh, Kh + koff);
                ldsm4(kl, Kl + koff);
#pragma unroll
                for (int hf = 0; hf < 2; hf++) {
                    int j = jp * 2 + hf;
                    mma16816(s[j], aQh[ks], &kh[hf * 2]);
                    mma16816(s[j], aQh[ks], &kl[hf * 2]);
                    mma16816(s[j], aQl[ks], &kh[hf * 2]);
                }
            }
        }

        {
            char* smp = smem;
            int r0 = wm0 + (lane >> 2);
            int c0 = 2 * (lane & 3);
#pragma unroll
            for (int j = 0; j < 16; j++) {
                int cc = j * 8 + c0;
                uint32_t loA, hiA = packsplit_hi(s[j][0], s[j][1], loA);
                uint32_t loB, hiB = packsplit_hi(s[j][2], s[j][3], loB);
                *(uint32_t*)(smp + OFF_SPH + (uint32_t)r0 * PRS2 + cc * 2) = hiA;
                *(uint32_t*)(smp + OFF_SPL + (uint32_t)r0 * PRS2 + cc * 2) = loA;
                *(uint32_t*)(smp + OFF_SPH + (uint32_t)(r0 + 8) * PRS2 + cc * 2) = hiB;
                *(uint32_t*)(smp + OFF_SPL + (uint32_t)(r0 + 8) * PRS2 + cc * 2) = loB;
            }
        }
        __syncthreads();

        const int r = tid >> 1, half = tid & 1;
        char* smp = smem;
        const uint32_t rowoff = (uint32_t)r * PRS2 + (uint32_t)half * 128u;
        const int colbase = c * 128 + half * 64;
        const int nvalid0 = NTOK - colbase;
        const int nvalid = nvalid0 < 0 ? 0 : (nvalid0 > 64 ? 64 : nvalid0);

        float chmax = -1e30f;
#pragma unroll 8
        for (int k = 0; k < 64; k += 2) {
            uint32_t hi = *(uint32_t*)(smp + OFF_SPH + rowoff + k * 2);
            uint32_t lo = *(uint32_t*)(smp + OFF_SPL + rowoff + k * 2);
            __nv_bfloat162 h2 = *reinterpret_cast<__nv_bfloat162*>(&hi);
            __nv_bfloat162 l2 = *reinterpret_cast<__nv_bfloat162*>(&lo);
            float v0 = __bfloat162float(h2.x) + __bfloat162float(l2.x);
            float v1 = __bfloat162float(h2.y) + __bfloat162float(l2.y);
            if (k < nvalid)     chmax = fmaxf(chmax, v0);
            if (k + 1 < nvalid) chmax = fmaxf(chmax, v1);
        }
        tred[tid] = chmax;
        __syncthreads();
        float m_old = mrow[r];
        float rmax = fmaxf(tred[2 * r], tred[2 * r + 1]);
        float m_new = fmaxf(m_old, rmax);
        float ca = __expf(SC * (m_old - m_new));
        __syncthreads();

        float esum = 0.f;
#pragma unroll 8
        for (int k = 0; k < 64; k += 2) {
            uint32_t hi = *(uint32_t*)(smp + OFF_SPH + rowoff + k * 2);
            uint32_t lo = *(uint32_t*)(smp + OFF_SPL + rowoff + k * 2);
            __nv_bfloat162 h2 = *reinterpret_cast<__nv_bfloat162*>(&hi);
            __nv_bfloat162 l2 = *reinterpret_cast<__nv_bfloat162*>(&lo);
            float v0 = __bfloat162float(h2.x) + __bfloat162float(l2.x);
            float v1 = __bfloat162float(h2.y) + __bfloat162float(l2.y);
            float e0 = (k < nvalid)     ? __expf(SC * (v0 - m_new)) : 0.f;
            float e1 = (k + 1 < nvalid) ? __expf(SC * (v1 - m_new)) : 0.f;
            esum += e0 + e1;
            uint32_t plo, phi = packsplit_hi(e0, e1, plo);
            *(uint32_t*)(smp + OFF_SPH + rowoff + k * 2) = phi;
            *(uint32_t*)(smp + OFF_SPL + rowoff + k * 2) = plo;
        }
        tred[tid] = esum;
        __syncthreads();
        if (half == 0) {
            lrow[r] = lrow[r] * ca + tred[2 * r] + tred[2 * r + 1];
            mrow[r] = m_new;
            crow[r] = ca;
        }
        __syncthreads();

        float caA = crow[wm0 + (lane >> 2)];
        float caB = crow[wm0 + 8 + (lane >> 2)];
#pragma unroll
        for (int nt = 0; nt < 8; nt++) {
            o[nt][0] *= caA; o[nt][1] *= caA;
            o[nt][2] *= caB; o[nt][3] *= caB;
        }

#pragma unroll
        for (int kt = 0; kt < 8; kt++) {
            uint32_t pa[4], pb[4];
            ldsm4(pa, s0 + OFF_SPH + ap_lane + (uint32_t)kt * 32u);
            ldsm4(pb, s0 + OFF_SPL + ap_lane + (uint32_t)kt * 32u);
#pragma unroll
            for (int dp = 0; dp < 4; dp++) {
                uint32_t vh[4], vl[4];
                uint32_t voff = vb_lane + (uint32_t)dp * (16 * VRS) + (uint32_t)kt * 32u;
                ldsm4(vh, Vh + voff);
                ldsm4(vl, Vl + voff);
#pragma unroll
                for (int hf = 0; hf < 2; hf++) {
                    int nt = dp * 2 + hf;
                    mma16816(o[nt], pa, &vh[hf * 2]);
                    mma16816(o[nt], pa, &vl[hf * 2]);
                    mma16816(o[nt], pb, &vh[hf * 2]);
                }
            }
        }
        __syncthreads();
    }

    float la = lrow[wm0 + (lane >> 2)];
    float lb = lrow[wm0 + 8 + (lane >> 2)];
    float ia = 1.0f / la, ib = 1.0f / lb;
    int ra = qt * 128 + wm0 + (lane >> 2);
    int rb = ra + 8;
#pragma unroll
    for (int nt = 0; nt < 8; nt++) {
        int col = h * 64 + nt * 8 + 2 * (lane & 3);
        if (ra < NTOK) {
            size_t p = (size_t)(b * NTOK + ra) * DM + col;
            *reinterpret_cast<uint32_t*>(yh + p) = packh2(o[nt][0] * ia, o[nt][1] * ia);
        }
        if (rb < NTOK) {
            size_t p = (size_t)(b * NTOK + rb) * DM + col;
            *reinterpret_cast<uint32_t*>(yh + p) = packh2(o[nt][2] * ib, o[nt][3] * ib);
        }
    }
}

// ---------------- fp16 GEMM: A single fp16, B split (BSPLIT=1) or single (0) ----------
// BSPLIT=1: C = A*Bh [f32] + A*Bl [f16]/2048.  BSPLIT=0: C = A*Bh [f32].
// BM=64 x BN=128, 8 warps (32x32 each), BK=64, double-buffered, occupancy 2.
// EPI: 0 fp32 (+bias?+res?), 1 bf16 split (+bias) [qkv], 2 fp16 single gelu (+bias)
static constexpr int GRS   = 144;
static constexpr int GASZ  = 64 * GRS;             // A plane 9216
static constexpr int GBSZ  = 128 * GRS;            // B plane 18432

template <int EPI, int BSPLIT>
__global__ void __launch_bounds__(256, 2)
h16_gemm(const f16* __restrict__ A, int lda,
         const f16* __restrict__ Bhi, const f16* __restrict__ Blo, int ldb,
         float* __restrict__ Cf, bf16* __restrict__ Cbh, bf16* __restrict__ Cbl,
         f16* __restrict__ Chh, int ldc,
         const float* __restrict__ bias, const float* __restrict__ res,
         int M, int N, int NC) {
    constexpr int GBUF = GASZ + (BSPLIT ? 2 : 1) * GBSZ;
    extern __shared__ __align__(16) char smem[];
    uint32_t s0 = s2u(smem);

    const int tid = threadIdx.x, lane = tid & 31, warp = tid >> 5;
    const int wm0 = (warp >> 2) * 32;
    const int wn0 = (warp & 3) * 32;
    const int row0 = blockIdx.y * 64, col0 = blockIdx.x * 128;

    float lead[2][4][4];
    uint32_t cross[2][4][2];
#pragma unroll
    for (int i = 0; i < 2; i++)
#pragma unroll
        for (int j = 0; j < 4; j++) {
#pragma unroll
            for (int k = 0; k < 4; k++) lead[i][j][k] = 0.f;
            cross[i][j][0] = 0u; cross[i][j][1] = 0u;
        }

    const uint32_t a_lane = (uint32_t)(wm0 + (lane & 15)) * GRS + (uint32_t)(lane >> 4) * 16u;
    const uint32_t b_lane = (uint32_t)(wn0 + (lane & 7) + ((lane >> 4) << 3)) * GRS +
                            (uint32_t)((lane >> 3) & 1) * 16u;

    auto load_chunk = [&](int ck, int bsel) {
        uint32_t base = s0 + bsel * GBUF;
#pragma unroll
        for (int i = 0; i < 2; i++) {
            int idx = tid + i * 256;
            int r = idx >> 3, c = idx & 7;
            int gm = row0 + r;
            bool v = gm < M;
            const f16* pa = v ? (A + (size_t)gm * lda + (size_t)ck * 64 + c * 8) : A;
            cp16(base + (uint32_t)r * GRS + (uint32_t)c * 16u, pa, v);
        }
#pragma unroll
        for (int i = 0; i < 4; i++) {
            int idx = tid + i * 256;
            int r = idx >> 3, c = idx & 7;
            int gn = col0 + r;
            bool v = gn < N;
            const f16* ph = v ? (Bhi + (size_t)gn * ldb + (size_t)ck * 64 + c * 8) : Bhi;
            uint32_t d = base + GASZ + (uint32_t)r * GRS + (uint32_t)c * 16u;
            cp16(d, ph, v);
            if (BSPLIT) {
                const f16* pl = v ? (Blo + (size_t)gn * ldb + (size_t)ck * 64 + c * 8) : Blo;
                cp16(d + GBSZ, pl, v);
            }
        }
        cpcommit();
    };

    auto compute = [&](int bsel) {
        uint32_t base = s0 + bsel * GBUF;
        uint32_t ah = base;
        uint32_t bh = base + GASZ, bl = base + GASZ + GBSZ;
#pragma unroll
        for (int ks = 0; ks < 4; ks++) {
            uint32_t af[2][4];
#pragma unroll
            for (int mt = 0; mt < 2; mt++) {
                uint32_t off = a_lane + (uint32_t)mt * (16 * GRS) + (uint32_t)ks * 32u;
                ldsm4(af[mt], ah + off);
            }
            uint32_t bfh[2][4], bfl[2][4];
#pragma unroll
            for (int np = 0; np < 2; np++) {
                uint32_t off = b_lane + (uint32_t)np * (16 * GRS) + (uint32_t)ks * 32u;
                ldsm4(bfh[np], bh + off);
                if (BSPLIT) ldsm4(bfl[np], bl + off);
            }
#pragma unroll
            for (int mt = 0; mt < 2; mt++)
#pragma unroll
                for (int nt = 0; nt < 4; nt++) {
                    const uint32_t* Bh2 = &bfh[nt >> 1][(nt & 1) * 2];
                    mma_h_f32(lead[mt][nt], af[mt], Bh2);
                    if (BSPLIT) {
                        const uint32_t* Bl2 = &bfl[nt >> 1][(nt & 1) * 2];
                        mma_h_f16(cross[mt][nt], af[mt], Bl2);
                    }
                }
        }
    };

    load_chunk(0, 0);
    for (int ck = 0; ck < NC; ck++) {
        if (ck + 1 < NC) { load_chunk(ck + 1, (ck + 1) & 1); cpwait1(); }
        else             { cpwait0(); }
        __syncthreads();
        compute(ck & 1);
        __syncthreads();
    }

    const float INV = 1.0f / 2048.0f;
#pragma unroll
    for (int mt = 0; mt < 2; mt++) {
#pragma unroll
        for (int nt = 0; nt < 4; nt++) {
            int r0 = row0 + wm0 + mt * 16 + (lane >> 2);
            int c0 = col0 + wn0 + nt * 8 + (lane & 3) * 2;
            float* a4 = lead[mt][nt];
#pragma unroll
            for (int h = 0; h < 2; h++) {
                int gm = r0 + h * 8;
                if (gm >= M) continue;
                float v0 = a4[h * 2], v1 = a4[h * 2 + 1];
                if (BSPLIT) {
                    __half2 cx = *reinterpret_cast<__half2*>(&cross[mt][nt][h]);
                    v0 += __half2float(cx.x) * INV;
                    v1 += __half2float(cx.y) * INV;
                }
                if (bias) { v0 += bias[c0]; v1 += bias[c0 + 1]; }
                if (EPI == 0) {
                    if (res) {
                        v0 += res[(size_t)gm * ldc + c0];
                        v1 += res[(size_t)gm * ldc + c0 + 1];
                    }
                    Cf[(size_t)gm * ldc + c0]     = v0;
                    Cf[(size_t)gm * ldc + c0 + 1] = v1;
                } else if (EPI == 1) {
                    uint32_t lo, hi = packsplit_hi(v0, v1, lo);
                    *reinterpret_cast<uint32_t*>(Cbh + (size_t)gm * ldc + c0) = hi;
                    *reinterpret_cast<uint32_t*>(Cbl + (size_t)gm * ldc + c0) = lo;
                } else {
                    *reinterpret_cast<uint32_t*>(Chh + (size_t)gm * ldc + c0) =
                        packh2(geluf(v0), geluf(v1));
                }
            }
        }
    }
}

template <int EPI, int BSPLIT>
static void hgemm(const f16* A, int lda,
                  const f16* Bh, const f16* Bl, int ldb,
                  float* Cf, bf16* Cbh, bf16* Cbl, f16* Chh, int ldc,
                  const float* bias, const float* res, int M, int N, int K) {
    constexpr int GBUF = GASZ + (BSPLIT ? 2 : 1) * GBSZ;
    int smem = 2 * GBUF;
    cudaFuncSetAttribute(h16_gemm<EPI, BSPLIT>, cudaFuncAttributeMaxDynamicSharedMemorySize, smem);
    dim3 grid(N / 128, (M + 63) / 64, 1);
    h16_gemm<EPI, BSPLIT><<<grid, 256, smem>>>(A, lda, Bh, Bl, ldb, Cf, Cbh, Cbl, Chh,
                                               ldc, bias, res, M, N, K / 64);
}

extern "C" void kernel_launch(void* const* d_in, const int* in_sizes, int n_in,
                              void* d_out, int out_size) {
    const float* x       = (const float*)d_in[0];
    const float* conv_w  = (const float*)d_in[1];
    const float* conv_b  = (const float*)d_in[2];
    const float* cls_tok = (const float*)d_in[3];
    const float* pos_emb = (const float*)d_in[4];
    const float* ln1_g   = (const float*)d_in[5];
    const float* ln1_b   = (const float*)d_in[6];
    const float* qkv_w   = (const float*)d_in[7];
    const float* qkv_b   = (const float*)d_in[8];
    const float* proj_w  = (const float*)d_in[9];
    const float* proj_b  = (const float*)d_in[10];
    const float* ln2_g   = (const float*)d_in[11];
    const float* ln2_b   = (const float*)d_in[12];
    const float* mlp_w1  = (const float*)d_in[13];
    const float* mlp_b1  = (const float*)d_in[14];
    const float* mlp_w2  = (const float*)d_in[15];
    const float* mlp_b2  = (const float*)d_in[16];
    const float* lnf_g   = (const float*)d_in[17];
    const float* lnf_b   = (const float*)d_in[18];
    float* out = (float*)d_out;

    f16 *wh, *wl, *cwh, *cwl, *pxh, *xh, *ahp, *mh;
    float *ph, *ptmp;
    bf16 *qhi, *qlo, *vthi, *vtlo;
    cudaGetSymbolAddress((void**)&wh, g_wh);
    cudaGetSymbolAddress((void**)&wl, g_wl);
    cudaGetSymbolAddress((void**)&cwh, g_cwh);
    cudaGetSymbolAddress((void**)&cwl, g_cwl);
    cudaGetSymbolAddress((void**)&pxh, g_pxh);
    cudaGetSymbolAddress((void**)&xh, g_xh);
    cudaGetSymbolAddress((void**)&ahp, g_ah);
    cudaGetSymbolAddress((void**)&mh, g_mh);
    cudaGetSymbolAddress((void**)&ph, g_h);
    cudaGetSymbolAddress((void**)&ptmp, g_ptmp);
    cudaGetSymbolAddress((void**)&qhi, g_qhi);
    cudaGetSymbolAddress((void**)&qlo, g_qlo);
    cudaGetSymbolAddress((void**)&vthi, g_vthi);
    cudaGetSymbolAddress((void**)&vtlo, g_vtlo);

    dim3 tb(32, 8);

    // ---- weight prep: split for qkv/proj/conv, single fp16 for mlp ----
    split_h<<<(DM * DM + 255) / 256, 256>>>(conv_w, cwh, cwl, DM * DM);
    for (int l = 0; l < LAYERS; l++) {
        long long wo = (long long)l * LW;
        wt_trans_h<<<dim3(2304 / 32, 768 / 32), tb>>>(qkv_w + (size_t)l * DM * 3 * DM,
                                                      wh + wo, wl + wo, DM, 3 * DM);
        wt_trans_h<<<dim3(768 / 32, 768 / 32), tb>>>(proj_w + (size_t)l * DM * DM,
                                                     wh + wo + 1769472, wl + wo + 1769472, DM, DM);
        wt_trans_h1<<<dim3(3072 / 32, 768 / 32), tb>>>(mlp_w1 + (size_t)l * DM * 4 * DM,
                                                       wh + wo + 2359296, DM, 4 * DM);
        wt_trans_h1<<<dim3(768 / 32, 3072 / 32), tb>>>(mlp_w2 + (size_t)l * 4 * DM * DM,
                                                       wh + wo + 4718592, 4 * DM, DM);
    }

    // ---- patch embed ----
    im2col_h<<<(MPATCH * DM + 255) / 256, 256>>>(x, pxh);
    hgemm<0, 1>(pxh, DM, cwh, cwl, DM, ptmp, nullptr, nullptr, nullptr, DM,
                conv_b, nullptr, MPATCH, DM, DM);
    assemble_kernel<<<(MTOK * DM + 255) / 256, 256>>>(ptmp, cls_tok, pos_emb, ph);

    cudaFuncSetAttribute(fused_attn, cudaFuncAttributeMaxDynamicSharedMemorySize, FA_SMEM);

    for (int l = 0; l < LAYERS; l++) {
        long long wo = (long long)l * LW;
        const f16* qwT_h = wh + wo;            const f16* qwT_l = wl + wo;
        const f16* pwT_h = wh + wo + 1769472;  const f16* pwT_l = wl + wo + 1769472;
        const f16* w1T_h = wh + wo + 2359296;
        const f16* w2T_h = wh + wo + 4718592;
        const float* l1g = ln1_g + (size_t)l * DM;
        const float* l1b = ln1_b + (size_t)l * DM;
        const float* qb  = qkv_b + (size_t)l * 3 * DM;
        const float* pb  = proj_b + (size_t)l * DM;
        const float* l2g = ln2_g + (size_t)l * DM;
        const float* l2b = ln2_b + (size_t)l * DM;
        const float* b1  = mlp_b1 + (size_t)l * 4 * DM;
        const float* b2  = mlp_b2 + (size_t)l * DM;

        // LN1 -> single fp16
        ln_h<<<MTOK, 256>>>(ph, l1g, l1b, xh);
        // QKV -> bf16 pair (attention input); weights split
        hgemm<1, 1>(xh, DM, qwT_h, qwT_l, DM, nullptr, qhi, qlo, nullptr, 3 * DM,
                    qb, nullptr, MTOK, 3 * DM, DM);
        // V transpose (validated)
        {
            size_t n = (size_t)BATCH * HEADS * 64 * SPAD;
            vt_split<<<(unsigned)((n + 255) / 256), 256>>>(qhi, qlo, vthi, vtlo);
        }
        // fused attention -> single fp16
        fused_attn<<<dim3(NCHUNK, BATCH * HEADS), 256, FA_SMEM>>>(qhi, qlo, vthi, vtlo, ahp);
        // proj + bias + residual -> h; weights split
        hgemm<0, 1>(ahp, DM, pwT_h, pwT_l, DM, ph, nullptr, nullptr, nullptr, DM,
                    pb, ph, MTOK, DM, DM);
        // LN2 -> single fp16
        ln_h<<<MTOK, 256>>>(ph, l2g, l2b, xh);
        // MLP1 + gelu -> single fp16; single-plane weights
        hgemm<2, 0>(xh, DM, w1T_h, nullptr, DM, nullptr, nullptr, nullptr, mh, 4 * DM,
                    b1, nullptr, MTOK, 4 * DM, DM);
        // MLP2 + bias + residual -> h; single-plane weights
        hgemm<0, 0>(mh, 4 * DM, w2T_h, nullptr, 4 * DM, ph, nullptr, nullptr, nullptr, DM,
                    b2, ph, MTOK, DM, 4 * DM);
    }

    // final LN on CLS rows -> out [8,768]
    ln_kernel<<<BATCH, 256>>>(ph, lnf_g, lnf_b, out, (long long)NTOK * DM, DM);
}

// round 14
// speedup vs baseline: 3.6434x; 1.0483x over previous
#include <cuda_runtime.h>
#include <cuda_bf16.h>
#include <cuda_fp16.h>
#include <math.h>
#include <stdint.h>

using bf16 = __nv_bfloat16;
using f16 = __half;

// ---------------- problem constants ----------------
static constexpr int BATCH  = 8;
static constexpr int DM     = 768;
static constexpr int HEADS  = 12;
static constexpr int LAYERS = 12;
static constexpr int NTOK   = 785;
static constexpr int NPATCH = 784;
static constexpr int MTOK   = BATCH * NTOK;    // 6280
static constexpr int MPATCH = BATCH * NPATCH;  // 6272
static constexpr int IMG    = 448;
static constexpr int PSZ    = 16;
static constexpr int GRID28 = 28;
static constexpr int SPAD   = 896;
static constexpr long long LW = 7077888LL;

// ---------------- device scratch ----------------
__device__ f16  g_wh[(size_t)LAYERS * LW];     // weights hi
__device__ f16  g_wl[(size_t)LAYERS * LW];     // weights lo (qkv/proj use; mlp ignores)
__device__ f16  g_cwh[DM * DM];
__device__ f16  g_cwl[DM * DM];
__device__ f16  g_pxh[(size_t)MPATCH * DM];
__device__ f16  g_xh[(size_t)MTOK * DM];
__device__ f16  g_ah[(size_t)MTOK * DM];
__device__ f16  g_mh[(size_t)MTOK * 4 * DM];
__device__ float g_h[(size_t)MTOK * DM];
__device__ float g_ptmp[(size_t)MPATCH * DM];
__device__ bf16  g_qhi[(size_t)MTOK * 3 * DM];
__device__ bf16  g_qlo[(size_t)MTOK * 3 * DM];
__device__ bf16  g_vthi[(size_t)BATCH * HEADS * 64 * SPAD];  // zero-init; tail stays 0
__device__ bf16  g_vtlo[(size_t)BATCH * HEADS * 64 * SPAD];

// ---------------- small helpers ----------------
__device__ __forceinline__ void split2(float v, bf16& h, bf16& l) {
    h = __float2bfloat16(v);
    l = __float2bfloat16(v - __bfloat162float(h));
}
__device__ __forceinline__ float geluf(float v) {
    return 0.5f * v * (1.0f + erff(v * 0.70710678118654752f));
}
__device__ __forceinline__ float warpSum(float v) {
#pragma unroll
    for (int o = 16; o > 0; o >>= 1) v += __shfl_xor_sync(0xffffffffu, v, o);
    return v;
}
__device__ __forceinline__ float blockSum256(float v, float* sh) {
    int lane = threadIdx.x & 31, w = threadIdx.x >> 5;
    v = warpSum(v);
    if (lane == 0) sh[w] = v;
    __syncthreads();
    float r = (threadIdx.x < 8) ? sh[threadIdx.x] : 0.f;
    if (w == 0) { r = warpSum(r); if (lane == 0) sh[0] = r; }
    __syncthreads();
    r = sh[0];
    __syncthreads();
    return r;
}

// ---------------- PTX wrappers ----------------
__device__ __forceinline__ uint32_t s2u(const void* p) {
    uint32_t a;
    asm("{ .reg .u64 t; cvta.to.shared.u64 t, %1; cvt.u32.u64 %0, t; }" : "=r"(a) : "l"(p));
    return a;
}
__device__ __forceinline__ void cp16(uint32_t d, const void* s, bool pred) {
    int sz = pred ? 16 : 0;
    asm volatile("cp.async.cg.shared.global [%0], [%1], 16, %2;" :: "r"(d), "l"(s), "r"(sz));
}
__device__ __forceinline__ void cpcommit() { asm volatile("cp.async.commit_group;" ::: "memory"); }
__device__ __forceinline__ void cpwait0()  { asm volatile("cp.async.wait_group 0;" ::: "memory"); }
__device__ __forceinline__ void cpwait1()  { asm volatile("cp.async.wait_group 1;" ::: "memory"); }
__device__ __forceinline__ void ldsm4(uint32_t* r, uint32_t addr) {
    asm volatile("ldmatrix.sync.aligned.m8n8.x4.shared.b16 {%0,%1,%2,%3}, [%4];"
                 : "=r"(r[0]), "=r"(r[1]), "=r"(r[2]), "=r"(r[3]) : "r"(addr));
}
// bf16 operands, f32 acc (validated; attention only)
__device__ __forceinline__ void mma16816(float* c, const uint32_t* a, const uint32_t* b) {
    asm volatile(
        "mma.sync.aligned.m16n8k16.row.col.f32.bf16.bf16.f32 "
        "{%0,%1,%2,%3}, {%4,%5,%6,%7}, {%8,%9}, {%0,%1,%2,%3};"
        : "+f"(c[0]), "+f"(c[1]), "+f"(c[2]), "+f"(c[3])
        : "r"(a[0]), "r"(a[1]), "r"(a[2]), "r"(a[3]), "r"(b[0]), "r"(b[1]));
}
// f16 operands, f32 acc (lead term)
__device__ __forceinline__ void mma_h_f32(float* c, const uint32_t* a, const uint32_t* b) {
    asm volatile(
        "mma.sync.aligned.m16n8k16.row.col.f32.f16.f16.f32 "
        "{%0,%1,%2,%3}, {%4,%5,%6,%7}, {%8,%9}, {%0,%1,%2,%3};"
        : "+f"(c[0]), "+f"(c[1]), "+f"(c[2]), "+f"(c[3])
        : "r"(a[0]), "r"(a[1]), "r"(a[2]), "r"(a[3]), "r"(b[0]), "r"(b[1]));
}
// f16 operands, f16 acc (cross term; 2 C regs)
__device__ __forceinline__ void mma_h_f16(uint32_t* c, const uint32_t* a, const uint32_t* b) {
    asm volatile(
        "mma.sync.aligned.m16n8k16.row.col.f16.f16.f16.f16 "
        "{%0,%1}, {%2,%3,%4,%5}, {%6,%7}, {%0,%1};"
        : "+r"(c[0]), "+r"(c[1])
        : "r"(a[0]), "r"(a[1]), "r"(a[2]), "r"(a[3]), "r"(b[0]), "r"(b[1]));
}
// bf16 split pack (attention internals; validated)
__device__ __forceinline__ uint32_t packsplit_hi(float a, float b, uint32_t& lo) {
    bf16 ah, al, bh, bl;
    split2(a, ah, al);
    split2(b, bh, bl);
    __nv_bfloat162 h2; h2.x = ah; h2.y = bh;
    __nv_bfloat162 l2; l2.x = al; l2.y = bl;
    lo = *reinterpret_cast<uint32_t*>(&l2);
    return *reinterpret_cast<uint32_t*>(&h2);
}
__device__ __forceinline__ uint32_t packh2(float a, float b) {
    __half2 h2 = __halves2half2(__float2half(a), __float2half(b));
    return *reinterpret_cast<uint32_t*>(&h2);
}
__device__ __forceinline__ void splith(float v, f16& h, f16& l) {
    h = __float2half(v);
    l = __float2half((v - __half2float(h)) * 2048.f);
}

// ---------------- elementwise / prep kernels ----------------
__global__ void im2col_h(const float* __restrict__ x, f16* __restrict__ Ph) {
    int idx = blockIdx.x * blockDim.x + threadIdx.x;
    if (idx >= MPATCH * DM) return;
    int k = idx % DM, m = idx / DM;
    int b = m / NPATCH, t = m % NPATCH;
    int py = t / GRID28, px = t % GRID28;
    int c = k >> 8, rem = k & 255, i = rem >> 4, j = rem & 15;
    size_t src = (((size_t)(b * 3 + c) * IMG) + (size_t)(py * PSZ + i)) * IMG + (px * PSZ + j);
    Ph[idx] = __float2half(x[src]);
}

__global__ void split_h(const float* __restrict__ W, f16* __restrict__ Oh,
                        f16* __restrict__ Ol, int n) {
    int idx = blockIdx.x * blockDim.x + threadIdx.x;
    if (idx >= n) return;
    f16 h, l;
    splith(W[idx], h, l);
    Oh[idx] = h; Ol[idx] = l;
}

// batched over layers (blockIdx.z): W[K,N] -> out[n*K + k], fp16 split
__global__ void wt_trans_hB(const float* __restrict__ W0, f16* __restrict__ Oh0,
                            f16* __restrict__ Ol0, int K, int N,
                            long long sIn, long long sOut) {
    const float* W = W0 + (long long)blockIdx.z * sIn;
    f16* Oh = Oh0 + (long long)blockIdx.z * sOut;
    f16* Ol = Ol0 + (long long)blockIdx.z * sOut;
    __shared__ float tile[32][33];
    int kb = blockIdx.y * 32, nb = blockIdx.x * 32;
    int tx = threadIdx.x, ty = threadIdx.y;  // 32 x 8
#pragma unroll
    for (int i = 0; i < 32; i += 8) {
        int k = kb + ty + i, n = nb + tx;
        tile[ty + i][tx] = (k < K && n < N) ? W[(size_t)k * N + n] : 0.f;
    }
    __syncthreads();
#pragma unroll
    for (int i = 0; i < 32; i += 8) {
        int n = nb + ty + i, k = kb + tx;
        if (n < N && k < K) {
            f16 h, l;
            splith(tile[tx][ty + i], h, l);
            Oh[(size_t)n * K + k] = h;
            Ol[(size_t)n * K + k] = l;
        }
    }
}

// batched, single fp16 out (MLP weights)
__global__ void wt_trans_h1B(const float* __restrict__ W0, f16* __restrict__ Oh0,
                             int K, int N, long long sIn, long long sOut) {
    const float* W = W0 + (long long)blockIdx.z * sIn;
    f16* Oh = Oh0 + (long long)blockIdx.z * sOut;
    __shared__ float tile[32][33];
    int kb = blockIdx.y * 32, nb = blockIdx.x * 32;
    int tx = threadIdx.x, ty = threadIdx.y;
#pragma unroll
    for (int i = 0; i < 32; i += 8) {
        int k = kb + ty + i, n = nb + tx;
        tile[ty + i][tx] = (k < K && n < N) ? W[(size_t)k * N + n] : 0.f;
    }
    __syncthreads();
#pragma unroll
    for (int i = 0; i < 32; i += 8) {
        int n = nb + ty + i, k = kb + tx;
        if (n < N && k < K)
            Oh[(size_t)n * K + k] = __float2half(tile[tx][ty + i]);
    }
}

__global__ void assemble_kernel(const float* __restrict__ tok, const float* __restrict__ cls,
                                const float* __restrict__ pos, float* __restrict__ H) {
    int idx = blockIdx.x * blockDim.x + threadIdx.x;
    if (idx >= MTOK * DM) return;
    int d = idx % DM;
    int r = idx / DM;
    int n = r % NTOK, b = r / NTOK;
    float v;
    if (n == 0) v = cls[d] + pos[d];
    else        v = tok[((size_t)b * NPATCH + (n - 1)) * DM + d] + pos[(size_t)n * DM + d];
    H[idx] = v;
}

__global__ void ln_kernel(const float* __restrict__ X, const float* __restrict__ g,
                          const float* __restrict__ bb, float* __restrict__ Y,
                          long long inStride, long long outStride) {
    const float* x = X + (long long)blockIdx.x * inStride;
    float* y = Y + (long long)blockIdx.x * outStride;
    int t = threadIdx.x;
    __shared__ float sh[8];
    float v0 = x[t], v1 = x[t + 256], v2 = x[t + 512];
    float mu = blockSum256(v0 + v1 + v2, sh) * (1.0f / 768.0f);
    float d0 = v0 - mu, d1 = v1 - mu, d2 = v2 - mu;
    float var = blockSum256(d0 * d0 + d1 * d1 + d2 * d2, sh) * (1.0f / 768.0f);
    float rs = rsqrtf(var + 1e-5f);
    y[t]       = d0 * rs * g[t]       + bb[t];
    y[t + 256] = d1 * rs * g[t + 256] + bb[t + 256];
    y[t + 512] = d2 * rs * g[t + 512] + bb[t + 512];
}

// LN -> single fp16
__global__ void ln_h(const float* __restrict__ X, const float* __restrict__ g,
                     const float* __restrict__ bb, f16* __restrict__ Yh) {
    const float* x = X + (size_t)blockIdx.x * DM;
    f16* yh = Yh + (size_t)blockIdx.x * DM;
    int t = threadIdx.x;
    __shared__ float sh[8];
    float v0 = x[t], v1 = x[t + 256], v2 = x[t + 512];
    float mu = blockSum256(v0 + v1 + v2, sh) * (1.0f / 768.0f);
    float d0 = v0 - mu, d1 = v1 - mu, d2 = v2 - mu;
    float var = blockSum256(d0 * d0 + d1 * d1 + d2 * d2, sh) * (1.0f / 768.0f);
    float rs = rsqrtf(var + 1e-5f);
    yh[t]       = __float2half(d0 * rs * g[t]       + bb[t]);
    yh[t + 256] = __float2half(d1 * rs * g[t + 256] + bb[t + 256]);
    yh[t + 512] = __float2half(d2 * rs * g[t + 512] + bb[t + 512]);
}

// ---------------- fused flash attention (validated; single-fp16 output) ----------------
static constexpr int ARS    = 144;
static constexpr int KTILE  = 128 * ARS;
static constexpr int VRS    = 272;
static constexpr int VTILE  = 64 * VRS;
static constexpr int KVBUF  = 2 * KTILE + 2 * VTILE;
static constexpr int PRS2   = 272;
static constexpr int SPTILE = 128 * PRS2;
static constexpr int OFF_SPH = 2 * KVBUF;
static constexpr int OFF_SPL = OFF_SPH + SPTILE;
static constexpr int OFF_M  = OFF_SPL + SPTILE;
static constexpr int OFF_L  = OFF_M + 512;
static constexpr int OFF_CA = OFF_L + 512;
static constexpr int OFF_T  = OFF_CA + 512;
static constexpr int FA_SMEM = OFF_T + 1024;
static constexpr int NCHUNK = 7;

__global__ void __launch_bounds__(256, 1)
fused_attn(const bf16* __restrict__ qkvh, const bf16* __restrict__ qkvl,
           const bf16* __restrict__ vth, const bf16* __restrict__ vtl,
           f16* __restrict__ yh) {
    extern __shared__ __align__(16) char smem[];
    uint32_t s0 = s2u(smem);
    const int tid = threadIdx.x, lane = tid & 31, warp = tid >> 5;
    const int qt = blockIdx.x;
    const int z = blockIdx.y;
    const int b = z / HEADS, h = z % HEADS;
    const float SC = 0.125f;

    const int wm0 = warp * 16;
    const uint32_t a_lane  = (uint32_t)(wm0 + (lane & 15)) * ARS + (uint32_t)(lane >> 4) * 16u;
    const uint32_t b_lane  = (uint32_t)((lane & 7) + ((lane >> 4) << 3)) * ARS +
                             (uint32_t)((lane >> 3) & 1) * 16u;
    const uint32_t vb_lane = (uint32_t)((lane & 7) + ((lane >> 4) << 3)) * VRS +
                             (uint32_t)((lane >> 3) & 1) * 16u;
    const uint32_t ap_lane = (uint32_t)(wm0 + (lane & 15)) * PRS2 + (uint32_t)(lane >> 4) * 16u;

    float* mrow = reinterpret_cast<float*>(smem + OFF_M);
    float* lrow = reinterpret_cast<float*>(smem + OFF_L);
    float* crow = reinterpret_cast<float*>(smem + OFF_CA);
    float* tred = reinterpret_cast<float*>(smem + OFF_T);

    auto load_qk = [&](int rowbase, int colbase, uint32_t dsth, uint32_t dstl) {
#pragma unroll
        for (int i = 0; i < 4; i++) {
            int idx = tid + i * 256;
            int r = idx >> 3, g = idx & 7;
            bool v = (rowbase + r) < NTOK;
            size_t off = ((size_t)(b * NTOK + rowbase + r)) * (3 * DM) + colbase + g * 8;
            const bf16* sh2 = v ? (qkvh + off) : qkvh;
            const bf16* sl2 = v ? (qkvl + off) : qkvl;
            uint32_t d = (uint32_t)r * ARS + (uint32_t)g * 16u;
            cp16(dsth + d, sh2, v);
            cp16(dstl + d, sl2, v);
        }
    };
    auto load_vt = [&](int c, uint32_t dsth, uint32_t dstl) {
        const bf16* bh2 = vth + (size_t)z * 64 * SPAD + (size_t)c * 128;
        const bf16* bl2 = vtl + (size_t)z * 64 * SPAD + (size_t)c * 128;
#pragma unroll
        for (int i = 0; i < 4; i++) {
            int idx = tid + i * 256;
            int r = idx >> 4, g = idx & 15;
            size_t off = (size_t)r * SPAD + g * 8;
            uint32_t d = (uint32_t)r * VRS + (uint32_t)g * 16u;
            cp16(dsth + d, bh2 + off, true);
            cp16(dstl + d, bl2 + off, true);
        }
    };
    auto load_chunk = [&](int c, int bsel) {
        uint32_t base = s0 + bsel * KVBUF;
        load_qk(c * 128, DM + h * 64, base, base + KTILE);
        load_vt(c, base + 2 * KTILE, base + 2 * KTILE + VTILE);
        cpcommit();
    };

    load_qk(qt * 128, h * 64, s0 + OFF_SPH, s0 + OFF_SPH + KTILE);
    cpcommit();
    cpwait0();
    __syncthreads();
    uint32_t aQh[4][4], aQl[4][4];
#pragma unroll
    for (int ks = 0; ks < 4; ks++) {
        ldsm4(aQh[ks], s0 + OFF_SPH + a_lane + ks * 32);
        ldsm4(aQl[ks], s0 + OFF_SPH + KTILE + a_lane + ks * 32);
    }
    if (tid < 128) { mrow[tid] = -1e30f; lrow[tid] = 0.f; }
    __syncthreads();

    float o[8][4];
#pragma unroll
    for (int i = 0; i < 8; i++)
#pragma unroll
        for (int j = 0; j < 4; j++) o[i][j] = 0.f;

    load_chunk(0, 0);
    for (int c = 0; c < NCHUNK; c++) {
        if (c + 1 < NCHUNK) { load_chunk(c + 1, (c + 1) & 1); cpwait1(); }
        else                { cpwait0(); }
        __syncthreads();
        uint32_t kvb = s0 + (c & 1) * KVBUF;
        uint32_t Kh = kvb, Kl = kvb + KTILE;
        uint32_t Vh = kvb + 2 * KTILE, Vl = kvb + 2 * KTILE + VTILE;

        float s[16][4];
#pragma unroll
        for (int j = 0; j < 16; j++)
#pragma unroll
            for (int q = 0; q < 4; q++) s[j][q] = 0.f;
#pragma unroll
        for (int ks = 0; ks < 4; ks++) {
#pragma unroll
            for (int jp = 0; jp < 8; jp++) {
                uint32_t kh[4], kl[4];
                uint32_t koff = b_lane + (uint32_t)jp * (16 * ARS) + (uint32_t)ks * 32u;
                ldsm4(kh, Kh + koff);
                ldsm4(kl, Kl + koff);
#pragma unroll
                for (int hf = 0; hf < 2; hf++) {
                    int j = jp * 2 + hf;
                    mma16816(s[j], aQh[ks], &kh[hf * 2]);
                    mma16816(s[j], aQh[ks], &kl[hf * 2]);
                    mma16816(s[j], aQl[ks], &kh[hf * 2]);
                }
            }
        }

        {
            char* smp = smem;
            int r0 = wm0 + (lane >> 2);
            int c0 = 2 * (lane & 3);
#pragma unroll
            for (int j = 0; j < 16; j++) {
                int cc = j * 8 + c0;
                uint32_t loA, hiA = packsplit_hi(s[j][0], s[j][1], loA);
                uint32_t loB, hiB = packsplit_hi(s[j][2], s[j][3], loB);
                *(uint32_t*)(smp + OFF_SPH + (uint32_t)r0 * PRS2 + cc * 2) = hiA;
                *(uint32_t*)(smp + OFF_SPL + (uint32_t)r0 * PRS2 + cc * 2) = loA;
                *(uint32_t*)(smp + OFF_SPH + (uint32_t)(r0 + 8) * PRS2 + cc * 2) = hiB;
                *(uint32_t*)(smp + OFF_SPL + (uint32_t)(r0 + 8) * PRS2 + cc * 2) = loB;
            }
        }
        __syncthreads();

        const int r = tid >> 1, half = tid & 1;
        char* smp = smem;
        const uint32_t rowoff = (uint32_t)r * PRS2 + (uint32_t)half * 128u;
        const int colbase = c * 128 + half * 64;
        const int nvalid0 = NTOK - colbase;
        const int nvalid = nvalid0 < 0 ? 0 : (nvalid0 > 64 ? 64 : nvalid0);

        float chmax = -1e30f;
#pragma unroll 8
        for (int k = 0; k < 64; k += 2) {
            uint32_t hi = *(uint32_t*)(smp + OFF_SPH + rowoff + k * 2);
            uint32_t lo = *(uint32_t*)(smp + OFF_SPL + rowoff + k * 2);
            __nv_bfloat162 h2 = *reinterpret_cast<__nv_bfloat162*>(&hi);
            __nv_bfloat162 l2 = *reinterpret_cast<__nv_bfloat162*>(&lo);
            float v0 = __bfloat162float(h2.x) + __bfloat162float(l2.x);
            float v1 = __bfloat162float(h2.y) + __bfloat162float(l2.y);
            if (k < nvalid)     chmax = fmaxf(chmax, v0);
            if (k + 1 < nvalid) chmax = fmaxf(chmax, v1);
        }
        tred[tid] = chmax;
        __syncthreads();
        float m_old = mrow[r];
        float rmax = fmaxf(tred[2 * r], tred[2 * r + 1]);
        float m_new = fmaxf(m_old, rmax);
        float ca = __expf(SC * (m_old - m_new));
        __syncthreads();

        float esum = 0.f;
#pragma unroll 8
        for (int k = 0; k < 64; k += 2) {
            uint32_t hi = *(uint32_t*)(smp + OFF_SPH + rowoff + k * 2);
            uint32_t lo = *(uint32_t*)(smp + OFF_SPL + rowoff + k * 2);
            __nv_bfloat162 h2 = *reinterpret_cast<__nv_bfloat162*>(&hi);
            __nv_bfloat162 l2 = *reinterpret_cast<__nv_bfloat162*>(&lo);
            float v0 = __bfloat162float(h2.x) + __bfloat162float(l2.x);
            float v1 = __bfloat162float(h2.y) + __bfloat162float(l2.y);
            float e0 = (k < nvalid)     ? __expf(SC * (v0 - m_new)) : 0.f;
            float e1 = (k + 1 < nvalid) ? __expf(SC * (v1 - m_new)) : 0.f;
            esum += e0 + e1;
            uint32_t plo, phi = packsplit_hi(e0, e1, plo);
            *(uint32_t*)(smp + OFF_SPH + rowoff + k * 2) = phi;
            *(uint32_t*)(smp + OFF_SPL + rowoff + k * 2) = plo;
        }
        tred[tid] = esum;
        __syncthreads();
        if (half == 0) {
            lrow[r] = lrow[r] * ca + tred[2 * r] + tred[2 * r + 1];
            mrow[r] = m_new;
            crow[r] = ca;
        }
        __syncthreads();

        float caA = crow[wm0 + (lane >> 2)];
        float caB = crow[wm0 + 8 + (lane >> 2)];
#pragma unroll
        for (int nt = 0; nt < 8; nt++) {
            o[nt][0] *= caA; o[nt][1] *= caA;
            o[nt][2] *= caB; o[nt][3] *= caB;
        }

#pragma unroll
        for (int kt = 0; kt < 8; kt++) {
            uint32_t pa[4], pb[4];
            ldsm4(pa, s0 + OFF_SPH + ap_lane + (uint32_t)kt * 32u);
            ldsm4(pb, s0 + OFF_SPL + ap_lane + (uint32_t)kt * 32u);
#pragma unroll
            for (int dp = 0; dp < 4; dp++) {
                uint32_t vh[4], vl[4];
                uint32_t voff = vb_lane + (uint32_t)dp * (16 * VRS) + (uint32_t)kt * 32u;
                ldsm4(vh, Vh + voff);
                ldsm4(vl, Vl + voff);
#pragma unroll
                for (int hf = 0; hf < 2; hf++) {
                    int nt = dp * 2 + hf;
                    mma16816(o[nt], pa, &vh[hf * 2]);
                    mma16816(o[nt], pa, &vl[hf * 2]);
                    mma16816(o[nt], pb, &vh[hf * 2]);
                }
            }
        }
        __syncthreads();
    }

    float la = lrow[wm0 + (lane >> 2)];
    float lb = lrow[wm0 + 8 + (lane >> 2)];
    float ia = 1.0f / la, ib = 1.0f / lb;
    int ra = qt * 128 + wm0 + (lane >> 2);
    int rb = ra + 8;
#pragma unroll
    for (int nt = 0; nt < 8; nt++) {
        int col = h * 64 + nt * 8 + 2 * (lane & 3);
        if (ra < NTOK) {
            size_t p = (size_t)(b * NTOK + ra) * DM + col;
            *reinterpret_cast<uint32_t*>(yh + p) = packh2(o[nt][0] * ia, o[nt][1] * ia);
        }
        if (rb < NTOK) {
            size_t p = (size_t)(b * NTOK + rb) * DM + col;
            *reinterpret_cast<uint32_t*>(yh + p) = packh2(o[nt][2] * ib, o[nt][3] * ib);
        }
    }
}

// ---------------- fp16 GEMM: A single fp16, B split (BSPLIT=1) or single (0) ----------
// EPI: 0 fp32 (+bias?+res?), 1 bf16 split (+bias), 2 fp16 single gelu (+bias),
//      3 bf16 split TRANSPOSED into per-head VT layout (+bias)  [V of qkv]
static constexpr int GRS   = 144;
static constexpr int GASZ  = 64 * GRS;             // A plane 9216
static constexpr int GBSZ  = 128 * GRS;            // B plane 18432
static constexpr int TRS   = 136;                  // VT staging row stride (64 tok * 2B + 8)
static constexpr int VTSTG = 128 * TRS;            // 17408 per plane

template <int EPI, int BSPLIT>
__global__ void __launch_bounds__(256, 2)
h16_gemm(const f16* __restrict__ A, int lda,
         const f16* __restrict__ Bhi, const f16* __restrict__ Blo, int ldb,
         float* __restrict__ Cf, bf16* __restrict__ Cbh, bf16* __restrict__ Cbl,
         f16* __restrict__ Chh, int ldc,
         const float* __restrict__ bias, const float* __restrict__ res,
         int M, int N, int NC) {
    constexpr int GBUF = GASZ + (BSPLIT ? 2 : 1) * GBSZ;
    extern __shared__ __align__(16) char smem[];
    uint32_t s0 = s2u(smem);

    const int tid = threadIdx.x, lane = tid & 31, warp = tid >> 5;
    const int wm0 = (warp >> 2) * 32;
    const int wn0 = (warp & 3) * 32;
    const int row0 = blockIdx.y * 64, col0 = blockIdx.x * 128;

    float lead[2][4][4];
    uint32_t cross[2][4][2];
#pragma unroll
    for (int i = 0; i < 2; i++)
#pragma unroll
        for (int j = 0; j < 4; j++) {
#pragma unroll
            for (int k = 0; k < 4; k++) lead[i][j][k] = 0.f;
            cross[i][j][0] = 0u; cross[i][j][1] = 0u;
        }

    const uint32_t a_lane = (uint32_t)(wm0 + (lane & 15)) * GRS + (uint32_t)(lane >> 4) * 16u;
    const uint32_t b_lane = (uint32_t)(wn0 + (lane & 7) + ((lane >> 4) << 3)) * GRS +
                            (uint32_t)((lane >> 3) & 1) * 16u;

    auto load_chunk = [&](int ck, int bsel) {
        uint32_t base = s0 + bsel * GBUF;
#pragma unroll
        for (int i = 0; i < 2; i++) {
            int idx = tid + i * 256;
            int r = idx >> 3, c = idx & 7;
            int gm = row0 + r;
            bool v = gm < M;
            const f16* pa = v ? (A + (size_t)gm * lda + (size_t)ck * 64 + c * 8) : A;
            cp16(base + (uint32_t)r * GRS + (uint32_t)c * 16u, pa, v);
        }
#pragma unroll
        for (int i = 0; i < 4; i++) {
            int idx = tid + i * 256;
            int r = idx >> 3, c = idx & 7;
            int gn = col0 + r;
            bool v = gn < N;
            const f16* ph = v ? (Bhi + (size_t)gn * ldb + (size_t)ck * 64 + c * 8) : Bhi;
            uint32_t d = base + GASZ + (uint32_t)r * GRS + (uint32_t)c * 16u;
            cp16(d, ph, v);
            if (BSPLIT) {
                const f16* pl = v ? (Blo + (size_t)gn * ldb + (size_t)ck * 64 + c * 8) : Blo;
                cp16(d + GBSZ, pl, v);
            }
        }
        cpcommit();
    };

    auto compute = [&](int bsel) {
        uint32_t base = s0 + bsel * GBUF;
        uint32_t ah = base;
        uint32_t bh = base + GASZ, bl = base + GASZ + GBSZ;
#pragma unroll
        for (int ks = 0; ks < 4; ks++) {
            uint32_t af[2][4];
#pragma unroll
            for (int mt = 0; mt < 2; mt++) {
                uint32_t off = a_lane + (uint32_t)mt * (16 * GRS) + (uint32_t)ks * 32u;
                ldsm4(af[mt], ah + off);
            }
            uint32_t bfh[2][4], bfl[2][4];
#pragma unroll
            for (int np = 0; np < 2; np++) {
                uint32_t off = b_lane + (uint32_t)np * (16 * GRS) + (uint32_t)ks * 32u;
                ldsm4(bfh[np], bh + off);
                if (BSPLIT) ldsm4(bfl[np], bl + off);
            }
#pragma unroll
            for (int mt = 0; mt < 2; mt++)
#pragma unroll
                for (int nt = 0; nt < 4; nt++) {
                    const uint32_t* Bh2 = &bfh[nt >> 1][(nt & 1) * 2];
                    mma_h_f32(lead[mt][nt], af[mt], Bh2);
                    if (BSPLIT) {
                        const uint32_t* Bl2 = &bfl[nt >> 1][(nt & 1) * 2];
                        mma_h_f16(cross[mt][nt], af[mt], Bl2);
                    }
                }
        }
    };

    load_chunk(0, 0);
    for (int ck = 0; ck < NC; ck++) {
        if (ck + 1 < NC) { load_chunk(ck + 1, (ck + 1) & 1); cpwait1(); }
        else             { cpwait0(); }
        __syncthreads();
        compute(ck & 1);
        __syncthreads();
    }

    const float INV = 1.0f / 2048.0f;
#pragma unroll
    for (int mt = 0; mt < 2; mt++) {
#pragma unroll
        for (int nt = 0; nt < 4; nt++) {
            int r0 = row0 + wm0 + mt * 16 + (lane >> 2);
            int c0 = col0 + wn0 + nt * 8 + (lane & 3) * 2;
            float* a4 = lead[mt][nt];
#pragma unroll
            for (int h = 0; h < 2; h++) {
                int gm = r0 + h * 8;
                if (gm >= M) continue;
                float v0 = a4[h * 2], v1 = a4[h * 2 + 1];
                if (BSPLIT) {
                    __half2 cx = *reinterpret_cast<__half2*>(&cross[mt][nt][h]);
                    v0 += __half2float(cx.x) * INV;
                    v1 += __half2float(cx.y) * INV;
                }
                if (bias) { v0 += bias[c0]; v1 += bias[c0 + 1]; }
                if (EPI == 0) {
                    if (res) {
                        v0 += res[(size_t)gm * ldc + c0];
                        v1 += res[(size_t)gm * ldc + c0 + 1];
                    }
                    Cf[(size_t)gm * ldc + c0]     = v0;
                    Cf[(size_t)gm * ldc + c0 + 1] = v1;
                } else if (EPI == 1) {
                    uint32_t lo, hi = packsplit_hi(v0, v1, lo);
                    *reinterpret_cast<uint32_t*>(Cbh + (size_t)gm * ldc + c0) = hi;
                    *reinterpret_cast<uint32_t*>(Cbl + (size_t)gm * ldc + c0) = lo;
                } else if (EPI == 2) {
                    *reinterpret_cast<uint32_t*>(Chh + (size_t)gm * ldc + c0) =
                        packh2(geluf(v0), geluf(v1));
                } else {
                    // EPI==3: stage bf16 pair transposed (d-major)
                    bf16 h0, l0, h1, l1;
                    split2(v0, h0, l0);
                    split2(v1, h1, l1);
                    int trow = gm - row0;
                    int dl = c0 - col0;
                    *(bf16*)(smem + (uint32_t)dl * TRS + (uint32_t)trow * 2) = h0;
                    *(bf16*)(smem + (uint32_t)(dl + 1) * TRS + (uint32_t)trow * 2) = h1;
                    *(bf16*)(smem + VTSTG + (uint32_t)dl * TRS + (uint32_t)trow * 2) = l0;
                    *(bf16*)(smem + VTSTG + (uint32_t)(dl + 1) * TRS + (uint32_t)trow * 2) = l1;
                }
            }
        }
    }

    if (EPI == 3) {
        // coalesced VT writes: warp w covers d = w + 8*it, lanes along tokens
        __syncthreads();
#pragma unroll 1
        for (int it = 0; it < 16; it++) {
            int dl = warp + it * 8;            // 0..127
            int gcol = col0 + dl;              // global V dim 0..767
            int hh = gcol >> 6, dh = gcol & 63;
#pragma unroll
            for (int pass = 0; pass < 2; pass++) {
                int trow = pass * 32 + lane;
                int gm = row0 + trow;
                if (gm < M) {
                    int b = gm / NTOK, t = gm % NTOK;
                    size_t dst = ((size_t)(b * HEADS + hh) * 64 + dh) * SPAD + t;
                    Cbh[dst] = *(bf16*)(smem + (uint32_t)dl * TRS + (uint32_t)trow * 2);
                    Cbl[dst] = *(bf16*)(smem + VTSTG + (uint32_t)dl * TRS + (uint32_t)trow * 2);
                }
            }
        }
    }
}

template <int EPI, int BSPLIT>
static void hgemm(const f16* A, int lda,
                  const f16* Bh, const f16* Bl, int ldb,
                  float* Cf, bf16* Cbh, bf16* Cbl, f16* Chh, int ldc,
                  const float* bias, const float* res, int M, int N, int K) {
    constexpr int GBUF = GASZ + (BSPLIT ? 2 : 1) * GBSZ;
    int smem = 2 * GBUF;
    cudaFuncSetAttribute(h16_gemm<EPI, BSPLIT>, cudaFuncAttributeMaxDynamicSharedMemorySize, smem);
    dim3 grid(N / 128, (M + 63) / 64, 1);
    h16_gemm<EPI, BSPLIT><<<grid, 256, smem>>>(A, lda, Bh, Bl, ldb, Cf, Cbh, Cbl, Chh,
                                               ldc, bias, res, M, N, K / 64);
}

extern "C" void kernel_launch(void* const* d_in, const int* in_sizes, int n_in,
                              void* d_out, int out_size) {
    const float* x       = (const float*)d_in[0];
    const float* conv_w  = (const float*)d_in[1];
    const float* conv_b  = (const float*)d_in[2];
    const float* cls_tok = (const float*)d_in[3];
    const float* pos_emb = (const float*)d_in[4];
    const float* ln1_g   = (const float*)d_in[5];
    const float* ln1_b   = (const float*)d_in[6];
    const float* qkv_w   = (const float*)d_in[7];
    const float* qkv_b   = (const float*)d_in[8];
    const float* proj_w  = (const float*)d_in[9];
    const float* proj_b  = (const float*)d_in[10];
    const float* ln2_g   = (const float*)d_in[11];
    const float* ln2_b   = (const float*)d_in[12];
    const float* mlp_w1  = (const float*)d_in[13];
    const float* mlp_b1  = (const float*)d_in[14];
    const float* mlp_w2  = (const float*)d_in[15];
    const float* mlp_b2  = (const float*)d_in[16];
    const float* lnf_g   = (const float*)d_in[17];
    const float* lnf_b   = (const float*)d_in[18];
    float* out = (float*)d_out;

    f16 *wh, *wl, *cwh, *cwl, *pxh, *xh, *ahp, *mh;
    float *ph, *ptmp;
    bf16 *qhi, *qlo, *vthi, *vtlo;
    cudaGetSymbolAddress((void**)&wh, g_wh);
    cudaGetSymbolAddress((void**)&wl, g_wl);
    cudaGetSymbolAddress((void**)&cwh, g_cwh);
    cudaGetSymbolAddress((void**)&cwl, g_cwl);
    cudaGetSymbolAddress((void**)&pxh, g_pxh);
    cudaGetSymbolAddress((void**)&xh, g_xh);
    cudaGetSymbolAddress((void**)&ahp, g_ah);
    cudaGetSymbolAddress((void**)&mh, g_mh);
    cudaGetSymbolAddress((void**)&ph, g_h);
    cudaGetSymbolAddress((void**)&ptmp, g_ptmp);
    cudaGetSymbolAddress((void**)&qhi, g_qhi);
    cudaGetSymbolAddress((void**)&qlo, g_qlo);
    cudaGetSymbolAddress((void**)&vthi, g_vthi);
    cudaGetSymbolAddress((void**)&vtlo, g_vtlo);

    dim3 tb(32, 8);

    // ---- weight prep: batched over layers (grid.z) ----
    split_h<<<(DM * DM + 255) / 256, 256>>>(conv_w, cwh, cwl, DM * DM);
    wt_trans_hB<<<dim3(2304 / 32, 768 / 32, LAYERS), tb>>>(
        qkv_w, wh, wl, DM, 3 * DM, (long long)DM * 3 * DM, LW);
    wt_trans_hB<<<dim3(768 / 32, 768 / 32, LAYERS), tb>>>(
        proj_w, wh + 1769472, wl + 1769472, DM, DM, (long long)DM * DM, LW);
    wt_trans_h1B<<<dim3(3072 / 32, 768 / 32, LAYERS), tb>>>(
        mlp_w1, wh + 2359296, DM, 4 * DM, (long long)DM * 4 * DM, LW);
    wt_trans_h1B<<<dim3(768 / 32, 3072 / 32, LAYERS), tb>>>(
        mlp_w2, wh + 4718592, 4 * DM, DM, (long long)4 * DM * DM, LW);

    // ---- patch embed ----
    im2col_h<<<(MPATCH * DM + 255) / 256, 256>>>(x, pxh);
    hgemm<0, 1>(pxh, DM, cwh, cwl, DM, ptmp, nullptr, nullptr, nullptr, DM,
                conv_b, nullptr, MPATCH, DM, DM);
    assemble_kernel<<<(MTOK * DM + 255) / 256, 256>>>(ptmp, cls_tok, pos_emb, ph);

    cudaFuncSetAttribute(fused_attn, cudaFuncAttributeMaxDynamicSharedMemorySize, FA_SMEM);

    for (int l = 0; l < LAYERS; l++) {
        long long wo = (long long)l * LW;
        const f16* qwT_h = wh + wo;            const f16* qwT_l = wl + wo;
        const f16* pwT_h = wh + wo + 1769472;  const f16* pwT_l = wl + wo + 1769472;
        const f16* w1T_h = wh + wo + 2359296;
        const f16* w2T_h = wh + wo + 4718592;
        const float* l1g = ln1_g + (size_t)l * DM;
        const float* l1b = ln1_b + (size_t)l * DM;
        const float* qb  = qkv_b + (size_t)l * 3 * DM;
        const float* pb  = proj_b + (size_t)l * DM;
        const float* l2g = ln2_g + (size_t)l * DM;
        const float* l2b = ln2_b + (size_t)l * DM;
        const float* b1  = mlp_b1 + (size_t)l * 4 * DM;
        const float* b2  = mlp_b2 + (size_t)l * DM;

        // LN1 -> single fp16
        ln_h<<<MTOK, 256>>>(ph, l1g, l1b, xh);
        // QK -> bf16 pair (first 1536 cols of qkv)
        hgemm<1, 1>(xh, DM, qwT_h, qwT_l, DM, nullptr, qhi, qlo, nullptr, 3 * DM,
                    qb, nullptr, MTOK, 2 * DM, DM);
        // V -> transposed VT bf16 pair directly (cols 1536..2304)
        hgemm<3, 1>(xh, DM, qwT_h + (size_t)2 * DM * DM, qwT_l + (size_t)2 * DM * DM, DM,
                    nullptr, vthi, vtlo, nullptr, SPAD,
                    qb + 2 * DM, nullptr, MTOK, DM, DM);
        // fused attention -> single fp16
        fused_attn<<<dim3(NCHUNK, BATCH * HEADS), 256, FA_SMEM>>>(qhi, qlo, vthi, vtlo, ahp);
        // proj + bias + residual -> h; weights split
        hgemm<0, 1>(ahp, DM, pwT_h, pwT_l, DM, ph, nullptr, nullptr, nullptr, DM,
                    pb, ph, MTOK, DM, DM);
        // LN2 -> single fp16
        ln_h<<<MTOK, 256>>>(ph, l2g, l2b, xh);
        // MLP1 + gelu -> single fp16; single-plane weights
        hgemm<2, 0>(xh, DM, w1T_h, nullptr, DM, nullptr, nullptr, nullptr, mh, 4 * DM,
                    b1, nullptr, MTOK, 4 * DM, DM);
        // MLP2 + bias + residual -> h; single-plane weights
        hgemm<0, 0>(mh, 4 * DM, w2T_h, nullptr, 4 * DM, ph, nullptr, nullptr, nullptr, DM,
                    b2, ph, MTOK, DM, 4 * DM);
    }

    // final LN on CLS rows -> out [8,768]
    ln_kernel<<<BATCH, 256>>>(ph, lnf_g, lnf_b, out, (long long)NTOK * DM, DM);
}

// round 15
// speedup vs baseline: 3.7679x; 1.0342x over previous
#include <cuda_runtime.h>
#include <cuda_bf16.h>
#include <cuda_fp16.h>
#include <math.h>
#include <stdint.h>

using bf16 = __nv_bfloat16;
using f16 = __half;

template <int N> struct ic { static constexpr int v = N; };

// ---------------- problem constants ----------------
static constexpr int BATCH  = 8;
static constexpr int DM     = 768;
static constexpr int HEADS  = 12;
static constexpr int LAYERS = 12;
static constexpr int NTOK   = 785;
static constexpr int NPATCH = 784;
static constexpr int MTOK   = BATCH * NTOK;    // 6280
static constexpr int MPATCH = BATCH * NPATCH;  // 6272
static constexpr int IMG    = 448;
static constexpr int PSZ    = 16;
static constexpr int GRID28 = 28;
static constexpr int SPAD   = 896;
static constexpr long long LW = 7077888LL;

// ---------------- device scratch ----------------
__device__ f16  g_wh[(size_t)LAYERS * LW];     // weights hi
__device__ f16  g_wl[(size_t)LAYERS * LW];     // weights lo (qkv/proj use; mlp ignores)
__device__ f16  g_cwh[DM * DM];
__device__ f16  g_cwl[DM * DM];
__device__ f16  g_pxh[(size_t)MPATCH * DM];
__device__ f16  g_xh[(size_t)MTOK * DM];
__device__ f16  g_ah[(size_t)MTOK * DM];
__device__ f16  g_mh[(size_t)MTOK * 4 * DM];
__device__ float g_h[(size_t)MTOK * DM];
__device__ float g_ptmp[(size_t)MPATCH * DM];
__device__ bf16  g_qhi[(size_t)MTOK * 3 * DM];
__device__ bf16  g_qlo[(size_t)MTOK * 3 * DM];
__device__ bf16  g_vthi[(size_t)BATCH * HEADS * 64 * SPAD];  // zero-init; tail stays 0
__device__ bf16  g_vtlo[(size_t)BATCH * HEADS * 64 * SPAD];

// ---------------- small helpers ----------------
__device__ __forceinline__ void split2(float v, bf16& h, bf16& l) {
    h = __float2bfloat16(v);
    l = __float2bfloat16(v - __bfloat162float(h));
}
__device__ __forceinline__ float geluf(float v) {
    return 0.5f * v * (1.0f + erff(v * 0.70710678118654752f));
}
__device__ __forceinline__ float warpSum(float v) {
#pragma unroll
    for (int o = 16; o > 0; o >>= 1) v += __shfl_xor_sync(0xffffffffu, v, o);
    return v;
}
__device__ __forceinline__ float blockSum256(float v, float* sh) {
    int lane = threadIdx.x & 31, w = threadIdx.x >> 5;
    v = warpSum(v);
    if (lane == 0) sh[w] = v;
    __syncthreads();
    float r = (threadIdx.x < 8) ? sh[threadIdx.x] : 0.f;
    if (w == 0) { r = warpSum(r); if (lane == 0) sh[0] = r; }
    __syncthreads();
    r = sh[0];
    __syncthreads();
    return r;
}

// ---------------- PTX wrappers ----------------
__device__ __forceinline__ uint32_t s2u(const void* p) {
    uint32_t a;
    asm("{ .reg .u64 t; cvta.to.shared.u64 t, %1; cvt.u32.u64 %0, t; }" : "=r"(a) : "l"(p));
    return a;
}
__device__ __forceinline__ void cp16(uint32_t d, const void* s, bool pred) {
    int sz = pred ? 16 : 0;
    asm volatile("cp.async.cg.shared.global [%0], [%1], 16, %2;" :: "r"(d), "l"(s), "r"(sz));
}
__device__ __forceinline__ void cpcommit() { asm volatile("cp.async.commit_group;" ::: "memory"); }
__device__ __forceinline__ void cpwait0()  { asm volatile("cp.async.wait_group 0;" ::: "memory"); }
__device__ __forceinline__ void cpwait1()  { asm volatile("cp.async.wait_group 1;" ::: "memory"); }
__device__ __forceinline__ void ldsm4(uint32_t* r, uint32_t addr) {
    asm volatile("ldmatrix.sync.aligned.m8n8.x4.shared.b16 {%0,%1,%2,%3}, [%4];"
                 : "=r"(r[0]), "=r"(r[1]), "=r"(r[2]), "=r"(r[3]) : "r"(addr));
}
// bf16 operands, f32 acc (validated; attention only)
__device__ __forceinline__ void mma16816(float* c, const uint32_t* a, const uint32_t* b) {
    asm volatile(
        "mma.sync.aligned.m16n8k16.row.col.f32.bf16.bf16.f32 "
        "{%0,%1,%2,%3}, {%4,%5,%6,%7}, {%8,%9}, {%0,%1,%2,%3};"
        : "+f"(c[0]), "+f"(c[1]), "+f"(c[2]), "+f"(c[3])
        : "r"(a[0]), "r"(a[1]), "r"(a[2]), "r"(a[3]), "r"(b[0]), "r"(b[1]));
}
// f16 operands, f32 acc (lead term)
__device__ __forceinline__ void mma_h_f32(float* c, const uint32_t* a, const uint32_t* b) {
    asm volatile(
        "mma.sync.aligned.m16n8k16.row.col.f32.f16.f16.f32 "
        "{%0,%1,%2,%3}, {%4,%5,%6,%7}, {%8,%9}, {%0,%1,%2,%3};"
        : "+f"(c[0]), "+f"(c[1]), "+f"(c[2]), "+f"(c[3])
        : "r"(a[0]), "r"(a[1]), "r"(a[2]), "r"(a[3]), "r"(b[0]), "r"(b[1]));
}
// f16 operands, f16 acc (cross term; 2 C regs)
__device__ __forceinline__ void mma_h_f16(uint32_t* c, const uint32_t* a, const uint32_t* b) {
    asm volatile(
        "mma.sync.aligned.m16n8k16.row.col.f16.f16.f16.f16 "
        "{%0,%1}, {%2,%3,%4,%5}, {%6,%7}, {%0,%1};"
        : "+r"(c[0]), "+r"(c[1])
        : "r"(a[0]), "r"(a[1]), "r"(a[2]), "r"(a[3]), "r"(b[0]), "r"(b[1]));
}
// bf16 split pack (attention internals; validated)
__device__ __forceinline__ uint32_t packsplit_hi(float a, float b, uint32_t& lo) {
    bf16 ah, al, bh, bl;
    split2(a, ah, al);
    split2(b, bh, bl);
    __nv_bfloat162 h2; h2.x = ah; h2.y = bh;
    __nv_bfloat162 l2; l2.x = al; l2.y = bl;
    lo = *reinterpret_cast<uint32_t*>(&l2);
    return *reinterpret_cast<uint32_t*>(&h2);
}
__device__ __forceinline__ uint32_t packh2(float a, float b) {
    __half2 h2 = __halves2half2(__float2half(a), __float2half(b));
    return *reinterpret_cast<uint32_t*>(&h2);
}
__device__ __forceinline__ void splith(float v, f16& h, f16& l) {
    h = __float2half(v);
    l = __float2half((v - __half2float(h)) * 2048.f);
}

// ---------------- elementwise / prep kernels ----------------
__global__ void im2col_h(const float* __restrict__ x, f16* __restrict__ Ph) {
    int idx = blockIdx.x * blockDim.x + threadIdx.x;
    if (idx >= MPATCH * DM) return;
    int k = idx % DM, m = idx / DM;
    int b = m / NPATCH, t = m % NPATCH;
    int py = t / GRID28, px = t % GRID28;
    int c = k >> 8, rem = k & 255, i = rem >> 4, j = rem & 15;
    size_t src = (((size_t)(b * 3 + c) * IMG) + (size_t)(py * PSZ + i)) * IMG + (px * PSZ + j);
    Ph[idx] = __float2half(x[src]);
}

__global__ void split_h(const float* __restrict__ W, f16* __restrict__ Oh,
                        f16* __restrict__ Ol, int n) {
    int idx = blockIdx.x * blockDim.x + threadIdx.x;
    if (idx >= n) return;
    f16 h, l;
    splith(W[idx], h, l);
    Oh[idx] = h; Ol[idx] = l;
}

// batched over layers (blockIdx.z): W[K,N] -> out[n*K + k], fp16 split
__global__ void wt_trans_hB(const float* __restrict__ W0, f16* __restrict__ Oh0,
                            f16* __restrict__ Ol0, int K, int N,
                            long long sIn, long long sOut) {
    const float* W = W0 + (long long)blockIdx.z * sIn;
    f16* Oh = Oh0 + (long long)blockIdx.z * sOut;
    f16* Ol = Ol0 + (long long)blockIdx.z * sOut;
    __shared__ float tile[32][33];
    int kb = blockIdx.y * 32, nb = blockIdx.x * 32;
    int tx = threadIdx.x, ty = threadIdx.y;  // 32 x 8
#pragma unroll
    for (int i = 0; i < 32; i += 8) {
        int k = kb + ty + i, n = nb + tx;
        tile[ty + i][tx] = (k < K && n < N) ? W[(size_t)k * N + n] : 0.f;
    }
    __syncthreads();
#pragma unroll
    for (int i = 0; i < 32; i += 8) {
        int n = nb + ty + i, k = kb + tx;
        if (n < N && k < K) {
            f16 h, l;
            splith(tile[tx][ty + i], h, l);
            Oh[(size_t)n * K + k] = h;
            Ol[(size_t)n * K + k] = l;
        }
    }
}

// batched, single fp16 out (MLP weights)
__global__ void wt_trans_h1B(const float* __restrict__ W0, f16* __restrict__ Oh0,
                             int K, int N, long long sIn, long long sOut) {
    const float* W = W0 + (long long)blockIdx.z * sIn;
    f16* Oh = Oh0 + (long long)blockIdx.z * sOut;
    __shared__ float tile[32][33];
    int kb = blockIdx.y * 32, nb = blockIdx.x * 32;
    int tx = threadIdx.x, ty = threadIdx.y;
#pragma unroll
    for (int i = 0; i < 32; i += 8) {
        int k = kb + ty + i, n = nb + tx;
        tile[ty + i][tx] = (k < K && n < N) ? W[(size_t)k * N + n] : 0.f;
    }
    __syncthreads();
#pragma unroll
    for (int i = 0; i < 32; i += 8) {
        int n = nb + ty + i, k = kb + tx;
        if (n < N && k < K)
            Oh[(size_t)n * K + k] = __float2half(tile[tx][ty + i]);
    }
}

__global__ void assemble_kernel(const float* __restrict__ tok, const float* __restrict__ cls,
                                const float* __restrict__ pos, float* __restrict__ H) {
    int idx = blockIdx.x * blockDim.x + threadIdx.x;
    if (idx >= MTOK * DM) return;
    int d = idx % DM;
    int r = idx / DM;
    int n = r % NTOK, b = r / NTOK;
    float v;
    if (n == 0) v = cls[d] + pos[d];
    else        v = tok[((size_t)b * NPATCH + (n - 1)) * DM + d] + pos[(size_t)n * DM + d];
    H[idx] = v;
}

__global__ void ln_kernel(const float* __restrict__ X, const float* __restrict__ g,
                          const float* __restrict__ bb, float* __restrict__ Y,
                          long long inStride, long long outStride) {
    const float* x = X + (long long)blockIdx.x * inStride;
    float* y = Y + (long long)blockIdx.x * outStride;
    int t = threadIdx.x;
    __shared__ float sh[8];
    float v0 = x[t], v1 = x[t + 256], v2 = x[t + 512];
    float mu = blockSum256(v0 + v1 + v2, sh) * (1.0f / 768.0f);
    float d0 = v0 - mu, d1 = v1 - mu, d2 = v2 - mu;
    float var = blockSum256(d0 * d0 + d1 * d1 + d2 * d2, sh) * (1.0f / 768.0f);
    float rs = rsqrtf(var + 1e-5f);
    y[t]       = d0 * rs * g[t]       + bb[t];
    y[t + 256] = d1 * rs * g[t + 256] + bb[t + 256];
    y[t + 512] = d2 * rs * g[t + 512] + bb[t + 512];
}

// LN -> single fp16
__global__ void ln_h(const float* __restrict__ X, const float* __restrict__ g,
                     const float* __restrict__ bb, f16* __restrict__ Yh) {
    const float* x = X + (size_t)blockIdx.x * DM;
    f16* yh = Yh + (size_t)blockIdx.x * DM;
    int t = threadIdx.x;
    __shared__ float sh[8];
    float v0 = x[t], v1 = x[t + 256], v2 = x[t + 512];
    float mu = blockSum256(v0 + v1 + v2, sh) * (1.0f / 768.0f);
    float d0 = v0 - mu, d1 = v1 - mu, d2 = v2 - mu;
    float var = blockSum256(d0 * d0 + d1 * d1 + d2 * d2, sh) * (1.0f / 768.0f);
    float rs = rsqrtf(var + 1e-5f);
    yh[t]       = __float2half(d0 * rs * g[t]       + bb[t]);
    yh[t + 256] = __float2half(d1 * rs * g[t + 256] + bb[t + 256]);
    yh[t + 512] = __float2half(d2 * rs * g[t + 512] + bb[t + 512]);
}

// ---------------- fused flash attention (v5: fast full-chunk softmax) ----------------
static constexpr int ARS    = 144;
static constexpr int KTILE  = 128 * ARS;
static constexpr int VRS    = 272;
static constexpr int VTILE  = 64 * VRS;
static constexpr int KVBUF  = 2 * KTILE + 2 * VTILE;
static constexpr int PRS2   = 272;
static constexpr int SPTILE = 128 * PRS2;
static constexpr int OFF_SPH = 2 * KVBUF;
static constexpr int OFF_SPL = OFF_SPH + SPTILE;
static constexpr int OFF_M  = OFF_SPL + SPTILE;
static constexpr int OFF_L  = OFF_M + 512;
static constexpr int OFF_CA = OFF_L + 512;
static constexpr int OFF_T  = OFF_CA + 512;
static constexpr int OFF_RM = OFF_T + 1024;
static constexpr int FA_SMEM = OFF_RM + 512;
static constexpr int NCHUNK = 7;

__global__ void __launch_bounds__(256, 1)
fused_attn(const bf16* __restrict__ qkvh, const bf16* __restrict__ qkvl,
           const bf16* __restrict__ vth, const bf16* __restrict__ vtl,
           f16* __restrict__ yh) {
    extern __shared__ __align__(16) char smem[];
    uint32_t s0 = s2u(smem);
    const int tid = threadIdx.x, lane = tid & 31, warp = tid >> 5;
    const int qt = blockIdx.x;
    const int z = blockIdx.y;
    const int b = z / HEADS, h = z % HEADS;
    const float SC = 0.125f;

    const int wm0 = warp * 16;
    const uint32_t a_lane  = (uint32_t)(wm0 + (lane & 15)) * ARS + (uint32_t)(lane >> 4) * 16u;
    const uint32_t b_lane  = (uint32_t)((lane & 7) + ((lane >> 4) << 3)) * ARS +
                             (uint32_t)((lane >> 3) & 1) * 16u;
    const uint32_t vb_lane = (uint32_t)((lane & 7) + ((lane >> 4) << 3)) * VRS +
                             (uint32_t)((lane >> 3) & 1) * 16u;
    const uint32_t ap_lane = (uint32_t)(wm0 + (lane & 15)) * PRS2 + (uint32_t)(lane >> 4) * 16u;

    float* mrow = reinterpret_cast<float*>(smem + OFF_M);
    float* lrow = reinterpret_cast<float*>(smem + OFF_L);
    float* crow = reinterpret_cast<float*>(smem + OFF_CA);
    float* tred = reinterpret_cast<float*>(smem + OFF_T);
    float* rmax = reinterpret_cast<float*>(smem + OFF_RM);

    auto load_qk = [&](int rowbase, int colbase, uint32_t dsth, uint32_t dstl) {
#pragma unroll
        for (int i = 0; i < 4; i++) {
            int idx = tid + i * 256;
            int r = idx >> 3, g = idx & 7;
            bool v = (rowbase + r) < NTOK;
            size_t off = ((size_t)(b * NTOK + rowbase + r)) * (3 * DM) + colbase + g * 8;
            const bf16* sh2 = v ? (qkvh + off) : qkvh;
            const bf16* sl2 = v ? (qkvl + off) : qkvl;
            uint32_t d = (uint32_t)r * ARS + (uint32_t)g * 16u;
            cp16(dsth + d, sh2, v);
            cp16(dstl + d, sl2, v);
        }
    };
    auto load_vt = [&](int c, uint32_t dsth, uint32_t dstl) {
        const bf16* bh2 = vth + (size_t)z * 64 * SPAD + (size_t)c * 128;
        const bf16* bl2 = vtl + (size_t)z * 64 * SPAD + (size_t)c * 128;
#pragma unroll
        for (int i = 0; i < 4; i++) {
            int idx = tid + i * 256;
            int r = idx >> 4, g = idx & 15;
            size_t off = (size_t)r * SPAD + g * 8;
            uint32_t d = (uint32_t)r * VRS + (uint32_t)g * 16u;
            cp16(dsth + d, bh2 + off, true);
            cp16(dstl + d, bl2 + off, true);
        }
    };
    auto load_chunk = [&](int c, int bsel) {
        uint32_t base = s0 + bsel * KVBUF;
        load_qk(c * 128, DM + h * 64, base, base + KTILE);
        load_vt(c, base + 2 * KTILE, base + 2 * KTILE + VTILE);
        cpcommit();
    };

    load_qk(qt * 128, h * 64, s0 + OFF_SPH, s0 + OFF_SPH + KTILE);
    cpcommit();
    cpwait0();
    __syncthreads();
    uint32_t aQh[4][4], aQl[4][4];
#pragma unroll
    for (int ks = 0; ks < 4; ks++) {
        ldsm4(aQh[ks], s0 + OFF_SPH + a_lane + ks * 32);
        ldsm4(aQl[ks], s0 + OFF_SPH + KTILE + a_lane + ks * 32);
    }
    if (tid < 128) { mrow[tid] = -1e30f; lrow[tid] = 0.f; }
    __syncthreads();

    float o[8][4];
#pragma unroll
    for (int i = 0; i < 8; i++)
#pragma unroll
        for (int j = 0; j < 4; j++) o[i][j] = 0.f;

    load_chunk(0, 0);
    for (int c = 0; c < NCHUNK; c++) {
        const bool full = (c < NCHUNK - 1);
        if (c + 1 < NCHUNK) { load_chunk(c + 1, (c + 1) & 1); cpwait1(); }
        else                { cpwait0(); }
        __syncthreads();
        uint32_t kvb = s0 + (c & 1) * KVBUF;
        uint32_t Kh = kvb, Kl = kvb + KTILE;
        uint32_t Vh = kvb + 2 * KTILE, Vl = kvb + 2 * KTILE + VTILE;

        // ---- S = Q K^T (3-term split); last chunk only 32 key cols ----
        float s[16][4];
#pragma unroll
        for (int j = 0; j < 16; j++)
#pragma unroll
            for (int q = 0; q < 4; q++) s[j][q] = 0.f;

        auto smma = [&](auto JPC) {
            constexpr int JP = decltype(JPC)::v;
#pragma unroll
            for (int ks = 0; ks < 4; ks++) {
#pragma unroll
                for (int jp = 0; jp < JP; jp++) {
                    uint32_t kh[4], kl[4];
                    uint32_t koff = b_lane + (uint32_t)jp * (16 * ARS) + (uint32_t)ks * 32u;
                    ldsm4(kh, Kh + koff);
                    ldsm4(kl, Kl + koff);
#pragma unroll
                    for (int hf = 0; hf < 2; hf++) {
                        int j = jp * 2 + hf;
                        mma16816(s[j], aQh[ks], &kh[hf * 2]);
                        mma16816(s[j], aQh[ks], &kl[hf * 2]);
                        mma16816(s[j], aQl[ks], &kh[hf * 2]);
                    }
                }
            }
        };
        if (full) smma(ic<8>{}); else smma(ic<2>{});

        // ---- stage S as split bf16 (validated store coords) ----
        {
            char* smp = smem;
            int r0 = wm0 + (lane >> 2);
            int c0 = 2 * (lane & 3);
            auto stage = [&](auto JTC) {
                constexpr int JT = decltype(JTC)::v;
#pragma unroll
                for (int j = 0; j < JT; j++) {
                    int cc = j * 8 + c0;
                    uint32_t loA, hiA = packsplit_hi(s[j][0], s[j][1], loA);
                    uint32_t loB, hiB = packsplit_hi(s[j][2], s[j][3], loB);
                    *(uint32_t*)(smp + OFF_SPH + (uint32_t)r0 * PRS2 + cc * 2) = hiA;
                    *(uint32_t*)(smp + OFF_SPL + (uint32_t)r0 * PRS2 + cc * 2) = loA;
                    *(uint32_t*)(smp + OFF_SPH + (uint32_t)(r0 + 8) * PRS2 + cc * 2) = hiB;
                    *(uint32_t*)(smp + OFF_SPL + (uint32_t)(r0 + 8) * PRS2 + cc * 2) = loB;
                }
            };
            if (full) stage(ic<16>{}); else stage(ic<4>{});
        }

        if (full) {
            // ---- fragment chunk-max (all 128 cols valid) ----
            float mxa = -1e30f, mxb = -1e30f;
#pragma unroll
            for (int j = 0; j < 16; j++) {
                mxa = fmaxf(mxa, fmaxf(s[j][0], s[j][1]));
                mxb = fmaxf(mxb, fmaxf(s[j][2], s[j][3]));
            }
#pragma unroll
            for (int off = 1; off <= 2; off <<= 1) {
                mxa = fmaxf(mxa, __shfl_xor_sync(0xffffffffu, mxa, off));
                mxb = fmaxf(mxb, __shfl_xor_sync(0xffffffffu, mxb, off));
            }
            if ((lane & 3) == 0) {
                rmax[wm0 + (lane >> 2)] = mxa;
                rmax[wm0 + 8 + (lane >> 2)] = mxb;
            }
            __syncthreads();  // S staged + rmax ready

            const int r = tid >> 1, half = tid & 1;
            char* smp = smem;
            const uint32_t rowoff = (uint32_t)r * PRS2 + (uint32_t)half * 128u;
            float m_old = mrow[r];
            float m_new = fmaxf(m_old, rmax[r]);
            float ca = __expf(SC * (m_old - m_new));

            float esum = 0.f;
#pragma unroll 8
            for (int k = 0; k < 64; k += 2) {
                uint32_t hi = *(uint32_t*)(smp + OFF_SPH + rowoff + k * 2);
                uint32_t lo = *(uint32_t*)(smp + OFF_SPL + rowoff + k * 2);
                __nv_bfloat162 h2 = *reinterpret_cast<__nv_bfloat162*>(&hi);
                __nv_bfloat162 l2 = *reinterpret_cast<__nv_bfloat162*>(&lo);
                float v0 = __bfloat162float(h2.x) + __bfloat162float(l2.x);
                float v1 = __bfloat162float(h2.y) + __bfloat162float(l2.y);
                float e0 = __expf(SC * (v0 - m_new));
                float e1 = __expf(SC * (v1 - m_new));
                esum += e0 + e1;
                uint32_t plo, phi = packsplit_hi(e0, e1, plo);
                *(uint32_t*)(smp + OFF_SPH + rowoff + k * 2) = phi;
                *(uint32_t*)(smp + OFF_SPL + rowoff + k * 2) = plo;
            }
            tred[tid] = esum;
            __syncthreads();
            if (half == 0) {
                lrow[r] = lrow[r] * ca + tred[2 * r] + tred[2 * r + 1];
                mrow[r] = m_new;
                crow[r] = ca;
            }
            __syncthreads();
        } else {
            // ---- last chunk: validated masked linear path ----
            __syncthreads();
            const int r = tid >> 1, half = tid & 1;
            char* smp = smem;
            const uint32_t rowoff = (uint32_t)r * PRS2 + (uint32_t)half * 128u;
            const int colbase = c * 128 + half * 64;
            const int nvalid0 = NTOK - colbase;
            const int nvalid = nvalid0 < 0 ? 0 : (nvalid0 > 64 ? 64 : nvalid0);

            float chmax = -1e30f;
#pragma unroll 8
            for (int k = 0; k < 64; k += 2) {
                uint32_t hi = *(uint32_t*)(smp + OFF_SPH + rowoff + k * 2);
                uint32_t lo = *(uint32_t*)(smp + OFF_SPL + rowoff + k * 2);
                __nv_bfloat162 h2 = *reinterpret_cast<__nv_bfloat162*>(&hi);
                __nv_bfloat162 l2 = *reinterpret_cast<__nv_bfloat162*>(&lo);
                float v0 = __bfloat162float(h2.x) + __bfloat162float(l2.x);
                float v1 = __bfloat162float(h2.y) + __bfloat162float(l2.y);
                if (k < nvalid)     chmax = fmaxf(chmax, v0);
                if (k + 1 < nvalid) chmax = fmaxf(chmax, v1);
            }
            tred[tid] = chmax;
            __syncthreads();
            float m_old = mrow[r];
            float rm = fmaxf(tred[2 * r], tred[2 * r + 1]);
            float m_new = fmaxf(m_old, rm);
            float ca = __expf(SC * (m_old - m_new));
            __syncthreads();

            float esum = 0.f;
#pragma unroll 8
            for (int k = 0; k < 64; k += 2) {
                uint32_t hi = *(uint32_t*)(smp + OFF_SPH + rowoff + k * 2);
                uint32_t lo = *(uint32_t*)(smp + OFF_SPL + rowoff + k * 2);
                __nv_bfloat162 h2 = *reinterpret_cast<__nv_bfloat162*>(&hi);
                __nv_bfloat162 l2 = *reinterpret_cast<__nv_bfloat162*>(&lo);
                float v0 = __bfloat162float(h2.x) + __bfloat162float(l2.x);
                float v1 = __bfloat162float(h2.y) + __bfloat162float(l2.y);
                float e0 = (k < nvalid)     ? __expf(SC * (v0 - m_new)) : 0.f;
                float e1 = (k + 1 < nvalid) ? __expf(SC * (v1 - m_new)) : 0.f;
                esum += e0 + e1;
                uint32_t plo, phi = packsplit_hi(e0, e1, plo);
                *(uint32_t*)(smp + OFF_SPH + rowoff + k * 2) = phi;
                *(uint32_t*)(smp + OFF_SPL + rowoff + k * 2) = plo;
            }
            tred[tid] = esum;
            __syncthreads();
            if (half == 0) {
                lrow[r] = lrow[r] * ca + tred[2 * r] + tred[2 * r + 1];
                mrow[r] = m_new;
                crow[r] = ca;
            }
            __syncthreads();
        }

        // ---- o rescale by this chunk's per-row ca ----
        float caA = crow[wm0 + (lane >> 2)];
        float caB = crow[wm0 + 8 + (lane >> 2)];
#pragma unroll
        for (int nt = 0; nt < 8; nt++) {
            o[nt][0] *= caA; o[nt][1] *= caA;
            o[nt][2] *= caB; o[nt][3] *= caB;
        }

        // ---- O += P V ; last chunk only kt 0..1 (rest of P is zero) ----
        auto pv = [&](auto KTC) {
            constexpr int KT = decltype(KTC)::v;
#pragma unroll
            for (int kt = 0; kt < KT; kt++) {
                uint32_t pa[4], pb[4];
                ldsm4(pa, s0 + OFF_SPH + ap_lane + (uint32_t)kt * 32u);
                ldsm4(pb, s0 + OFF_SPL + ap_lane + (uint32_t)kt * 32u);
#pragma unroll
                for (int dp = 0; dp < 4; dp++) {
                    uint32_t vh[4], vl[4];
                    uint32_t voff = vb_lane + (uint32_t)dp * (16 * VRS) + (uint32_t)kt * 32u;
                    ldsm4(vh, Vh + voff);
                    ldsm4(vl, Vl + voff);
#pragma unroll
                    for (int hf = 0; hf < 2; hf++) {
                        int nt = dp * 2 + hf;
                        mma16816(o[nt], pa, &vh[hf * 2]);
                        mma16816(o[nt], pa, &vl[hf * 2]);
                        mma16816(o[nt], pb, &vh[hf * 2]);
                    }
                }
            }
        };
        if (full) pv(ic<8>{}); else pv(ic<2>{});
        __syncthreads();
    }

    float la = lrow[wm0 + (lane >> 2)];
    float lb = lrow[wm0 + 8 + (lane >> 2)];
    float ia = 1.0f / la, ib = 1.0f / lb;
    int ra = qt * 128 + wm0 + (lane >> 2);
    int rb = ra + 8;
#pragma unroll
    for (int nt = 0; nt < 8; nt++) {
        int col = h * 64 + nt * 8 + 2 * (lane & 3);
        if (ra < NTOK) {
            size_t p = (size_t)(b * NTOK + ra) * DM + col;
            *reinterpret_cast<uint32_t*>(yh + p) = packh2(o[nt][0] * ia, o[nt][1] * ia);
        }
        if (rb < NTOK) {
            size_t p = (size_t)(b * NTOK + rb) * DM + col;
            *reinterpret_cast<uint32_t*>(yh + p) = packh2(o[nt][2] * ib, o[nt][3] * ib);
        }
    }
}

// ---------------- fp16 GEMM: A single fp16, B split (BSPLIT=1) or single (0) ----------
// EPI: 0 fp32 (+bias?+res?), 1 bf16 split (+bias), 2 fp16 single gelu (+bias),
//      3 bf16 split TRANSPOSED into per-head VT layout (+bias)  [V of qkv]
static constexpr int GRS   = 144;
static constexpr int GASZ  = 64 * GRS;             // A plane 9216
static constexpr int GBSZ  = 128 * GRS;            // B plane 18432
static constexpr int TRS   = 136;                  // VT staging row stride
static constexpr int VTSTG = 128 * TRS;            // 17408 per plane

template <int EPI, int BSPLIT>
__global__ void __launch_bounds__(256, 2)
h16_gemm(const f16* __restrict__ A, int lda,
         const f16* __restrict__ Bhi, const f16* __restrict__ Blo, int ldb,
         float* __restrict__ Cf, bf16* __restrict__ Cbh, bf16* __restrict__ Cbl,
         f16* __restrict__ Chh, int ldc,
         const float* __restrict__ bias, const float* __restrict__ res,
         int M, int N, int NC) {
    constexpr int GBUF = GASZ + (BSPLIT ? 2 : 1) * GBSZ;
    extern __shared__ __align__(16) char smem[];
    uint32_t s0 = s2u(smem);

    const int tid = threadIdx.x, lane = tid & 31, warp = tid >> 5;
    const int wm0 = (warp >> 2) * 32;
    const int wn0 = (warp & 3) * 32;
    const int row0 = blockIdx.y * 64, col0 = blockIdx.x * 128;

    float lead[2][4][4];
    uint32_t cross[2][4][2];
#pragma unroll
    for (int i = 0; i < 2; i++)
#pragma unroll
        for (int j = 0; j < 4; j++) {
#pragma unroll
            for (int k = 0; k < 4; k++) lead[i][j][k] = 0.f;
            cross[i][j][0] = 0u; cross[i][j][1] = 0u;
        }

    const uint32_t a_lane = (uint32_t)(wm0 + (lane & 15)) * GRS + (uint32_t)(lane >> 4) * 16u;
    const uint32_t b_lane = (uint32_t)(wn0 + (lane & 7) + ((lane >> 4) << 3)) * GRS +
                            (uint32_t)((lane >> 3) & 1) * 16u;

    auto load_chunk = [&](int ck, int bsel) {
        uint32_t base = s0 + bsel * GBUF;
#pragma unroll
        for (int i = 0; i < 2; i++) {
            int idx = tid + i * 256;
            int r = idx >> 3, c = idx & 7;
            int gm = row0 + r;
            bool v = gm < M;
            const f16* pa = v ? (A + (size_t)gm * lda + (size_t)ck * 64 + c * 8) : A;
            cp16(base + (uint32_t)r * GRS + (uint32_t)c * 16u, pa, v);
        }
#pragma unroll
        for (int i = 0; i < 4; i++) {
            int idx = tid + i * 256;
            int r = idx >> 3, c = idx & 7;
            int gn = col0 + r;
            bool v = gn < N;
            const f16* ph = v ? (Bhi + (size_t)gn * ldb + (size_t)ck * 64 + c * 8) : Bhi;
            uint32_t d = base + GASZ + (uint32_t)r * GRS + (uint32_t)c * 16u;
            cp16(d, ph, v);
            if (BSPLIT) {
                const f16* pl = v ? (Blo + (size_t)gn * ldb + (size_t)ck * 64 + c * 8) : Blo;
                cp16(d + GBSZ, pl, v);
            }
        }
        cpcommit();
    };

    auto compute = [&](int bsel) {
        uint32_t base = s0 + bsel * GBUF;
        uint32_t ah = base;
        uint32_t bh = base + GASZ, bl = base + GASZ + GBSZ;
#pragma unroll
        for (int ks = 0; ks < 4; ks++) {
            uint32_t af[2][4];
#pragma unroll
            for (int mt = 0; mt < 2; mt++) {
                uint32_t off = a_lane + (uint32_t)mt * (16 * GRS) + (uint32_t)ks * 32u;
                ldsm4(af[mt], ah + off);
            }
            uint32_t bfh[2][4], bfl[2][4];
#pragma unroll
            for (int np = 0; np < 2; np++) {
                uint32_t off = b_lane + (uint32_t)np * (16 * GRS) + (uint32_t)ks * 32u;
                ldsm4(bfh[np], bh + off);
                if (BSPLIT) ldsm4(bfl[np], bl + off);
            }
#pragma unroll
            for (int mt = 0; mt < 2; mt++)
#pragma unroll
                for (int nt = 0; nt < 4; nt++) {
                    const uint32_t* Bh2 = &bfh[nt >> 1][(nt & 1) * 2];
                    mma_h_f32(lead[mt][nt], af[mt], Bh2);
                    if (BSPLIT) {
                        const uint32_t* Bl2 = &bfl[nt >> 1][(nt & 1) * 2];
                        mma_h_f16(cross[mt][nt], af[mt], Bl2);
                    }
                }
        }
    };

    load_chunk(0, 0);
    for (int ck = 0; ck < NC; ck++) {
        if (ck + 1 < NC) { load_chunk(ck + 1, (ck + 1) & 1); cpwait1(); }
        else             { cpwait0(); }
        __syncthreads();
        compute(ck & 1);
        __syncthreads();
    }

    const float INV = 1.0f / 2048.0f;
#pragma unroll
    for (int mt = 0; mt < 2; mt++) {
#pragma unroll
        for (int nt = 0; nt < 4; nt++) {
            int r0 = row0 + wm0 + mt * 16 + (lane >> 2);
            int c0 = col0 + wn0 + nt * 8 + (lane & 3) * 2;
            float* a4 = lead[mt][nt];
#pragma unroll
            for (int h = 0; h < 2; h++) {
                int gm = r0 + h * 8;
                if (gm >= M) continue;
                float v0 = a4[h * 2], v1 = a4[h * 2 + 1];
                if (BSPLIT) {
                    __half2 cx = *reinterpret_cast<__half2*>(&cross[mt][nt][h]);
                    v0 += __half2float(cx.x) * INV;
                    v1 += __half2float(cx.y) * INV;
                }
                if (bias) { v0 += bias[c0]; v1 += bias[c0 + 1]; }
                if (EPI == 0) {
                    if (res) {
                        v0 += res[(size_t)gm * ldc + c0];
                        v1 += res[(size_t)gm * ldc + c0 + 1];
                    }
                    Cf[(size_t)gm * ldc + c0]     = v0;
                    Cf[(size_t)gm * ldc + c0 + 1] = v1;
                } else if (EPI == 1) {
                    uint32_t lo, hi = packsplit_hi(v0, v1, lo);
                    *reinterpret_cast<uint32_t*>(Cbh + (size_t)gm * ldc + c0) = hi;
                    *reinterpret_cast<uint32_t*>(Cbl + (size_t)gm * ldc + c0) = lo;
                } else if (EPI == 2) {
                    *reinterpret_cast<uint32_t*>(Chh + (size_t)gm * ldc + c0) =
                        packh2(geluf(v0), geluf(v1));
                } else {
                    bf16 h0, l0, h1, l1;
                    split2(v0, h0, l0);
                    split2(v1, h1, l1);
                    int trow = gm - row0;
                    int dl = c0 - col0;
                    *(bf16*)(smem + (uint32_t)dl * TRS + (uint32_t)trow * 2) = h0;
                    *(bf16*)(smem + (uint32_t)(dl + 1) * TRS + (uint32_t)trow * 2) = h1;
                    *(bf16*)(smem + VTSTG + (uint32_t)dl * TRS + (uint32_t)trow * 2) = l0;
                    *(bf16*)(smem + VTSTG + (uint32_t)(dl + 1) * TRS + (uint32_t)trow * 2) = l1;
                }
            }
        }
    }

    if (EPI == 3) {
        __syncthreads();
#pragma unroll 1
        for (int it = 0; it < 16; it++) {
            int dl = warp + it * 8;
            int gcol = col0 + dl;
            int hh = gcol >> 6, dh = gcol & 63;
#pragma unroll
            for (int pass = 0; pass < 2; pass++) {
                int trow = pass * 32 + lane;
                int gm = row0 + trow;
                if (gm < M) {
                    int b = gm / NTOK, t = gm % NTOK;
                    size_t dst = ((size_t)(b * HEADS + hh) * 64 + dh) * SPAD + t;
                    Cbh[dst] = *(bf16*)(smem + (uint32_t)dl * TRS + (uint32_t)trow * 2);
                    Cbl[dst] = *(bf16*)(smem + VTSTG + (uint32_t)dl * TRS + (uint32_t)trow * 2);
                }
            }
        }
    }
}

template <int EPI, int BSPLIT>
static void hgemm(const f16* A, int lda,
                  const f16* Bh, const f16* Bl, int ldb,
                  float* Cf, bf16* Cbh, bf16* Cbl, f16* Chh, int ldc,
                  const float* bias, const float* res, int M, int N, int K) {
    constexpr int GBUF = GASZ + (BSPLIT ? 2 : 1) * GBSZ;
    int smem = 2 * GBUF;
    cudaFuncSetAttribute(h16_gemm<EPI, BSPLIT>, cudaFuncAttributeMaxDynamicSharedMemorySize, smem);
    dim3 grid(N / 128, (M + 63) / 64, 1);
    h16_gemm<EPI, BSPLIT><<<grid, 256, smem>>>(A, lda, Bh, Bl, ldb, Cf, Cbh, Cbl, Chh,
                                               ldc, bias, res, M, N, K / 64);
}

extern "C" void kernel_launch(void* const* d_in, const int* in_sizes, int n_in,
                              void* d_out, int out_size) {
    const float* x       = (const float*)d_in[0];
    const float* conv_w  = (const float*)d_in[1];
    const float* conv_b  = (const float*)d_in[2];
    const float* cls_tok = (const float*)d_in[3];
    const float* pos_emb = (const float*)d_in[4];
    const float* ln1_g   = (const float*)d_in[5];
    const float* ln1_b   = (const float*)d_in[6];
    const float* qkv_w   = (const float*)d_in[7];
    const float* qkv_b   = (const float*)d_in[8];
    const float* proj_w  = (const float*)d_in[9];
    const float* proj_b  = (const float*)d_in[10];
    const float* ln2_g   = (const float*)d_in[11];
    const float* ln2_b   = (const float*)d_in[12];
    const float* mlp_w1  = (const float*)d_in[13];
    const float* mlp_b1  = (const float*)d_in[14];
    const float* mlp_w2  = (const float*)d_in[15];
    const float* mlp_b2  = (const float*)d_in[16];
    const float* lnf_g   = (const float*)d_in[17];
    const float* lnf_b   = (const float*)d_in[18];
    float* out = (float*)d_out;

    f16 *wh, *wl, *cwh, *cwl, *pxh, *xh, *ahp, *mh;
    float *ph, *ptmp;
    bf16 *qhi, *qlo, *vthi, *vtlo;
    cudaGetSymbolAddress((void**)&wh, g_wh);
    cudaGetSymbolAddress((void**)&wl, g_wl);
    cudaGetSymbolAddress((void**)&cwh, g_cwh);
    cudaGetSymbolAddress((void**)&cwl, g_cwl);
    cudaGetSymbolAddress((void**)&pxh, g_pxh);
    cudaGetSymbolAddress((void**)&xh, g_xh);
    cudaGetSymbolAddress((void**)&ahp, g_ah);
    cudaGetSymbolAddress((void**)&mh, g_mh);
    cudaGetSymbolAddress((void**)&ph, g_h);
    cudaGetSymbolAddress((void**)&ptmp, g_ptmp);
    cudaGetSymbolAddress((void**)&qhi, g_qhi);
    cudaGetSymbolAddress((void**)&qlo, g_qlo);
    cudaGetSymbolAddress((void**)&vthi, g_vthi);
    cudaGetSymbolAddress((void**)&vtlo, g_vtlo);

    dim3 tb(32, 8);

    // ---- weight prep: batched over layers (grid.z) ----
    split_h<<<(DM * DM + 255) / 256, 256>>>(conv_w, cwh, cwl, DM * DM);
    wt_trans_hB<<<dim3(2304 / 32, 768 / 32, LAYERS), tb>>>(
        qkv_w, wh, wl, DM, 3 * DM, (long long)DM * 3 * DM, LW);
    wt_trans_hB<<<dim3(768 / 32, 768 / 32, LAYERS), tb>>>(
        proj_w, wh + 1769472, wl + 1769472, DM, DM, (long long)DM * DM, LW);
    wt_trans_h1B<<<dim3(3072 / 32, 768 / 32, LAYERS), tb>>>(
        mlp_w1, wh + 2359296, DM, 4 * DM, (long long)DM * 4 * DM, LW);
    wt_trans_h1B<<<dim3(768 / 32, 3072 / 32, LAYERS), tb>>>(
        mlp_w2, wh + 4718592, 4 * DM, DM, (long long)4 * DM * DM, LW);

    // ---- patch embed ----
    im2col_h<<<(MPATCH * DM + 255) / 256, 256>>>(x, pxh);
    hgemm<0, 1>(pxh, DM, cwh, cwl, DM, ptmp, nullptr, nullptr, nullptr, DM,
                conv_b, nullptr, MPATCH, DM, DM);
    assemble_kernel<<<(MTOK * DM + 255) / 256, 256>>>(ptmp, cls_tok, pos_emb, ph);

    cudaFuncSetAttribute(fused_attn, cudaFuncAttributeMaxDynamicSharedMemorySize, FA_SMEM);

    for (int l = 0; l < LAYERS; l++) {
        long long wo = (long long)l * LW;
        const f16* qwT_h = wh + wo;            const f16* qwT_l = wl + wo;
        const f16* pwT_h = wh + wo + 1769472;  const f16* pwT_l = wl + wo + 1769472;
        const f16* w1T_h = wh + wo + 2359296;
        const f16* w2T_h = wh + wo + 4718592;
        const float* l1g = ln1_g + (size_t)l * DM;
        const float* l1b = ln1_b + (size_t)l * DM;
        const float* qb  = qkv_b + (size_t)l * 3 * DM;
        const float* pb  = proj_b + (size_t)l * DM;
        const float* l2g = ln2_g + (size_t)l * DM;
        const float* l2b = ln2_b + (size_t)l * DM;
        const float* b1  = mlp_b1 + (size_t)l * 4 * DM;
        const float* b2  = mlp_b2 + (size_t)l * DM;

        // LN1 -> single fp16
        ln_h<<<MTOK, 256>>>(ph, l1g, l1b, xh);
        // QK -> bf16 pair (first 1536 cols of qkv)
        hgemm<1, 1>(xh, DM, qwT_h, qwT_l, DM, nullptr, qhi, qlo, nullptr, 3 * DM,
                    qb, nullptr, MTOK, 2 * DM, DM);
        // V -> transposed VT bf16 pair directly (cols 1536..2304)
        hgemm<3, 1>(xh, DM, qwT_h + (size_t)2 * DM * DM, qwT_l + (size_t)2 * DM * DM, DM,
                    nullptr, vthi, vtlo, nullptr, SPAD,
                    qb + 2 * DM, nullptr, MTOK, DM, DM);
        // fused attention -> single fp16
        fused_attn<<<dim3(NCHUNK, BATCH * HEADS), 256, FA_SMEM>>>(qhi, qlo, vthi, vtlo, ahp);
        // proj + bias + residual -> h; weights split
        hgemm<0, 1>(ahp, DM, pwT_h, pwT_l, DM, ph, nullptr, nullptr, nullptr, DM,
                    pb, ph, MTOK, DM, DM);
        // LN2 -> single fp16
        ln_h<<<MTOK, 256>>>(ph, l2g, l2b, xh);
        // MLP1 + gelu -> single fp16; single-plane weights
        hgemm<2, 0>(xh, DM, w1T_h, nullptr, DM, nullptr, nullptr, nullptr, mh, 4 * DM,
                    b1, nullptr, MTOK, 4 * DM, DM);
        // MLP2 + bias + residual -> h; single-plane weights
        hgemm<0, 0>(mh, 4 * DM, w2T_h, nullptr, 4 * DM, ph, nullptr, nullptr, nullptr, DM,
                    b2, ph, MTOK, DM, 4 * DM);
    }

    // final LN on CLS rows -> out [8,768]
    ln_kernel<<<BATCH, 256>>>(ph, lnf_g, lnf_b, out, (long long)NTOK * DM, DM);
}

// round 16
// speedup vs baseline: 3.9125x; 1.0384x over previous
#include <cuda_runtime.h>
#include <cuda_bf16.h>
#include <cuda_fp16.h>
#include <math.h>
#include <stdint.h>

using bf16 = __nv_bfloat16;
using f16 = __half;

template <int N> struct ic { static constexpr int v = N; };

// ---------------- problem constants ----------------
static constexpr int BATCH  = 8;
static constexpr int DM     = 768;
static constexpr int HEADS  = 12;
static constexpr int LAYERS = 12;
static constexpr int NTOK   = 785;
static constexpr int NPATCH = 784;
static constexpr int MTOK   = BATCH * NTOK;    // 6280
static constexpr int MPATCH = BATCH * NPATCH;  // 6272
static constexpr int IMG    = 448;
static constexpr int PSZ    = 16;
static constexpr int GRID28 = 28;
static constexpr int SPAD   = 896;
static constexpr long long LW = 7077888LL;

// ---------------- device scratch ----------------
__device__ f16  g_wh[(size_t)LAYERS * LW];     // weights hi
__device__ f16  g_wl[(size_t)LAYERS * LW];     // weights lo (qkv/proj use; mlp ignores)
__device__ f16  g_cwh[DM * DM];
__device__ f16  g_cwl[DM * DM];
__device__ f16  g_pxh[(size_t)MPATCH * DM];
__device__ f16  g_xh[(size_t)MTOK * DM];
__device__ f16  g_ah[(size_t)MTOK * DM];
__device__ f16  g_mh[(size_t)MTOK * 4 * DM];
__device__ float g_h[(size_t)MTOK * DM];
__device__ float g_ptmp[(size_t)MPATCH * DM];
__device__ bf16  g_qhi[(size_t)MTOK * 3 * DM];
__device__ bf16  g_qlo[(size_t)MTOK * 3 * DM];
__device__ f16   g_vthi[(size_t)BATCH * HEADS * 64 * SPAD];  // fp16 split VT; zero tail
__device__ f16   g_vtlo[(size_t)BATCH * HEADS * 64 * SPAD];

// ---------------- small helpers ----------------
__device__ __forceinline__ void split2(float v, bf16& h, bf16& l) {
    h = __float2bfloat16(v);
    l = __float2bfloat16(v - __bfloat162float(h));
}
__device__ __forceinline__ float geluf(float v) {
    return 0.5f * v * (1.0f + erff(v * 0.70710678118654752f));
}
__device__ __forceinline__ float warpSum(float v) {
#pragma unroll
    for (int o = 16; o > 0; o >>= 1) v += __shfl_xor_sync(0xffffffffu, v, o);
    return v;
}
__device__ __forceinline__ float blockSum256(float v, float* sh) {
    int lane = threadIdx.x & 31, w = threadIdx.x >> 5;
    v = warpSum(v);
    if (lane == 0) sh[w] = v;
    __syncthreads();
    float r = (threadIdx.x < 8) ? sh[threadIdx.x] : 0.f;
    if (w == 0) { r = warpSum(r); if (lane == 0) sh[0] = r; }
    __syncthreads();
    r = sh[0];
    __syncthreads();
    return r;
}

// ---------------- PTX wrappers ----------------
__device__ __forceinline__ uint32_t s2u(const void* p) {
    uint32_t a;
    asm("{ .reg .u64 t; cvta.to.shared.u64 t, %1; cvt.u32.u64 %0, t; }" : "=r"(a) : "l"(p));
    return a;
}
__device__ __forceinline__ void cp16(uint32_t d, const void* s, bool pred) {
    int sz = pred ? 16 : 0;
    asm volatile("cp.async.cg.shared.global [%0], [%1], 16, %2;" :: "r"(d), "l"(s), "r"(sz));
}
__device__ __forceinline__ void cpcommit() { asm volatile("cp.async.commit_group;" ::: "memory"); }
__device__ __forceinline__ void cpwait0()  { asm volatile("cp.async.wait_group 0;" ::: "memory"); }
__device__ __forceinline__ void cpwait1()  { asm volatile("cp.async.wait_group 1;" ::: "memory"); }
__device__ __forceinline__ void ldsm4(uint32_t* r, uint32_t addr) {
    asm volatile("ldmatrix.sync.aligned.m8n8.x4.shared.b16 {%0,%1,%2,%3}, [%4];"
                 : "=r"(r[0]), "=r"(r[1]), "=r"(r[2]), "=r"(r[3]) : "r"(addr));
}
// bf16 operands, f32 acc (validated; attention QK)
__device__ __forceinline__ void mma16816(float* c, const uint32_t* a, const uint32_t* b) {
    asm volatile(
        "mma.sync.aligned.m16n8k16.row.col.f32.bf16.bf16.f32 "
        "{%0,%1,%2,%3}, {%4,%5,%6,%7}, {%8,%9}, {%0,%1,%2,%3};"
        : "+f"(c[0]), "+f"(c[1]), "+f"(c[2]), "+f"(c[3])
        : "r"(a[0]), "r"(a[1]), "r"(a[2]), "r"(a[3]), "r"(b[0]), "r"(b[1]));
}
// f16 operands, f32 acc (lead term)
__device__ __forceinline__ void mma_h_f32(float* c, const uint32_t* a, const uint32_t* b) {
    asm volatile(
        "mma.sync.aligned.m16n8k16.row.col.f32.f16.f16.f32 "
        "{%0,%1,%2,%3}, {%4,%5,%6,%7}, {%8,%9}, {%0,%1,%2,%3};"
        : "+f"(c[0]), "+f"(c[1]), "+f"(c[2]), "+f"(c[3])
        : "r"(a[0]), "r"(a[1]), "r"(a[2]), "r"(a[3]), "r"(b[0]), "r"(b[1]));
}
// f16 operands, f16 acc (cross term; 2 C regs)
__device__ __forceinline__ void mma_h_f16(uint32_t* c, const uint32_t* a, const uint32_t* b) {
    asm volatile(
        "mma.sync.aligned.m16n8k16.row.col.f16.f16.f16.f16 "
        "{%0,%1}, {%2,%3,%4,%5}, {%6,%7}, {%0,%1};"
        : "+r"(c[0]), "+r"(c[1])
        : "r"(a[0]), "r"(a[1]), "r"(a[2]), "r"(a[3]), "r"(b[0]), "r"(b[1]));
}
// bf16 split pack (attention S staging; validated)
__device__ __forceinline__ uint32_t packsplit_hi(float a, float b, uint32_t& lo) {
    bf16 ah, al, bh, bl;
    split2(a, ah, al);
    split2(b, bh, bl);
    __nv_bfloat162 h2; h2.x = ah; h2.y = bh;
    __nv_bfloat162 l2; l2.x = al; l2.y = bl;
    lo = *reinterpret_cast<uint32_t*>(&l2);
    return *reinterpret_cast<uint32_t*>(&h2);
}
__device__ __forceinline__ uint32_t packh2(float a, float b) {
    __half2 h2 = __halves2half2(__float2half(a), __float2half(b));
    return *reinterpret_cast<uint32_t*>(&h2);
}
__device__ __forceinline__ void splith(float v, f16& h, f16& l) {
    h = __float2half(v);
    l = __float2half((v - __half2float(h)) * 2048.f);
}

// ---------------- elementwise / prep kernels ----------------
__global__ void im2col_h(const float* __restrict__ x, f16* __restrict__ Ph) {
    int idx = blockIdx.x * blockDim.x + threadIdx.x;
    if (idx >= MPATCH * DM) return;
    int k = idx % DM, m = idx / DM;
    int b = m / NPATCH, t = m % NPATCH;
    int py = t / GRID28, px = t % GRID28;
    int c = k >> 8, rem = k & 255, i = rem >> 4, j = rem & 15;
    size_t src = (((size_t)(b * 3 + c) * IMG) + (size_t)(py * PSZ + i)) * IMG + (px * PSZ + j);
    Ph[idx] = __float2half(x[src]);
}

__global__ void split_h(const float* __restrict__ W, f16* __restrict__ Oh,
                        f16* __restrict__ Ol, int n) {
    int idx = blockIdx.x * blockDim.x + threadIdx.x;
    if (idx >= n) return;
    f16 h, l;
    splith(W[idx], h, l);
    Oh[idx] = h; Ol[idx] = l;
}

// batched over layers (blockIdx.z): W[K,N] -> out[n*K + k], fp16 split
__global__ void wt_trans_hB(const float* __restrict__ W0, f16* __restrict__ Oh0,
                            f16* __restrict__ Ol0, int K, int N,
                            long long sIn, long long sOut) {
    const float* W = W0 + (long long)blockIdx.z * sIn;
    f16* Oh = Oh0 + (long long)blockIdx.z * sOut;
    f16* Ol = Ol0 + (long long)blockIdx.z * sOut;
    __shared__ float tile[32][33];
    int kb = blockIdx.y * 32, nb = blockIdx.x * 32;
    int tx = threadIdx.x, ty = threadIdx.y;  // 32 x 8
#pragma unroll
    for (int i = 0; i < 32; i += 8) {
        int k = kb + ty + i, n = nb + tx;
        tile[ty + i][tx] = (k < K && n < N) ? W[(size_t)k * N + n] : 0.f;
    }
    __syncthreads();
#pragma unroll
    for (int i = 0; i < 32; i += 8) {
        int n = nb + ty + i, k = kb + tx;
        if (n < N && k < K) {
            f16 h, l;
            splith(tile[tx][ty + i], h, l);
            Oh[(size_t)n * K + k] = h;
            Ol[(size_t)n * K + k] = l;
        }
    }
}

// batched, single fp16 out (MLP weights)
__global__ void wt_trans_h1B(const float* __restrict__ W0, f16* __restrict__ Oh0,
                             int K, int N, long long sIn, long long sOut) {
    const float* W = W0 + (long long)blockIdx.z * sIn;
    f16* Oh = Oh0 + (long long)blockIdx.z * sOut;
    __shared__ float tile[32][33];
    int kb = blockIdx.y * 32, nb = blockIdx.x * 32;
    int tx = threadIdx.x, ty = threadIdx.y;
#pragma unroll
    for (int i = 0; i < 32; i += 8) {
        int k = kb + ty + i, n = nb + tx;
        tile[ty + i][tx] = (k < K && n < N) ? W[(size_t)k * N + n] : 0.f;
    }
    __syncthreads();
#pragma unroll
    for (int i = 0; i < 32; i += 8) {
        int n = nb + ty + i, k = kb + tx;
        if (n < N && k < K)
            Oh[(size_t)n * K + k] = __float2half(tile[tx][ty + i]);
    }
}

__global__ void assemble_kernel(const float* __restrict__ tok, const float* __restrict__ cls,
                                const float* __restrict__ pos, float* __restrict__ H) {
    int idx = blockIdx.x * blockDim.x + threadIdx.x;
    if (idx >= MTOK * DM) return;
    int d = idx % DM;
    int r = idx / DM;
    int n = r % NTOK, b = r / NTOK;
    float v;
    if (n == 0) v = cls[d] + pos[d];
    else        v = tok[((size_t)b * NPATCH + (n - 1)) * DM + d] + pos[(size_t)n * DM + d];
    H[idx] = v;
}

__global__ void ln_kernel(const float* __restrict__ X, const float* __restrict__ g,
                          const float* __restrict__ bb, float* __restrict__ Y,
                          long long inStride, long long outStride) {
    const float* x = X + (long long)blockIdx.x * inStride;
    float* y = Y + (long long)blockIdx.x * outStride;
    int t = threadIdx.x;
    __shared__ float sh[8];
    float v0 = x[t], v1 = x[t + 256], v2 = x[t + 512];
    float mu = blockSum256(v0 + v1 + v2, sh) * (1.0f / 768.0f);
    float d0 = v0 - mu, d1 = v1 - mu, d2 = v2 - mu;
    float var = blockSum256(d0 * d0 + d1 * d1 + d2 * d2, sh) * (1.0f / 768.0f);
    float rs = rsqrtf(var + 1e-5f);
    y[t]       = d0 * rs * g[t]       + bb[t];
    y[t + 256] = d1 * rs * g[t + 256] + bb[t + 256];
    y[t + 512] = d2 * rs * g[t + 512] + bb[t + 512];
}

// LN -> single fp16
__global__ void ln_h(const float* __restrict__ X, const float* __restrict__ g,
                     const float* __restrict__ bb, f16* __restrict__ Yh) {
    const float* x = X + (size_t)blockIdx.x * DM;
    f16* yh = Yh + (size_t)blockIdx.x * DM;
    int t = threadIdx.x;
    __shared__ float sh[8];
    float v0 = x[t], v1 = x[t + 256], v2 = x[t + 512];
    float mu = blockSum256(v0 + v1 + v2, sh) * (1.0f / 768.0f);
    float d0 = v0 - mu, d1 = v1 - mu, d2 = v2 - mu;
    float var = blockSum256(d0 * d0 + d1 * d1 + d2 * d2, sh) * (1.0f / 768.0f);
    float rs = rsqrtf(var + 1e-5f);
    yh[t]       = __float2half(d0 * rs * g[t]       + bb[t]);
    yh[t + 256] = __float2half(d1 * rs * g[t + 256] + bb[t + 256]);
    yh[t + 512] = __float2half(d2 * rs * g[t + 512] + bb[t + 512]);
}

// ---------------- fused flash attention (v6: fp16 P·V, 2-term) ----------------
static constexpr int ARS    = 144;
static constexpr int KTILE  = 128 * ARS;
static constexpr int VRS    = 272;
static constexpr int VTILE  = 64 * VRS;
static constexpr int KVBUF  = 2 * KTILE + 2 * VTILE;
static constexpr int PRS2   = 272;
static constexpr int SPTILE = 128 * PRS2;
static constexpr int OFF_SPH = 2 * KVBUF;
static constexpr int OFF_SPL = OFF_SPH + SPTILE;
static constexpr int OFF_M  = OFF_SPL + SPTILE;
static constexpr int OFF_L  = OFF_M + 512;
static constexpr int OFF_CA = OFF_L + 512;
static constexpr int OFF_T  = OFF_CA + 512;
static constexpr int OFF_RM = OFF_T + 1024;
static constexpr int FA_SMEM = OFF_RM + 512;
static constexpr int NCHUNK = 7;

__global__ void __launch_bounds__(256, 1)
fused_attn(const bf16* __restrict__ qkvh, const bf16* __restrict__ qkvl,
           const f16* __restrict__ vth, const f16* __restrict__ vtl,
           f16* __restrict__ yh) {
    extern __shared__ __align__(16) char smem[];
    uint32_t s0 = s2u(smem);
    const int tid = threadIdx.x, lane = tid & 31, warp = tid >> 5;
    const int qt = blockIdx.x;
    const int z = blockIdx.y;
    const int b = z / HEADS, h = z % HEADS;
    const float SC = 0.125f;

    const int wm0 = warp * 16;
    const uint32_t a_lane  = (uint32_t)(wm0 + (lane & 15)) * ARS + (uint32_t)(lane >> 4) * 16u;
    const uint32_t b_lane  = (uint32_t)((lane & 7) + ((lane >> 4) << 3)) * ARS +
                             (uint32_t)((lane >> 3) & 1) * 16u;
    const uint32_t vb_lane = (uint32_t)((lane & 7) + ((lane >> 4) << 3)) * VRS +
                             (uint32_t)((lane >> 3) & 1) * 16u;
    const uint32_t ap_lane = (uint32_t)(wm0 + (lane & 15)) * PRS2 + (uint32_t)(lane >> 4) * 16u;

    float* mrow = reinterpret_cast<float*>(smem + OFF_M);
    float* lrow = reinterpret_cast<float*>(smem + OFF_L);
    float* crow = reinterpret_cast<float*>(smem + OFF_CA);
    float* tred = reinterpret_cast<float*>(smem + OFF_T);
    float* rmax = reinterpret_cast<float*>(smem + OFF_RM);

    auto load_qk = [&](int rowbase, int colbase, uint32_t dsth, uint32_t dstl) {
#pragma unroll
        for (int i = 0; i < 4; i++) {
            int idx = tid + i * 256;
            int r = idx >> 3, g = idx & 7;
            bool v = (rowbase + r) < NTOK;
            size_t off = ((size_t)(b * NTOK + rowbase + r)) * (3 * DM) + colbase + g * 8;
            const bf16* sh2 = v ? (qkvh + off) : qkvh;
            const bf16* sl2 = v ? (qkvl + off) : qkvl;
            uint32_t d = (uint32_t)r * ARS + (uint32_t)g * 16u;
            cp16(dsth + d, sh2, v);
            cp16(dstl + d, sl2, v);
        }
    };
    auto load_vt = [&](int c, uint32_t dsth, uint32_t dstl) {
        const f16* bh2 = vth + (size_t)z * 64 * SPAD + (size_t)c * 128;
        const f16* bl2 = vtl + (size_t)z * 64 * SPAD + (size_t)c * 128;
#pragma unroll
        for (int i = 0; i < 4; i++) {
            int idx = tid + i * 256;
            int r = idx >> 4, g = idx & 15;
            size_t off = (size_t)r * SPAD + g * 8;
            uint32_t d = (uint32_t)r * VRS + (uint32_t)g * 16u;
            cp16(dsth + d, bh2 + off, true);
            cp16(dstl + d, bl2 + off, true);
        }
    };
    auto load_chunk = [&](int c, int bsel) {
        uint32_t base = s0 + bsel * KVBUF;
        load_qk(c * 128, DM + h * 64, base, base + KTILE);
        load_vt(c, base + 2 * KTILE, base + 2 * KTILE + VTILE);
        cpcommit();
    };

    load_qk(qt * 128, h * 64, s0 + OFF_SPH, s0 + OFF_SPH + KTILE);
    cpcommit();
    cpwait0();
    __syncthreads();
    uint32_t aQh[4][4], aQl[4][4];
#pragma unroll
    for (int ks = 0; ks < 4; ks++) {
        ldsm4(aQh[ks], s0 + OFF_SPH + a_lane + ks * 32);
        ldsm4(aQl[ks], s0 + OFF_SPH + KTILE + a_lane + ks * 32);
    }
    if (tid < 128) { mrow[tid] = -1e30f; lrow[tid] = 0.f; }
    __syncthreads();

    float o[8][4];
#pragma unroll
    for (int i = 0; i < 8; i++)
#pragma unroll
        for (int j = 0; j < 4; j++) o[i][j] = 0.f;

    load_chunk(0, 0);
    for (int c = 0; c < NCHUNK; c++) {
        const bool full = (c < NCHUNK - 1);
        if (c + 1 < NCHUNK) { load_chunk(c + 1, (c + 1) & 1); cpwait1(); }
        else                { cpwait0(); }
        __syncthreads();
        uint32_t kvb = s0 + (c & 1) * KVBUF;
        uint32_t Kh = kvb, Kl = kvb + KTILE;
        uint32_t Vh = kvb + 2 * KTILE, Vl = kvb + 2 * KTILE + VTILE;

        // ---- S = Q K^T (3-term split bf16); last chunk only 32 key cols ----
        float s[16][4];
#pragma unroll
        for (int j = 0; j < 16; j++)
#pragma unroll
            for (int q = 0; q < 4; q++) s[j][q] = 0.f;

        auto smma = [&](auto JPC) {
            constexpr int JP = decltype(JPC)::v;
#pragma unroll
            for (int ks = 0; ks < 4; ks++) {
#pragma unroll
                for (int jp = 0; jp < JP; jp++) {
                    uint32_t kh[4], kl[4];
                    uint32_t koff = b_lane + (uint32_t)jp * (16 * ARS) + (uint32_t)ks * 32u;
                    ldsm4(kh, Kh + koff);
                    ldsm4(kl, Kl + koff);
#pragma unroll
                    for (int hf = 0; hf < 2; hf++) {
                        int j = jp * 2 + hf;
                        mma16816(s[j], aQh[ks], &kh[hf * 2]);
                        mma16816(s[j], aQh[ks], &kl[hf * 2]);
                        mma16816(s[j], aQl[ks], &kh[hf * 2]);
                    }
                }
            }
        };
        if (full) smma(ic<8>{}); else smma(ic<2>{});

        // ---- stage S as split bf16 (validated store coords) ----
        {
            char* smp = smem;
            int r0 = wm0 + (lane >> 2);
            int c0 = 2 * (lane & 3);
            auto stage = [&](auto JTC) {
                constexpr int JT = decltype(JTC)::v;
#pragma unroll
                for (int j = 0; j < JT; j++) {
                    int cc = j * 8 + c0;
                    uint32_t loA, hiA = packsplit_hi(s[j][0], s[j][1], loA);
                    uint32_t loB, hiB = packsplit_hi(s[j][2], s[j][3], loB);
                    *(uint32_t*)(smp + OFF_SPH + (uint32_t)r0 * PRS2 + cc * 2) = hiA;
                    *(uint32_t*)(smp + OFF_SPL + (uint32_t)r0 * PRS2 + cc * 2) = loA;
                    *(uint32_t*)(smp + OFF_SPH + (uint32_t)(r0 + 8) * PRS2 + cc * 2) = hiB;
                    *(uint32_t*)(smp + OFF_SPL + (uint32_t)(r0 + 8) * PRS2 + cc * 2) = loB;
                }
            };
            if (full) stage(ic<16>{}); else stage(ic<4>{});
        }

        if (full) {
            // ---- fragment chunk-max (all 128 cols valid) ----
            float mxa = -1e30f, mxb = -1e30f;
#pragma unroll
            for (int j = 0; j < 16; j++) {
                mxa = fmaxf(mxa, fmaxf(s[j][0], s[j][1]));
                mxb = fmaxf(mxb, fmaxf(s[j][2], s[j][3]));
            }
#pragma unroll
            for (int off = 1; off <= 2; off <<= 1) {
                mxa = fmaxf(mxa, __shfl_xor_sync(0xffffffffu, mxa, off));
                mxb = fmaxf(mxb, __shfl_xor_sync(0xffffffffu, mxb, off));
            }
            if ((lane & 3) == 0) {
                rmax[wm0 + (lane >> 2)] = mxa;
                rmax[wm0 + 8 + (lane >> 2)] = mxb;
            }
            __syncthreads();

            const int r = tid >> 1, half = tid & 1;
            char* smp = smem;
            const uint32_t rowoff = (uint32_t)r * PRS2 + (uint32_t)half * 128u;
            float m_old = mrow[r];
            float m_new = fmaxf(m_old, rmax[r]);
            float ca = __expf(SC * (m_old - m_new));

            float esum = 0.f;
#pragma unroll 8
            for (int k = 0; k < 64; k += 2) {
                uint32_t hi = *(uint32_t*)(smp + OFF_SPH + rowoff + k * 2);
                uint32_t lo = *(uint32_t*)(smp + OFF_SPL + rowoff + k * 2);
                __nv_bfloat162 h2 = *reinterpret_cast<__nv_bfloat162*>(&hi);
                __nv_bfloat162 l2 = *reinterpret_cast<__nv_bfloat162*>(&lo);
                float v0 = __bfloat162float(h2.x) + __bfloat162float(l2.x);
                float v1 = __bfloat162float(h2.y) + __bfloat162float(l2.y);
                float e0 = __expf(SC * (v0 - m_new));
                float e1 = __expf(SC * (v1 - m_new));
                esum += e0 + e1;
                *(uint32_t*)(smp + OFF_SPH + rowoff + k * 2) = packh2(e0, e1);
            }
            tred[tid] = esum;
            __syncthreads();
            if (half == 0) {
                lrow[r] = lrow[r] * ca + tred[2 * r] + tred[2 * r + 1];
                mrow[r] = m_new;
                crow[r] = ca;
            }
            __syncthreads();
        } else {
            // ---- last chunk: validated masked linear path ----
            __syncthreads();
            const int r = tid >> 1, half = tid & 1;
            char* smp = smem;
            const uint32_t rowoff = (uint32_t)r * PRS2 + (uint32_t)half * 128u;
            const int colbase = c * 128 + half * 64;
            const int nvalid0 = NTOK - colbase;
            const int nvalid = nvalid0 < 0 ? 0 : (nvalid0 > 64 ? 64 : nvalid0);

            float chmax = -1e30f;
#pragma unroll 8
            for (int k = 0; k < 64; k += 2) {
                uint32_t hi = *(uint32_t*)(smp + OFF_SPH + rowoff + k * 2);
                uint32_t lo = *(uint32_t*)(smp + OFF_SPL + rowoff + k * 2);
                __nv_bfloat162 h2 = *reinterpret_cast<__nv_bfloat162*>(&hi);
                __nv_bfloat162 l2 = *reinterpret_cast<__nv_bfloat162*>(&lo);
                float v0 = __bfloat162float(h2.x) + __bfloat162float(l2.x);
                float v1 = __bfloat162float(h2.y) + __bfloat162float(l2.y);
                if (k < nvalid)     chmax = fmaxf(chmax, v0);
                if (k + 1 < nvalid) chmax = fmaxf(chmax, v1);
            }
            tred[tid] = chmax;
            __syncthreads();
            float m_old = mrow[r];
            float rm = fmaxf(tred[2 * r], tred[2 * r + 1]);
            float m_new = fmaxf(m_old, rm);
            float ca = __expf(SC * (m_old - m_new));
            __syncthreads();

            float esum = 0.f;
#pragma unroll 8
            for (int k = 0; k < 64; k += 2) {
                uint32_t hi = *(uint32_t*)(smp + OFF_SPH + rowoff + k * 2);
                uint32_t lo = *(uint32_t*)(smp + OFF_SPL + rowoff + k * 2);
                __nv_bfloat162 h2 = *reinterpret_cast<__nv_bfloat162*>(&hi);
                __nv_bfloat162 l2 = *reinterpret_cast<__nv_bfloat162*>(&lo);
                float v0 = __bfloat162float(h2.x) + __bfloat162float(l2.x);
                float v1 = __bfloat162float(h2.y) + __bfloat162float(l2.y);
                float e0 = (k < nvalid)     ? __expf(SC * (v0 - m_new)) : 0.f;
                float e1 = (k + 1 < nvalid) ? __expf(SC * (v1 - m_new)) : 0.f;
                esum += e0 + e1;
                *(uint32_t*)(smp + OFF_SPH + rowoff + k * 2) = packh2(e0, e1);
            }
            tred[tid] = esum;
            __syncthreads();
            if (half == 0) {
                lrow[r] = lrow[r] * ca + tred[2 * r] + tred[2 * r + 1];
                mrow[r] = m_new;
                crow[r] = ca;
            }
            __syncthreads();
        }

        // ---- o rescale by this chunk's per-row ca ----
        float caA = crow[wm0 + (lane >> 2)];
        float caB = crow[wm0 + 8 + (lane >> 2)];
#pragma unroll
        for (int nt = 0; nt < 8; nt++) {
            o[nt][0] *= caA; o[nt][1] *= caA;
            o[nt][2] *= caB; o[nt][3] *= caB;
        }

        // ---- O += P V : P fp16 single, V fp16 split (lead f32 + cross f16/2048) ----
        auto pv = [&](auto KTC) {
            constexpr int KT = decltype(KTC)::v;
            uint32_t ocx[8][2];
#pragma unroll
            for (int nt = 0; nt < 8; nt++) { ocx[nt][0] = 0u; ocx[nt][1] = 0u; }
#pragma unroll
            for (int kt = 0; kt < KT; kt++) {
                uint32_t pa[4];
                ldsm4(pa, s0 + OFF_SPH + ap_lane + (uint32_t)kt * 32u);
#pragma unroll
                for (int dp = 0; dp < 4; dp++) {
                    uint32_t vh[4], vl[4];
                    uint32_t voff = vb_lane + (uint32_t)dp * (16 * VRS) + (uint32_t)kt * 32u;
                    ldsm4(vh, Vh + voff);
                    ldsm4(vl, Vl + voff);
#pragma unroll
                    for (int hf = 0; hf < 2; hf++) {
                        int nt = dp * 2 + hf;
                        mma_h_f32(o[nt], pa, &vh[hf * 2]);
                        mma_h_f16(ocx[nt], pa, &vl[hf * 2]);
                    }
                }
            }
            const float INV = 1.0f / 2048.0f;
#pragma unroll
            for (int nt = 0; nt < 8; nt++) {
                __half2 c0 = *reinterpret_cast<__half2*>(&ocx[nt][0]);
                __half2 c1 = *reinterpret_cast<__half2*>(&ocx[nt][1]);
                o[nt][0] += __half2float(c0.x) * INV;
                o[nt][1] += __half2float(c0.y) * INV;
                o[nt][2] += __half2float(c1.x) * INV;
                o[nt][3] += __half2float(c1.y) * INV;
            }
        };
        if (full) pv(ic<8>{}); else pv(ic<2>{});
        __syncthreads();
    }

    float la = lrow[wm0 + (lane >> 2)];
    float lb = lrow[wm0 + 8 + (lane >> 2)];
    float ia = 1.0f / la, ib = 1.0f / lb;
    int ra = qt * 128 + wm0 + (lane >> 2);
    int rb = ra + 8;
#pragma unroll
    for (int nt = 0; nt < 8; nt++) {
        int col = h * 64 + nt * 8 + 2 * (lane & 3);
        if (ra < NTOK) {
            size_t p = (size_t)(b * NTOK + ra) * DM + col;
            *reinterpret_cast<uint32_t*>(yh + p) = packh2(o[nt][0] * ia, o[nt][1] * ia);
        }
        if (rb < NTOK) {
            size_t p = (size_t)(b * NTOK + rb) * DM + col;
            *reinterpret_cast<uint32_t*>(yh + p) = packh2(o[nt][2] * ib, o[nt][3] * ib);
        }
    }
}

// ---------------- fp16 GEMM: A single fp16, B split (BSPLIT=1) or single (0) ----------
// EPI: 0 fp32 (+bias?+res?), 1 bf16 split (+bias), 2 fp16 single gelu (+bias),
//      3 fp16 split TRANSPOSED into per-head VT layout (+bias)  [V of qkv]
static constexpr int GRS   = 144;
static constexpr int GASZ  = 64 * GRS;             // A plane 9216
static constexpr int GBSZ  = 128 * GRS;            // B plane 18432
static constexpr int TRS   = 136;                  // VT staging row stride
static constexpr int VTSTG = 128 * TRS;            // 17408 per plane

template <int EPI, int BSPLIT>
__global__ void __launch_bounds__(256, 2)
h16_gemm(const f16* __restrict__ A, int lda,
         const f16* __restrict__ Bhi, const f16* __restrict__ Blo, int ldb,
         float* __restrict__ Cf, bf16* __restrict__ Cbh, bf16* __restrict__ Cbl,
         f16* __restrict__ Chh, f16* __restrict__ Chl, int ldc,
         const float* __restrict__ bias, const float* __restrict__ res,
         int M, int N, int NC) {
    constexpr int GBUF = GASZ + (BSPLIT ? 2 : 1) * GBSZ;
    extern __shared__ __align__(16) char smem[];
    uint32_t s0 = s2u(smem);

    const int tid = threadIdx.x, lane = tid & 31, warp = tid >> 5;
    const int wm0 = (warp >> 2) * 32;
    const int wn0 = (warp & 3) * 32;
    const int row0 = blockIdx.y * 64, col0 = blockIdx.x * 128;

    float lead[2][4][4];
    uint32_t cross[2][4][2];
#pragma unroll
    for (int i = 0; i < 2; i++)
#pragma unroll
        for (int j = 0; j < 4; j++) {
#pragma unroll
            for (int k = 0; k < 4; k++) lead[i][j][k] = 0.f;
            cross[i][j][0] = 0u; cross[i][j][1] = 0u;
        }

    const uint32_t a_lane = (uint32_t)(wm0 + (lane & 15)) * GRS + (uint32_t)(lane >> 4) * 16u;
    const uint32_t b_lane = (uint32_t)(wn0 + (lane & 7) + ((lane >> 4) << 3)) * GRS +
                            (uint32_t)((lane >> 3) & 1) * 16u;

    auto load_chunk = [&](int ck, int bsel) {
        uint32_t base = s0 + bsel * GBUF;
#pragma unroll
        for (int i = 0; i < 2; i++) {
            int idx = tid + i * 256;
            int r = idx >> 3, c = idx & 7;
            int gm = row0 + r;
            bool v = gm < M;
            const f16* pa = v ? (A + (size_t)gm * lda + (size_t)ck * 64 + c * 8) : A;
            cp16(base + (uint32_t)r * GRS + (uint32_t)c * 16u, pa, v);
        }
#pragma unroll
        for (int i = 0; i < 4; i++) {
            int idx = tid + i * 256;
            int r = idx >> 3, c = idx & 7;
            int gn = col0 + r;
            bool v = gn < N;
            const f16* ph = v ? (Bhi + (size_t)gn * ldb + (size_t)ck * 64 + c * 8) : Bhi;
            uint32_t d = base + GASZ + (uint32_t)r * GRS + (uint32_t)c * 16u;
            cp16(d, ph, v);
            if (BSPLIT) {
                const f16* pl = v ? (Blo + (size_t)gn * ldb + (size_t)ck * 64 + c * 8) : Blo;
                cp16(d + GBSZ, pl, v);
            }
        }
        cpcommit();
    };

    auto compute = [&](int bsel) {
        uint32_t base = s0 + bsel * GBUF;
        uint32_t ah = base;
        uint32_t bh = base + GASZ, bl = base + GASZ + GBSZ;
#pragma unroll
        for (int ks = 0; ks < 4; ks++) {
            uint32_t af[2][4];
#pragma unroll
            for (int mt = 0; mt < 2; mt++) {
                uint32_t off = a_lane + (uint32_t)mt * (16 * GRS) + (uint32_t)ks * 32u;
                ldsm4(af[mt], ah + off);
            }
            uint32_t bfh[2][4], bfl[2][4];
#pragma unroll
            for (int np = 0; np < 2; np++) {
                uint32_t off = b_lane + (uint32_t)np * (16 * GRS) + (uint32_t)ks * 32u;
                ldsm4(bfh[np], bh + off);
                if (BSPLIT) ldsm4(bfl[np], bl + off);
            }
#pragma unroll
            for (int mt = 0; mt < 2; mt++)
#pragma unroll
                for (int nt = 0; nt < 4; nt++) {
                    const uint32_t* Bh2 = &bfh[nt >> 1][(nt & 1) * 2];
                    mma_h_f32(lead[mt][nt], af[mt], Bh2);
                    if (BSPLIT) {
                        const uint32_t* Bl2 = &bfl[nt >> 1][(nt & 1) * 2];
                        mma_h_f16(cross[mt][nt], af[mt], Bl2);
                    }
                }
        }
    };

    load_chunk(0, 0);
    for (int ck = 0; ck < NC; ck++) {
        if (ck + 1 < NC) { load_chunk(ck + 1, (ck + 1) & 1); cpwait1(); }
        else             { cpwait0(); }
        __syncthreads();
        compute(ck & 1);
        __syncthreads();
    }

    const float INV = 1.0f / 2048.0f;
#pragma unroll
    for (int mt = 0; mt < 2; mt++) {
#pragma unroll
        for (int nt = 0; nt < 4; nt++) {
            int r0 = row0 + wm0 + mt * 16 + (lane >> 2);
            int c0 = col0 + wn0 + nt * 8 + (lane & 3) * 2;
            float* a4 = lead[mt][nt];
#pragma unroll
            for (int h = 0; h < 2; h++) {
                int gm = r0 + h * 8;
                if (gm >= M) continue;
                float v0 = a4[h * 2], v1 = a4[h * 2 + 1];
                if (BSPLIT) {
                    __half2 cx = *reinterpret_cast<__half2*>(&cross[mt][nt][h]);
                    v0 += __half2float(cx.x) * INV;
                    v1 += __half2float(cx.y) * INV;
                }
                if (bias) { v0 += bias[c0]; v1 += bias[c0 + 1]; }
                if (EPI == 0) {
                    if (res) {
                        v0 += res[(size_t)gm * ldc + c0];
                        v1 += res[(size_t)gm * ldc + c0 + 1];
                    }
                    Cf[(size_t)gm * ldc + c0]     = v0;
                    Cf[(size_t)gm * ldc + c0 + 1] = v1;
                } else if (EPI == 1) {
                    uint32_t lo, hi = packsplit_hi(v0, v1, lo);
                    *reinterpret_cast<uint32_t*>(Cbh + (size_t)gm * ldc + c0) = hi;
                    *reinterpret_cast<uint32_t*>(Cbl + (size_t)gm * ldc + c0) = lo;
                } else if (EPI == 2) {
                    *reinterpret_cast<uint32_t*>(Chh + (size_t)gm * ldc + c0) =
                        packh2(geluf(v0), geluf(v1));
                } else {
                    // EPI==3: stage fp16 pair transposed (d-major)
                    f16 h0, l0, h1, l1;
                    splith(v0, h0, l0);
                    splith(v1, h1, l1);
                    int trow = gm - row0;
                    int dl = c0 - col0;
                    *(f16*)(smem + (uint32_t)dl * TRS + (uint32_t)trow * 2) = h0;
                    *(f16*)(smem + (uint32_t)(dl + 1) * TRS + (uint32_t)trow * 2) = h1;
                    *(f16*)(smem + VTSTG + (uint32_t)dl * TRS + (uint32_t)trow * 2) = l0;
                    *(f16*)(smem + VTSTG + (uint32_t)(dl + 1) * TRS + (uint32_t)trow * 2) = l1;
                }
            }
        }
    }

    if (EPI == 3) {
        __syncthreads();
#pragma unroll 1
        for (int it = 0; it < 16; it++) {
            int dl = warp + it * 8;
            int gcol = col0 + dl;
            int hh = gcol >> 6, dh = gcol & 63;
#pragma unroll
            for (int pass = 0; pass < 2; pass++) {
                int trow = pass * 32 + lane;
                int gm = row0 + trow;
                if (gm < M) {
                    int b = gm / NTOK, t = gm % NTOK;
                    size_t dst = ((size_t)(b * HEADS + hh) * 64 + dh) * SPAD + t;
                    Chh[dst] = *(f16*)(smem + (uint32_t)dl * TRS + (uint32_t)trow * 2);
                    Chl[dst] = *(f16*)(smem + VTSTG + (uint32_t)dl * TRS + (uint32_t)trow * 2);
                }
            }
        }
    }
}

template <int EPI, int BSPLIT>
static void hgemm(const f16* A, int lda,
                  const f16* Bh, const f16* Bl, int ldb,
                  float* Cf, bf16* Cbh, bf16* Cbl, f16* Chh, f16* Chl, int ldc,
                  const float* bias, const float* res, int M, int N, int K) {
    constexpr int GBUF = GASZ + (BSPLIT ? 2 : 1) * GBSZ;
    int smem = 2 * GBUF;
    cudaFuncSetAttribute(h16_gemm<EPI, BSPLIT>, cudaFuncAttributeMaxDynamicSharedMemorySize, smem);
    dim3 grid(N / 128, (M + 63) / 64, 1);
    h16_gemm<EPI, BSPLIT><<<grid, 256, smem>>>(A, lda, Bh, Bl, ldb, Cf, Cbh, Cbl, Chh, Chl,
                                               ldc, bias, res, M, N, K / 64);
}

extern "C" void kernel_launch(void* const* d_in, const int* in_sizes, int n_in,
                              void* d_out, int out_size) {
    const float* x       = (const float*)d_in[0];
    const float* conv_w  = (const float*)d_in[1];
    const float* conv_b  = (const float*)d_in[2];
    const float* cls_tok = (const float*)d_in[3];
    const float* pos_emb = (const float*)d_in[4];
    const float* ln1_g   = (const float*)d_in[5];
    const float* ln1_b   = (const float*)d_in[6];
    const float* qkv_w   = (const float*)d_in[7];
    const float* qkv_b   = (const float*)d_in[8];
    const float* proj_w  = (const float*)d_in[9];
    const float* proj_b  = (const float*)d_in[10];
    const float* ln2_g   = (const float*)d_in[11];
    const float* ln2_b   = (const float*)d_in[12];
    const float* mlp_w1  = (const float*)d_in[13];
    const float* mlp_b1  = (const float*)d_in[14];
    const float* mlp_w2  = (const float*)d_in[15];
    const float* mlp_b2  = (const float*)d_in[16];
    const float* lnf_g   = (const float*)d_in[17];
    const float* lnf_b   = (const float*)d_in[18];
    float* out = (float*)d_out;

    f16 *wh, *wl, *cwh, *cwl, *pxh, *xh, *ahp, *mh, *vthi, *vtlo;
    float *ph, *ptmp;
    bf16 *qhi, *qlo;
    cudaGetSymbolAddress((void**)&wh, g_wh);
    cudaGetSymbolAddress((void**)&wl, g_wl);
    cudaGetSymbolAddress((void**)&cwh, g_cwh);
    cudaGetSymbolAddress((void**)&cwl, g_cwl);
    cudaGetSymbolAddress((void**)&pxh, g_pxh);
    cudaGetSymbolAddress((void**)&xh, g_xh);
    cudaGetSymbolAddress((void**)&ahp, g_ah);
    cudaGetSymbolAddress((void**)&mh, g_mh);
    cudaGetSymbolAddress((void**)&ph, g_h);
    cudaGetSymbolAddress((void**)&ptmp, g_ptmp);
    cudaGetSymbolAddress((void**)&qhi, g_qhi);
    cudaGetSymbolAddress((void**)&qlo, g_qlo);
    cudaGetSymbolAddress((void**)&vthi, g_vthi);
    cudaGetSymbolAddress((void**)&vtlo, g_vtlo);

    dim3 tb(32, 8);

    // ---- weight prep: batched over layers (grid.z) ----
    split_h<<<(DM * DM + 255) / 256, 256>>>(conv_w, cwh, cwl, DM * DM);
    wt_trans_hB<<<dim3(2304 / 32, 768 / 32, LAYERS), tb>>>(
        qkv_w, wh, wl, DM, 3 * DM, (long long)DM * 3 * DM, LW);
    wt_trans_hB<<<dim3(768 / 32, 768 / 32, LAYERS), tb>>>(
        proj_w, wh + 1769472, wl + 1769472, DM, DM, (long long)DM * DM, LW);
    wt_trans_h1B<<<dim3(3072 / 32, 768 / 32, LAYERS), tb>>>(
        mlp_w1, wh + 2359296, DM, 4 * DM, (long long)DM * 4 * DM, LW);
    wt_trans_h1B<<<dim3(768 / 32, 3072 / 32, LAYERS), tb>>>(
        mlp_w2, wh + 4718592, 4 * DM, DM, (long long)4 * DM * DM, LW);

    // ---- patch embed ----
    im2col_h<<<(MPATCH * DM + 255) / 256, 256>>>(x, pxh);
    hgemm<0, 1>(pxh, DM, cwh, cwl, DM, ptmp, nullptr, nullptr, nullptr, nullptr, DM,
                conv_b, nullptr, MPATCH, DM, DM);
    assemble_kernel<<<(MTOK * DM + 255) / 256, 256>>>(ptmp, cls_tok, pos_emb, ph);

    cudaFuncSetAttribute(fused_attn, cudaFuncAttributeMaxDynamicSharedMemorySize, FA_SMEM);

    for (int l = 0; l < LAYERS; l++) {
        long long wo = (long long)l * LW;
        const f16* qwT_h = wh + wo;            const f16* qwT_l = wl + wo;
        const f16* pwT_h = wh + wo + 1769472;  const f16* pwT_l = wl + wo + 1769472;
        const f16* w1T_h = wh + wo + 2359296;
        const f16* w2T_h = wh + wo + 4718592;
        const float* l1g = ln1_g + (size_t)l * DM;
        const float* l1b = ln1_b + (size_t)l * DM;
        const float* qb  = qkv_b + (size_t)l * 3 * DM;
        const float* pb  = proj_b + (size_t)l * DM;
        const float* l2g = ln2_g + (size_t)l * DM;
        const float* l2b = ln2_b + (size_t)l * DM;
        const float* b1  = mlp_b1 + (size_t)l * 4 * DM;
        const float* b2  = mlp_b2 + (size_t)l * DM;

        // LN1 -> single fp16
        ln_h<<<MTOK, 256>>>(ph, l1g, l1b, xh);
        // QK -> bf16 pair (first 1536 cols of qkv)
        hgemm<1, 1>(xh, DM, qwT_h, qwT_l, DM, nullptr, qhi, qlo, nullptr, nullptr, 3 * DM,
                    qb, nullptr, MTOK, 2 * DM, DM);
        // V -> transposed VT fp16 pair directly (cols 1536..2304)
        hgemm<3, 1>(xh, DM, qwT_h + (size_t)2 * DM * DM, qwT_l + (size_t)2 * DM * DM, DM,
                    nullptr, nullptr, nullptr, vthi, vtlo, SPAD,
                    qb + 2 * DM, nullptr, MTOK, DM, DM);
        // fused attention -> single fp16
        fused_attn<<<dim3(NCHUNK, BATCH * HEADS), 256, FA_SMEM>>>(qhi, qlo, vthi, vtlo, ahp);
        // proj + bias + residual -> h; weights split
        hgemm<0, 1>(ahp, DM, pwT_h, pwT_l, DM, ph, nullptr, nullptr, nullptr, nullptr, DM,
                    pb, ph, MTOK, DM, DM);
        // LN2 -> single fp16
        ln_h<<<MTOK, 256>>>(ph, l2g, l2b, xh);
        // MLP1 + gelu -> single fp16; single-plane weights
        hgemm<2, 0>(xh, DM, w1T_h, nullptr, DM, nullptr, nullptr, nullptr, mh, nullptr, 4 * DM,
                    b1, nullptr, MTOK, 4 * DM, DM);
        // MLP2 + bias + residual -> h; single-plane weights
        hgemm<0, 0>(mh, 4 * DM, w2T_h, nullptr, 4 * DM, ph, nullptr, nullptr, nullptr, nullptr, DM,
                    b2, ph, MTOK, DM, 4 * DM);
    }

    // final LN on CLS rows -> out [8,768]
    ln_kernel<<<BATCH, 256>>>(ph, lnf_g, lnf_b, out, (long long)NTOK * DM, DM);
}

// round 17
// speedup vs baseline: 4.3792x; 1.1193x over previous
#include <cuda_runtime.h>
#include <cuda_bf16.h>
#include <cuda_fp16.h>
#include <math.h>
#include <stdint.h>

using bf16 = __nv_bfloat16;
using f16 = __half;

template <int N> struct ic { static constexpr int v = N; };

// ---------------- problem constants ----------------
static constexpr int BATCH  = 8;
static constexpr int DM     = 768;
static constexpr int HEADS  = 12;
static constexpr int LAYERS = 12;
static constexpr int NTOK   = 785;
static constexpr int NPATCH = 784;
static constexpr int MTOK   = BATCH * NTOK;    // 6280
static constexpr int MPATCH = BATCH * NPATCH;  // 6272
static constexpr int IMG    = 448;
static constexpr int PSZ    = 16;
static constexpr int GRID28 = 28;
static constexpr int SPAD   = 896;
static constexpr long long LW = 7077888LL;

// ---------------- device scratch ----------------
__device__ f16  g_wh[(size_t)LAYERS * LW];     // weights hi
__device__ f16  g_wl[(size_t)LAYERS * LW];     // weights lo (qkv uses; proj/mlp ignore)
__device__ f16  g_cwh[DM * DM];
__device__ f16  g_cwl[DM * DM];
__device__ f16  g_pxh[(size_t)MPATCH * DM];
__device__ f16  g_xh[(size_t)MTOK * DM];
__device__ f16  g_ah[(size_t)MTOK * DM];
__device__ f16  g_mh[(size_t)MTOK * 4 * DM];
__device__ float g_h[(size_t)MTOK * DM];
__device__ float g_ptmp[(size_t)MPATCH * DM];
__device__ bf16  g_qhi[(size_t)MTOK * 3 * DM];
__device__ bf16  g_qlo[(size_t)MTOK * 3 * DM];
__device__ f16   g_vthi[(size_t)BATCH * HEADS * 64 * SPAD];  // fp16 split VT; zero tail
__device__ f16   g_vtlo[(size_t)BATCH * HEADS * 64 * SPAD];

// ---------------- small helpers ----------------
__device__ __forceinline__ void split2(float v, bf16& h, bf16& l) {
    h = __float2bfloat16(v);
    l = __float2bfloat16(v - __bfloat162float(h));
}
__device__ __forceinline__ float geluf(float v) {
    return 0.5f * v * (1.0f + erff(v * 0.70710678118654752f));
}
__device__ __forceinline__ float warpSum(float v) {
#pragma unroll
    for (int o = 16; o > 0; o >>= 1) v += __shfl_xor_sync(0xffffffffu, v, o);
    return v;
}
__device__ __forceinline__ float blockSum256(float v, float* sh) {
    int lane = threadIdx.x & 31, w = threadIdx.x >> 5;
    v = warpSum(v);
    if (lane == 0) sh[w] = v;
    __syncthreads();
    float r = (threadIdx.x < 8) ? sh[threadIdx.x] : 0.f;
    if (w == 0) { r = warpSum(r); if (lane == 0) sh[0] = r; }
    __syncthreads();
    r = sh[0];
    __syncthreads();
    return r;
}

// ---------------- PTX wrappers ----------------
__device__ __forceinline__ uint32_t s2u(const void* p) {
    uint32_t a;
    asm("{ .reg .u64 t; cvta.to.shared.u64 t, %1; cvt.u32.u64 %0, t; }" : "=r"(a) : "l"(p));
    return a;
}
__device__ __forceinline__ void cp16(uint32_t d, const void* s, bool pred) {
    int sz = pred ? 16 : 0;
    asm volatile("cp.async.cg.shared.global [%0], [%1], 16, %2;" :: "r"(d), "l"(s), "r"(sz));
}
__device__ __forceinline__ void cpcommit() { asm volatile("cp.async.commit_group;" ::: "memory"); }
__device__ __forceinline__ void cpwait0()  { asm volatile("cp.async.wait_group 0;" ::: "memory"); }
__device__ __forceinline__ void cpwait1()  { asm volatile("cp.async.wait_group 1;" ::: "memory"); }
__device__ __forceinline__ void ldsm4(uint32_t* r, uint32_t addr) {
    asm volatile("ldmatrix.sync.aligned.m8n8.x4.shared.b16 {%0,%1,%2,%3}, [%4];"
                 : "=r"(r[0]), "=r"(r[1]), "=r"(r[2]), "=r"(r[3]) : "r"(addr));
}
// bf16 operands, f32 acc (validated; attention QK)
__device__ __forceinline__ void mma16816(float* c, const uint32_t* a, const uint32_t* b) {
    asm volatile(
        "mma.sync.aligned.m16n8k16.row.col.f32.bf16.bf16.f32 "
        "{%0,%1,%2,%3}, {%4,%5,%6,%7}, {%8,%9}, {%0,%1,%2,%3};"
        : "+f"(c[0]), "+f"(c[1]), "+f"(c[2]), "+f"(c[3])
        : "r"(a[0]), "r"(a[1]), "r"(a[2]), "r"(a[3]), "r"(b[0]), "r"(b[1]));
}
// f16 operands, f32 acc (lead term)
__device__ __forceinline__ void mma_h_f32(float* c, const uint32_t* a, const uint32_t* b) {
    asm volatile(
        "mma.sync.aligned.m16n8k16.row.col.f32.f16.f16.f32 "
        "{%0,%1,%2,%3}, {%4,%5,%6,%7}, {%8,%9}, {%0,%1,%2,%3};"
        : "+f"(c[0]), "+f"(c[1]), "+f"(c[2]), "+f"(c[3])
        : "r"(a[0]), "r"(a[1]), "r"(a[2]), "r"(a[3]), "r"(b[0]), "r"(b[1]));
}
// f16 operands, f16 acc (cross term; 2 C regs)
__device__ __forceinline__ void mma_h_f16(uint32_t* c, const uint32_t* a, const uint32_t* b) {
    asm volatile(
        "mma.sync.aligned.m16n8k16.row.col.f16.f16.f16.f16 "
        "{%0,%1}, {%2,%3,%4,%5}, {%6,%7}, {%0,%1};"
        : "+r"(c[0]), "+r"(c[1])
        : "r"(a[0]), "r"(a[1]), "r"(a[2]), "r"(a[3]), "r"(b[0]), "r"(b[1]));
}
// bf16 split pack (attention S staging, last chunk; validated)
__device__ __forceinline__ uint32_t packsplit_hi(float a, float b, uint32_t& lo) {
    bf16 ah, al, bh, bl;
    split2(a, ah, al);
    split2(b, bh, bl);
    __nv_bfloat162 h2; h2.x = ah; h2.y = bh;
    __nv_bfloat162 l2; l2.x = al; l2.y = bl;
    lo = *reinterpret_cast<uint32_t*>(&l2);
    return *reinterpret_cast<uint32_t*>(&h2);
}
__device__ __forceinline__ uint32_t packh2(float a, float b) {
    __half2 h2 = __halves2half2(__float2half(a), __float2half(b));
    return *reinterpret_cast<uint32_t*>(&h2);
}
__device__ __forceinline__ void splith(float v, f16& h, f16& l) {
    h = __float2half(v);
    l = __float2half((v - __half2float(h)) * 2048.f);
}

// ---------------- elementwise / prep kernels ----------------
__global__ void im2col_h(const float* __restrict__ x, f16* __restrict__ Ph) {
    int idx = blockIdx.x * blockDim.x + threadIdx.x;
    if (idx >= MPATCH * DM) return;
    int k = idx % DM, m = idx / DM;
    int b = m / NPATCH, t = m % NPATCH;
    int py = t / GRID28, px = t % GRID28;
    int c = k >> 8, rem = k & 255, i = rem >> 4, j = rem & 15;
    size_t src = (((size_t)(b * 3 + c) * IMG) + (size_t)(py * PSZ + i)) * IMG + (px * PSZ + j);
    Ph[idx] = __float2half(x[src]);
}

__global__ void split_h(const float* __restrict__ W, f16* __restrict__ Oh,
                        f16* __restrict__ Ol, int n) {
    int idx = blockIdx.x * blockDim.x + threadIdx.x;
    if (idx >= n) return;
    f16 h, l;
    splith(W[idx], h, l);
    Oh[idx] = h; Ol[idx] = l;
}

// batched over layers (blockIdx.z): W[K,N] -> out[n*K + k], fp16 split
__global__ void wt_trans_hB(const float* __restrict__ W0, f16* __restrict__ Oh0,
                            f16* __restrict__ Ol0, int K, int N,
                            long long sIn, long long sOut) {
    const float* W = W0 + (long long)blockIdx.z * sIn;
    f16* Oh = Oh0 + (long long)blockIdx.z * sOut;
    f16* Ol = Ol0 + (long long)blockIdx.z * sOut;
    __shared__ float tile[32][33];
    int kb = blockIdx.y * 32, nb = blockIdx.x * 32;
    int tx = threadIdx.x, ty = threadIdx.y;  // 32 x 8
#pragma unroll
    for (int i = 0; i < 32; i += 8) {
        int k = kb + ty + i, n = nb + tx;
        tile[ty + i][tx] = (k < K && n < N) ? W[(size_t)k * N + n] : 0.f;
    }
    __syncthreads();
#pragma unroll
    for (int i = 0; i < 32; i += 8) {
        int n = nb + ty + i, k = kb + tx;
        if (n < N && k < K) {
            f16 h, l;
            splith(tile[tx][ty + i], h, l);
            Oh[(size_t)n * K + k] = h;
            Ol[(size_t)n * K + k] = l;
        }
    }
}

// batched, single fp16 out (proj/MLP weights)
__global__ void wt_trans_h1B(const float* __restrict__ W0, f16* __restrict__ Oh0,
                             int K, int N, long long sIn, long long sOut) {
    const float* W = W0 + (long long)blockIdx.z * sIn;
    f16* Oh = Oh0 + (long long)blockIdx.z * sOut;
    __shared__ float tile[32][33];
    int kb = blockIdx.y * 32, nb = blockIdx.x * 32;
    int tx = threadIdx.x, ty = threadIdx.y;
#pragma unroll
    for (int i = 0; i < 32; i += 8) {
        int k = kb + ty + i, n = nb + tx;
        tile[ty + i][tx] = (k < K && n < N) ? W[(size_t)k * N + n] : 0.f;
    }
    __syncthreads();
#pragma unroll
    for (int i = 0; i < 32; i += 8) {
        int n = nb + ty + i, k = kb + tx;
        if (n < N && k < K)
            Oh[(size_t)n * K + k] = __float2half(tile[tx][ty + i]);
    }
}

__global__ void assemble_kernel(const float* __restrict__ tok, const float* __restrict__ cls,
                                const float* __restrict__ pos, float* __restrict__ H) {
    int idx = blockIdx.x * blockDim.x + threadIdx.x;
    if (idx >= MTOK * DM) return;
    int d = idx % DM;
    int r = idx / DM;
    int n = r % NTOK, b = r / NTOK;
    float v;
    if (n == 0) v = cls[d] + pos[d];
    else        v = tok[((size_t)b * NPATCH + (n - 1)) * DM + d] + pos[(size_t)n * DM + d];
    H[idx] = v;
}

__global__ void ln_kernel(const float* __restrict__ X, const float* __restrict__ g,
                          const float* __restrict__ bb, float* __restrict__ Y,
                          long long inStride, long long outStride) {
    const float* x = X + (long long)blockIdx.x * inStride;
    float* y = Y + (long long)blockIdx.x * outStride;
    int t = threadIdx.x;
    __shared__ float sh[8];
    float v0 = x[t], v1 = x[t + 256], v2 = x[t + 512];
    float mu = blockSum256(v0 + v1 + v2, sh) * (1.0f / 768.0f);
    float d0 = v0 - mu, d1 = v1 - mu, d2 = v2 - mu;
    float var = blockSum256(d0 * d0 + d1 * d1 + d2 * d2, sh) * (1.0f / 768.0f);
    float rs = rsqrtf(var + 1e-5f);
    y[t]       = d0 * rs * g[t]       + bb[t];
    y[t + 256] = d1 * rs * g[t + 256] + bb[t + 256];
    y[t + 512] = d2 * rs * g[t + 512] + bb[t + 512];
}

// LN -> single fp16
__global__ void ln_h(const float* __restrict__ X, const float* __restrict__ g,
                     const float* __restrict__ bb, f16* __restrict__ Yh) {
    const float* x = X + (size_t)blockIdx.x * DM;
    f16* yh = Yh + (size_t)blockIdx.x * DM;
    int t = threadIdx.x;
    __shared__ float sh[8];
    float v0 = x[t], v1 = x[t + 256], v2 = x[t + 512];
    float mu = blockSum256(v0 + v1 + v2, sh) * (1.0f / 768.0f);
    float d0 = v0 - mu, d1 = v1 - mu, d2 = v2 - mu;
    float var = blockSum256(d0 * d0 + d1 * d1 + d2 * d2, sh) * (1.0f / 768.0f);
    float rs = rsqrtf(var + 1e-5f);
    yh[t]       = __float2half(d0 * rs * g[t]       + bb[t]);
    yh[t + 256] = __float2half(d1 * rs * g[t + 256] + bb[t + 256]);
    yh[t + 512] = __float2half(d2 * rs * g[t + 512] + bb[t + 512]);
}

// ---------------- fused flash attention (v7: fragment softmax on full chunks) ----------------
static constexpr int ARS    = 144;
static constexpr int KTILE  = 128 * ARS;
static constexpr int VRS    = 272;
static constexpr int VTILE  = 64 * VRS;
static constexpr int KVBUF  = 2 * KTILE + 2 * VTILE;
static constexpr int PRS2   = 272;
static constexpr int SPTILE = 128 * PRS2;
static constexpr int OFF_SPH = 2 * KVBUF;
static constexpr int OFF_SPL = OFF_SPH + SPTILE;
static constexpr int OFF_M  = OFF_SPL + SPTILE;
static constexpr int OFF_L  = OFF_M + 512;
static constexpr int OFF_CA = OFF_L + 512;
static constexpr int OFF_T  = OFF_CA + 512;
static constexpr int FA_SMEM = OFF_T + 1024;
static constexpr int NCHUNK = 7;

__global__ void __launch_bounds__(256, 1)
fused_attn(const bf16* __restrict__ qkvh, const bf16* __restrict__ qkvl,
           const f16* __restrict__ vth, const f16* __restrict__ vtl,
           f16* __restrict__ yh) {
    extern __shared__ __align__(16) char smem[];
    uint32_t s0 = s2u(smem);
    const int tid = threadIdx.x, lane = tid & 31, warp = tid >> 5;
    const int qt = blockIdx.x;
    const int z = blockIdx.y;
    const int b = z / HEADS, h = z % HEADS;
    const float SC = 0.125f;

    const int wm0 = warp * 16;
    const uint32_t a_lane  = (uint32_t)(wm0 + (lane & 15)) * ARS + (uint32_t)(lane >> 4) * 16u;
    const uint32_t b_lane  = (uint32_t)((lane & 7) + ((lane >> 4) << 3)) * ARS +
                             (uint32_t)((lane >> 3) & 1) * 16u;
    const uint32_t vb_lane = (uint32_t)((lane & 7) + ((lane >> 4) << 3)) * VRS +
                             (uint32_t)((lane >> 3) & 1) * 16u;
    const uint32_t ap_lane = (uint32_t)(wm0 + (lane & 15)) * PRS2 + (uint32_t)(lane >> 4) * 16u;

    float* mrow = reinterpret_cast<float*>(smem + OFF_M);
    float* lrow = reinterpret_cast<float*>(smem + OFF_L);
    float* crow = reinterpret_cast<float*>(smem + OFF_CA);
    float* tred = reinterpret_cast<float*>(smem + OFF_T);

    auto load_qk = [&](int rowbase, int colbase, uint32_t dsth, uint32_t dstl) {
#pragma unroll
        for (int i = 0; i < 4; i++) {
            int idx = tid + i * 256;
            int r = idx >> 3, g = idx & 7;
            bool v = (rowbase + r) < NTOK;
            size_t off = ((size_t)(b * NTOK + rowbase + r)) * (3 * DM) + colbase + g * 8;
            const bf16* sh2 = v ? (qkvh + off) : qkvh;
            const bf16* sl2 = v ? (qkvl + off) : qkvl;
            uint32_t d = (uint32_t)r * ARS + (uint32_t)g * 16u;
            cp16(dsth + d, sh2, v);
            cp16(dstl + d, sl2, v);
        }
    };
    auto load_vt = [&](int c, uint32_t dsth, uint32_t dstl) {
        const f16* bh2 = vth + (size_t)z * 64 * SPAD + (size_t)c * 128;
        const f16* bl2 = vtl + (size_t)z * 64 * SPAD + (size_t)c * 128;
#pragma unroll
        for (int i = 0; i < 4; i++) {
            int idx = tid + i * 256;
            int r = idx >> 4, g = idx & 15;
            size_t off = (size_t)r * SPAD + g * 8;
            uint32_t d = (uint32_t)r * VRS + (uint32_t)g * 16u;
            cp16(dsth + d, bh2 + off, true);
            cp16(dstl + d, bl2 + off, true);
        }
    };
    auto load_chunk = [&](int c, int bsel) {
        uint32_t base = s0 + bsel * KVBUF;
        load_qk(c * 128, DM + h * 64, base, base + KTILE);
        load_vt(c, base + 2 * KTILE, base + 2 * KTILE + VTILE);
        cpcommit();
    };

    load_qk(qt * 128, h * 64, s0 + OFF_SPH, s0 + OFF_SPH + KTILE);
    cpcommit();
    cpwait0();
    __syncthreads();
    uint32_t aQh[4][4], aQl[4][4];
#pragma unroll
    for (int ks = 0; ks < 4; ks++) {
        ldsm4(aQh[ks], s0 + OFF_SPH + a_lane + ks * 32);
        ldsm4(aQl[ks], s0 + OFF_SPH + KTILE + a_lane + ks * 32);
    }
    if (tid < 128) { mrow[tid] = -1e30f; lrow[tid] = 0.f; }
    __syncthreads();

    float o[8][4];
#pragma unroll
    for (int i = 0; i < 8; i++)
#pragma unroll
        for (int j = 0; j < 4; j++) o[i][j] = 0.f;

    load_chunk(0, 0);
    for (int c = 0; c < NCHUNK; c++) {
        const bool full = (c < NCHUNK - 1);
        if (c + 1 < NCHUNK) { load_chunk(c + 1, (c + 1) & 1); cpwait1(); }
        else                { cpwait0(); }
        __syncthreads();
        uint32_t kvb = s0 + (c & 1) * KVBUF;
        uint32_t Kh = kvb, Kl = kvb + KTILE;
        uint32_t Vh = kvb + 2 * KTILE, Vl = kvb + 2 * KTILE + VTILE;

        // ---- S = Q K^T (3-term split bf16); last chunk only 32 key cols ----
        float s[16][4];
#pragma unroll
        for (int j = 0; j < 16; j++)
#pragma unroll
            for (int q = 0; q < 4; q++) s[j][q] = 0.f;

        auto smma = [&](auto JPC) {
            constexpr int JP = decltype(JPC)::v;
#pragma unroll
            for (int ks = 0; ks < 4; ks++) {
#pragma unroll
                for (int jp = 0; jp < JP; jp++) {
                    uint32_t kh[4], kl[4];
                    uint32_t koff = b_lane + (uint32_t)jp * (16 * ARS) + (uint32_t)ks * 32u;
                    ldsm4(kh, Kh + koff);
                    ldsm4(kl, Kl + koff);
#pragma unroll
                    for (int hf = 0; hf < 2; hf++) {
                        int j = jp * 2 + hf;
                        mma16816(s[j], aQh[ks], &kh[hf * 2]);
                        mma16816(s[j], aQh[ks], &kl[hf * 2]);
                        mma16816(s[j], aQl[ks], &kh[hf * 2]);
                    }
                }
            }
        };

        // PV: P fp16 single from smem, V fp16 split (lead f32 + cross f16/2048)
        auto pv = [&](auto KTC) {
            constexpr int KT = decltype(KTC)::v;
            uint32_t ocx[8][2];
#pragma unroll
            for (int nt = 0; nt < 8; nt++) { ocx[nt][0] = 0u; ocx[nt][1] = 0u; }
#pragma unroll
            for (int kt = 0; kt < KT; kt++) {
                uint32_t pa[4];
                ldsm4(pa, s0 + OFF_SPH + ap_lane + (uint32_t)kt * 32u);
#pragma unroll
                for (int dp = 0; dp < 4; dp++) {
                    uint32_t vh[4], vl[4];
                    uint32_t voff = vb_lane + (uint32_t)dp * (16 * VRS) + (uint32_t)kt * 32u;
                    ldsm4(vh, Vh + voff);
                    ldsm4(vl, Vl + voff);
#pragma unroll
                    for (int hf = 0; hf < 2; hf++) {
                        int nt = dp * 2 + hf;
                        mma_h_f32(o[nt], pa, &vh[hf * 2]);
                        mma_h_f16(ocx[nt], pa, &vl[hf * 2]);
                    }
                }
            }
            const float INV = 1.0f / 2048.0f;
#pragma unroll
            for (int nt = 0; nt < 8; nt++) {
                __half2 c0 = *reinterpret_cast<__half2*>(&ocx[nt][0]);
                __half2 c1 = *reinterpret_cast<__half2*>(&ocx[nt][1]);
                o[nt][0] += __half2float(c0.x) * INV;
                o[nt][1] += __half2float(c0.y) * INV;
                o[nt][2] += __half2float(c1.x) * INV;
                o[nt][3] += __half2float(c1.y) * INV;
            }
        };

        if (full) {
            smma(ic<8>{});

            // ---- fragment softmax (all 128 cols valid) ----
            const int rA = wm0 + (lane >> 2), rB = rA + 8;
            float mxa = -1e30f, mxb = -1e30f;
#pragma unroll
            for (int j = 0; j < 16; j++) {
                mxa = fmaxf(mxa, fmaxf(s[j][0], s[j][1]));
                mxb = fmaxf(mxb, fmaxf(s[j][2], s[j][3]));
            }
#pragma unroll
            for (int off = 1; off <= 2; off <<= 1) {
                mxa = fmaxf(mxa, __shfl_xor_sync(0xffffffffu, mxa, off));
                mxb = fmaxf(mxb, __shfl_xor_sync(0xffffffffu, mxb, off));
            }
            float moA = mrow[rA], moB = mrow[rB];
            float mnA = fmaxf(moA, mxa), mnB = fmaxf(moB, mxb);
            float caA = __expf(SC * (moA - mnA));
            float caB = __expf(SC * (moB - mnB));

            // exp in registers, write P fp16 directly (validated C-store coords)
            char* smp = smem;
            const int c0 = 2 * (lane & 3);
            float esA = 0.f, esB = 0.f;
#pragma unroll
            for (int j = 0; j < 16; j++) {
                float e0 = __expf(SC * (s[j][0] - mnA));
                float e1 = __expf(SC * (s[j][1] - mnA));
                float e2 = __expf(SC * (s[j][2] - mnB));
                float e3 = __expf(SC * (s[j][3] - mnB));
                esA += e0 + e1;
                esB += e2 + e3;
                int cc = j * 8 + c0;
                *(uint32_t*)(smp + OFF_SPH + (uint32_t)rA * PRS2 + cc * 2) = packh2(e0, e1);
                *(uint32_t*)(smp + OFF_SPH + (uint32_t)rB * PRS2 + cc * 2) = packh2(e2, e3);
            }
#pragma unroll
            for (int off = 1; off <= 2; off <<= 1) {
                esA += __shfl_xor_sync(0xffffffffu, esA, off);
                esB += __shfl_xor_sync(0xffffffffu, esB, off);
            }
            if ((lane & 3) == 0) {
                lrow[rA] = lrow[rA] * caA + esA;
                mrow[rA] = mnA;
                lrow[rB] = lrow[rB] * caB + esB;
                mrow[rB] = mnB;
            }
            __syncwarp();

            // o rescale (register ca)
#pragma unroll
            for (int nt = 0; nt < 8; nt++) {
                o[nt][0] *= caA; o[nt][1] *= caA;
                o[nt][2] *= caB; o[nt][3] *= caB;
            }
            pv(ic<8>{});
        } else {
            smma(ic<2>{});
            // ---- stage S as split bf16 (validated store coords), 4 j-tiles ----
            {
                char* smp = smem;
                int r0 = wm0 + (lane >> 2);
                int c0 = 2 * (lane & 3);
#pragma unroll
                for (int j = 0; j < 4; j++) {
                    int cc = j * 8 + c0;
                    uint32_t loA, hiA = packsplit_hi(s[j][0], s[j][1], loA);
                    uint32_t loB, hiB = packsplit_hi(s[j][2], s[j][3], loB);
                    *(uint32_t*)(smp + OFF_SPH + (uint32_t)r0 * PRS2 + cc * 2) = hiA;
                    *(uint32_t*)(smp + OFF_SPL + (uint32_t)r0 * PRS2 + cc * 2) = loA;
                    *(uint32_t*)(smp + OFF_SPH + (uint32_t)(r0 + 8) * PRS2 + cc * 2) = hiB;
                    *(uint32_t*)(smp + OFF_SPL + (uint32_t)(r0 + 8) * PRS2 + cc * 2) = loB;
                }
            }
            __syncthreads();

            // ---- masked linear softmax over first 64 cols (valid 17) ----
            const int r = tid >> 1, half = tid & 1;
            char* smp = smem;
            const uint32_t rowoff = (uint32_t)r * PRS2 + (uint32_t)half * 128u;
            const int colbase = c * 128 + half * 64;
            const int nvalid0 = NTOK - colbase;
            const int nvalid = nvalid0 < 0 ? 0 : (nvalid0 > 64 ? 64 : nvalid0);

            float chmax = -1e30f;
#pragma unroll 8
            for (int k = 0; k < 64; k += 2) {
                uint32_t hi = *(uint32_t*)(smp + OFF_SPH + rowoff + k * 2);
                uint32_t lo = *(uint32_t*)(smp + OFF_SPL + rowoff + k * 2);
                __nv_bfloat162 h2 = *reinterpret_cast<__nv_bfloat162*>(&hi);
                __nv_bfloat162 l2 = *reinterpret_cast<__nv_bfloat162*>(&lo);
                float v0 = __bfloat162float(h2.x) + __bfloat162float(l2.x);
                float v1 = __bfloat162float(h2.y) + __bfloat162float(l2.y);
                if (k < nvalid)     chmax = fmaxf(chmax, v0);
                if (k + 1 < nvalid) chmax = fmaxf(chmax, v1);
            }
            tred[tid] = chmax;
            __syncthreads();
            float m_old = mrow[r];
            float rm = fmaxf(tred[2 * r], tred[2 * r + 1]);
            float m_new = fmaxf(m_old, rm);
            float ca = __expf(SC * (m_old - m_new));
            __syncthreads();

            float esum = 0.f;
#pragma unroll 8
            for (int k = 0; k < 64; k += 2) {
                uint32_t hi = *(uint32_t*)(smp + OFF_SPH + rowoff + k * 2);
                uint32_t lo = *(uint32_t*)(smp + OFF_SPL + rowoff + k * 2);
                __nv_bfloat162 h2 = *reinterpret_cast<__nv_bfloat162*>(&hi);
                __nv_bfloat162 l2 = *reinterpret_cast<__nv_bfloat162*>(&lo);
                float v0 = __bfloat162float(h2.x) + __bfloat162float(l2.x);
                float v1 = __bfloat162float(h2.y) + __bfloat162float(l2.y);
                float e0 = (k < nvalid)     ? __expf(SC * (v0 - m_new)) : 0.f;
                float e1 = (k + 1 < nvalid) ? __expf(SC * (v1 - m_new)) : 0.f;
                esum += e0 + e1;
                *(uint32_t*)(smp + OFF_SPH + rowoff + k * 2) = packh2(e0, e1);
            }
            tred[tid] = esum;
            __syncthreads();
            if (half == 0) {
                lrow[r] = lrow[r] * ca + tred[2 * r] + tred[2 * r + 1];
                mrow[r] = m_new;
                crow[r] = ca;
            }
            __syncthreads();

            float caA = crow[wm0 + (lane >> 2)];
            float caB = crow[wm0 + 8 + (lane >> 2)];
#pragma unroll
            for (int nt = 0; nt < 8; nt++) {
                o[nt][0] *= caA; o[nt][1] *= caA;
                o[nt][2] *= caB; o[nt][3] *= caB;
            }
            pv(ic<2>{});
        }
        __syncthreads();
    }

    float la = lrow[wm0 + (lane >> 2)];
    float lb = lrow[wm0 + 8 + (lane >> 2)];
    float ia = 1.0f / la, ib = 1.0f / lb;
    int ra = qt * 128 + wm0 + (lane >> 2);
    int rb = ra + 8;
#pragma unroll
    for (int nt = 0; nt < 8; nt++) {
        int col = h * 64 + nt * 8 + 2 * (lane & 3);
        if (ra < NTOK) {
            size_t p = (size_t)(b * NTOK + ra) * DM + col;
            *reinterpret_cast<uint32_t*>(yh + p) = packh2(o[nt][0] * ia, o[nt][1] * ia);
        }
        if (rb < NTOK) {
            size_t p = (size_t)(b * NTOK + rb) * DM + col;
            *reinterpret_cast<uint32_t*>(yh + p) = packh2(o[nt][2] * ib, o[nt][3] * ib);
        }
    }
}

// ---------------- fp16 GEMM: A single fp16, B split (BSPLIT=1) or single (0) ----------
// EPI: 0 fp32 (+bias?+res?), 1 bf16 split (+bias), 2 fp16 single gelu (+bias),
//      3 fp16 split TRANSPOSED into per-head VT layout (+bias)  [V of qkv]
static constexpr int GRS   = 144;
static constexpr int GASZ  = 64 * GRS;             // A plane 9216
static constexpr int GBSZ  = 128 * GRS;            // B plane 18432
static constexpr int TRS   = 136;                  // VT staging row stride
static constexpr int VTSTG = 128 * TRS;            // 17408 per plane

template <int EPI, int BSPLIT>
__global__ void __launch_bounds__(256, 2)
h16_gemm(const f16* __restrict__ A, int lda,
         const f16* __restrict__ Bhi, const f16* __restrict__ Blo, int ldb,
         float* __restrict__ Cf, bf16* __restrict__ Cbh, bf16* __restrict__ Cbl,
         f16* __restrict__ Chh, f16* __restrict__ Chl, int ldc,
         const float* __restrict__ bias, const float* __restrict__ res,
         int M, int N, int NC) {
    constexpr int GBUF = GASZ + (BSPLIT ? 2 : 1) * GBSZ;
    extern __shared__ __align__(16) char smem[];
    uint32_t s0 = s2u(smem);

    const int tid = threadIdx.x, lane = tid & 31, warp = tid >> 5;
    const int wm0 = (warp >> 2) * 32;
    const int wn0 = (warp & 3) * 32;
    const int row0 = blockIdx.y * 64, col0 = blockIdx.x * 128;

    float lead[2][4][4];
    uint32_t cross[2][4][2];
#pragma unroll
    for (int i = 0; i < 2; i++)
#pragma unroll
        for (int j = 0; j < 4; j++) {
#pragma unroll
            for (int k = 0; k < 4; k++) lead[i][j][k] = 0.f;
            cross[i][j][0] = 0u; cross[i][j][1] = 0u;
        }

    const uint32_t a_lane = (uint32_t)(wm0 + (lane & 15)) * GRS + (uint32_t)(lane >> 4) * 16u;
    const uint32_t b_lane = (uint32_t)(wn0 + (lane & 7) + ((lane >> 4) << 3)) * GRS +
                            (uint32_t)((lane >> 3) & 1) * 16u;

    auto load_chunk = [&](int ck, int bsel) {
        uint32_t base = s0 + bsel * GBUF;
#pragma unroll
        for (int i = 0; i < 2; i++) {
            int idx = tid + i * 256;
            int r = idx >> 3, c = idx & 7;
            int gm = row0 + r;
            bool v = gm < M;
            const f16* pa = v ? (A + (size_t)gm * lda + (size_t)ck * 64 + c * 8) : A;
            cp16(base + (uint32_t)r * GRS + (uint32_t)c * 16u, pa, v);
        }
#pragma unroll
        for (int i = 0; i < 4; i++) {
            int idx = tid + i * 256;
            int r = idx >> 3, c = idx & 7;
            int gn = col0 + r;
            bool v = gn < N;
            const f16* ph = v ? (Bhi + (size_t)gn * ldb + (size_t)ck * 64 + c * 8) : Bhi;
            uint32_t d = base + GASZ + (uint32_t)r * GRS + (uint32_t)c * 16u;
            cp16(d, ph, v);
            if (BSPLIT) {
                const f16* pl = v ? (Blo + (size_t)gn * ldb + (size_t)ck * 64 + c * 8) : Blo;
                cp16(d + GBSZ, pl, v);
            }
        }
        cpcommit();
    };

    auto compute = [&](int bsel) {
        uint32_t base = s0 + bsel * GBUF;
        uint32_t ah = base;
        uint32_t bh = base + GASZ, bl = base + GASZ + GBSZ;
#pragma unroll
        for (int ks = 0; ks < 4; ks++) {
            uint32_t af[2][4];
#pragma unroll
            for (int mt = 0; mt < 2; mt++) {
                uint32_t off = a_lane + (uint32_t)mt * (16 * GRS) + (uint32_t)ks * 32u;
                ldsm4(af[mt], ah + off);
            }
            uint32_t bfh[2][4], bfl[2][4];
#pragma unroll
            for (int np = 0; np < 2; np++) {
                uint32_t off = b_lane + (uint32_t)np * (16 * GRS) + (uint32_t)ks * 32u;
                ldsm4(bfh[np], bh + off);
                if (BSPLIT) ldsm4(bfl[np], bl + off);
            }
#pragma unroll
            for (int mt = 0; mt < 2; mt++)
#pragma unroll
                for (int nt = 0; nt < 4; nt++) {
                    const uint32_t* Bh2 = &bfh[nt >> 1][(nt & 1) * 2];
                    mma_h_f32(lead[mt][nt], af[mt], Bh2);
                    if (BSPLIT) {
                        const uint32_t* Bl2 = &bfl[nt >> 1][(nt & 1) * 2];
                        mma_h_f16(cross[mt][nt], af[mt], Bl2);
                    }
                }
        }
    };

    load_chunk(0, 0);
    for (int ck = 0; ck < NC; ck++) {
        if (ck + 1 < NC) { load_chunk(ck + 1, (ck + 1) & 1); cpwait1(); }
        else             { cpwait0(); }
        __syncthreads();
        compute(ck & 1);
        __syncthreads();
    }

    const float INV = 1.0f / 2048.0f;
#pragma unroll
    for (int mt = 0; mt < 2; mt++) {
#pragma unroll
        for (int nt = 0; nt < 4; nt++) {
            int r0 = row0 + wm0 + mt * 16 + (lane >> 2);
            int c0 = col0 + wn0 + nt * 8 + (lane & 3) * 2;
            float* a4 = lead[mt][nt];
#pragma unroll
            for (int h = 0; h < 2; h++) {
                int gm = r0 + h * 8;
                if (gm >= M) continue;
                float v0 = a4[h * 2], v1 = a4[h * 2 + 1];
                if (BSPLIT) {
                    __half2 cx = *reinterpret_cast<__half2*>(&cross[mt][nt][h]);
                    v0 += __half2float(cx.x) * INV;
                    v1 += __half2float(cx.y) * INV;
                }
                if (bias) { v0 += bias[c0]; v1 += bias[c0 + 1]; }
                if (EPI == 0) {
                    if (res) {
                        v0 += res[(size_t)gm * ldc + c0];
                        v1 += res[(size_t)gm * ldc + c0 + 1];
                    }
                    Cf[(size_t)gm * ldc + c0]     = v0;
                    Cf[(size_t)gm * ldc + c0 + 1] = v1;
                } else if (EPI == 1) {
                    uint32_t lo, hi = packsplit_hi(v0, v1, lo);
                    *reinterpret_cast<uint32_t*>(Cbh + (size_t)gm * ldc + c0) = hi;
                    *reinterpret_cast<uint32_t*>(Cbl + (size_t)gm * ldc + c0) = lo;
                } else if (EPI == 2) {
                    *reinterpret_cast<uint32_t*>(Chh + (size_t)gm * ldc + c0) =
                        packh2(geluf(v0), geluf(v1));
                } else {
                    // EPI==3: stage fp16 pair transposed (d-major)
                    f16 h0, l0, h1, l1;
                    splith(v0, h0, l0);
                    splith(v1, h1, l1);
                    int trow = gm - row0;
                    int dl = c0 - col0;
                    *(f16*)(smem + (uint32_t)dl * TRS + (uint32_t)trow * 2) = h0;
                    *(f16*)(smem + (uint32_t)(dl + 1) * TRS + (uint32_t)trow * 2) = h1;
                    *(f16*)(smem + VTSTG + (uint32_t)dl * TRS + (uint32_t)trow * 2) = l0;
                    *(f16*)(smem + VTSTG + (uint32_t)(dl + 1) * TRS + (uint32_t)trow * 2) = l1;
                }
            }
        }
    }

    if (EPI == 3) {
        __syncthreads();
#pragma unroll 1
        for (int it = 0; it < 16; it++) {
            int dl = warp + it * 8;
            int gcol = col0 + dl;
            int hh = gcol >> 6, dh = gcol & 63;
#pragma unroll
            for (int pass = 0; pass < 2; pass++) {
                int trow = pass * 32 + lane;
                int gm = row0 + trow;
                if (gm < M) {
                    int b = gm / NTOK, t = gm % NTOK;
                    size_t dst = ((size_t)(b * HEADS + hh) * 64 + dh) * SPAD + t;
                    Chh[dst] = *(f16*)(smem + (uint32_t)dl * TRS + (uint32_t)trow * 2);
                    Chl[dst] = *(f16*)(smem + VTSTG + (uint32_t)dl * TRS + (uint32_t)trow * 2);
                }
            }
        }
    }
}

template <int EPI, int BSPLIT>
static void hgemm(const f16* A, int lda,
                  const f16* Bh, const f16* Bl, int ldb,
                  float* Cf, bf16* Cbh, bf16* Cbl, f16* Chh, f16* Chl, int ldc,
                  const float* bias, const float* res, int M, int N, int K) {
    constexpr int GBUF = GASZ + (BSPLIT ? 2 : 1) * GBSZ;
    int smem = 2 * GBUF;
    cudaFuncSetAttribute(h16_gemm<EPI, BSPLIT>, cudaFuncAttributeMaxDynamicSharedMemorySize, smem);
    dim3 grid(N / 128, (M + 63) / 64, 1);
    h16_gemm<EPI, BSPLIT><<<grid, 256, smem>>>(A, lda, Bh, Bl, ldb, Cf, Cbh, Cbl, Chh, Chl,
                                               ldc, bias, res, M, N, K / 64);
}

extern "C" void kernel_launch(void* const* d_in, const int* in_sizes, int n_in,
                              void* d_out, int out_size) {
    const float* x       = (const float*)d_in[0];
    const float* conv_w  = (const float*)d_in[1];
    const float* conv_b  = (const float*)d_in[2];
    const float* cls_tok = (const float*)d_in[3];
    const float* pos_emb = (const float*)d_in[4];
    const float* ln1_g   = (const float*)d_in[5];
    const float* ln1_b   = (const float*)d_in[6];
    const float* qkv_w   = (const float*)d_in[7];
    const float* qkv_b   = (const float*)d_in[8];
    const float* proj_w  = (const float*)d_in[9];
    const float* proj_b  = (const float*)d_in[10];
    const float* ln2_g   = (const float*)d_in[11];
    const float* ln2_b   = (const float*)d_in[12];
    const float* mlp_w1  = (const float*)d_in[13];
    const float* mlp_b1  = (const float*)d_in[14];
    const float* mlp_w2  = (const float*)d_in[15];
    const float* mlp_b2  = (const float*)d_in[16];
    const float* lnf_g   = (const float*)d_in[17];
    const float* lnf_b   = (const float*)d_in[18];
    float* out = (float*)d_out;

    f16 *wh, *wl, *cwh, *cwl, *pxh, *xh, *ahp, *mh, *vthi, *vtlo;
    float *ph, *ptmp;
    bf16 *qhi, *qlo;
    cudaGetSymbolAddress((void**)&wh, g_wh);
    cudaGetSymbolAddress((void**)&wl, g_wl);
    cudaGetSymbolAddress((void**)&cwh, g_cwh);
    cudaGetSymbolAddress((void**)&cwl, g_cwl);
    cudaGetSymbolAddress((void**)&pxh, g_pxh);
    cudaGetSymbolAddress((void**)&xh, g_xh);
    cudaGetSymbolAddress((void**)&ahp, g_ah);
    cudaGetSymbolAddress((void**)&mh, g_mh);
    cudaGetSymbolAddress((void**)&ph, g_h);
    cudaGetSymbolAddress((void**)&ptmp, g_ptmp);
    cudaGetSymbolAddress((void**)&qhi, g_qhi);
    cudaGetSymbolAddress((void**)&qlo, g_qlo);
    cudaGetSymbolAddress((void**)&vthi, g_vthi);
    cudaGetSymbolAddress((void**)&vtlo, g_vtlo);

    dim3 tb(32, 8);

    // ---- weight prep: qkv split; proj/mlp single fp16 (batched over layers) ----
    split_h<<<(DM * DM + 255) / 256, 256>>>(conv_w, cwh, cwl, DM * DM);
    wt_trans_hB<<<dim3(2304 / 32, 768 / 32, LAYERS), tb>>>(
        qkv_w, wh, wl, DM, 3 * DM, (long long)DM * 3 * DM, LW);
    wt_trans_h1B<<<dim3(768 / 32, 768 / 32, LAYERS), tb>>>(
        proj_w, wh + 1769472, DM, DM, (long long)DM * DM, LW);
    wt_trans_h1B<<<dim3(3072 / 32, 768 / 32, LAYERS), tb>>>(
        mlp_w1, wh + 2359296, DM, 4 * DM, (long long)DM * 4 * DM, LW);
    wt_trans_h1B<<<dim3(768 / 32, 3072 / 32, LAYERS), tb>>>(
        mlp_w2, wh + 4718592, 4 * DM, DM, (long long)4 * DM * DM, LW);

    // ---- patch embed ----
    im2col_h<<<(MPATCH * DM + 255) / 256, 256>>>(x, pxh);
    hgemm<0, 1>(pxh, DM, cwh, cwl, DM, ptmp, nullptr, nullptr, nullptr, nullptr, DM,
                conv_b, nullptr, MPATCH, DM, DM);
    assemble_kernel<<<(MTOK * DM + 255) / 256, 256>>>(ptmp, cls_tok, pos_emb, ph);

    cudaFuncSetAttribute(fused_attn, cudaFuncAttributeMaxDynamicSharedMemorySize, FA_SMEM);

    for (int l = 0; l < LAYERS; l++) {
        long long wo = (long long)l * LW;
        const f16* qwT_h = wh + wo;            const f16* qwT_l = wl + wo;
        const f16* pwT_h = wh + wo + 1769472;
        const f16* w1T_h = wh + wo + 2359296;
        const f16* w2T_h = wh + wo + 4718592;
        const float* l1g = ln1_g + (size_t)l * DM;
        const float* l1b = ln1_b + (size_t)l * DM;
        const float* qb  = qkv_b + (size_t)l * 3 * DM;
        const float* pb  = proj_b + (size_t)l * DM;
        const float* l2g = ln2_g + (size_t)l * DM;
        const float* l2b = ln2_b + (size_t)l * DM;
        const float* b1  = mlp_b1 + (size_t)l * 4 * DM;
        const float* b2  = mlp_b2 + (size_t)l * DM;

        // LN1 -> single fp16
        ln_h<<<MTOK, 256>>>(ph, l1g, l1b, xh);
        // QK -> bf16 pair (first 1536 cols of qkv); weights split
        hgemm<1, 1>(xh, DM, qwT_h, qwT_l, DM, nullptr, qhi, qlo, nullptr, nullptr, 3 * DM,
                    qb, nullptr, MTOK, 2 * DM, DM);
        // V -> transposed VT fp16 pair directly (cols 1536..2304); weights split
        hgemm<3, 1>(xh, DM, qwT_h + (size_t)2 * DM * DM, qwT_l + (size_t)2 * DM * DM, DM,
                    nullptr, nullptr, nullptr, vthi, vtlo, SPAD,
                    qb + 2 * DM, nullptr, MTOK, DM, DM);
        // fused attention -> single fp16
        fused_attn<<<dim3(NCHUNK, BATCH * HEADS), 256, FA_SMEM>>>(qhi, qlo, vthi, vtlo, ahp);
        // proj + bias + residual -> h; single-plane weights
        hgemm<0, 0>(ahp, DM, pwT_h, nullptr, DM, ph, nullptr, nullptr, nullptr, nullptr, DM,
                    pb, ph, MTOK, DM, DM);
        // LN2 -> single fp16
        ln_h<<<MTOK, 256>>>(ph, l2g, l2b, xh);
        // MLP1 + gelu -> single fp16; single-plane weights
        hgemm<2, 0>(xh, DM, w1T_h, nullptr, DM, nullptr, nullptr, nullptr, mh, nullptr, 4 * DM,
                    b1, nullptr, MTOK, 4 * DM, DM);
        // MLP2 + bias + residual -> h; single-plane weights
        hgemm<0, 0>(mh, 4 * DM, w2T_h, nullptr, 4 * DM, ph, nullptr, nullptr, nullptr, nullptr, DM,
                    b2, ph, MTOK, DM, 4 * DM);
    }

    // final LN on CLS rows -> out [8,768]
    ln_kernel<<<BATCH, 256>>>(ph, lnf_g, lnf_b, out, (long long)NTOK * DM, DM);
}